// round 1
// baseline (speedup 1.0000x reference)
#include <cuda_runtime.h>
#include <math.h>

// Problem constants
#define BATCH 4
#define SEQ   2048
#define DMODEL 1024
#define MTOT  (BATCH * SEQ)   // 8192

// Device-global scratch (allocation-free rule: static __device__ arrays)
__device__ float g_Q[(size_t)BATCH * SEQ * DMODEL];            // 32 MB
__device__ float g_K[(size_t)BATCH * SEQ * DMODEL];            // 32 MB
__device__ float g_V[(size_t)BATCH * SEQ * DMODEL];            // 32 MB
__device__ float g_P[(size_t)BATCH * SEQ * SEQ];               // 64 MB (scores/probs)
__device__ float g_O[(size_t)BATCH * SEQ * DMODEL];            // 32 MB

// ---------------------------------------------------------------------------
// Tiled SGEMM: 128x128 block tile, BK=8, 256 threads, 8x8 per-thread microtile
// TRANSB = true : C[m,n] = scale * sum_k A[m,k] * B[n,k]  (+ bias[n])   "NT"
// TRANSB = false: C[m,n] = scale * sum_k A[m,k] * B[k,n]  (+ bias[n])   "NN"
// All dims assumed multiples of tile sizes (true for this problem).
// blockIdx.z batches via element strides sA/sB/sC.
// ---------------------------------------------------------------------------
template <bool TRANSB>
__global__ __launch_bounds__(256, 2)
void gemm128(const float* __restrict__ A, const float* __restrict__ B,
             float* __restrict__ C, const float* __restrict__ bias,
             int M, int N, int K, float scale,
             size_t sA, size_t sB, size_t sC)
{
    A += (size_t)blockIdx.z * sA;
    B += (size_t)blockIdx.z * sB;
    C += (size_t)blockIdx.z * sC;

    const int tid   = threadIdx.x;
    const int mBase = blockIdx.y * 128;
    const int nBase = blockIdx.x * 128;

    __shared__ float As[8][128];
    __shared__ float Bs[8][128];

    // A-tile (and NT B-tile) load mapping: 128 rows x 8 k, one float4/thread
    const int arow = tid >> 1;        // 0..127
    const int acol = (tid & 1) * 4;   // 0 or 4
    // NN B-tile load mapping: 8 k-rows x 128 n, one float4/thread
    const int bkr  = tid >> 5;        // 0..7
    const int bnc  = (tid & 31) * 4;  // 0..124

    // compute mapping: 16x16 thread grid of 8x8 microtiles
    const int tr = (tid >> 4) * 8;    // row offset in tile
    const int tc = (tid & 15) * 8;    // col offset in tile

    float acc[8][8];
    #pragma unroll
    for (int i = 0; i < 8; i++)
        #pragma unroll
        for (int j = 0; j < 8; j++) acc[i][j] = 0.0f;

    for (int k0 = 0; k0 < K; k0 += 8) {
        // Load A tile (transposed into SMEM: As[k][m])
        {
            float4 v = *reinterpret_cast<const float4*>(
                &A[(size_t)(mBase + arow) * K + (k0 + acol)]);
            As[acol + 0][arow] = v.x;
            As[acol + 1][arow] = v.y;
            As[acol + 2][arow] = v.z;
            As[acol + 3][arow] = v.w;
        }
        // Load B tile
        if (TRANSB) {
            float4 v = *reinterpret_cast<const float4*>(
                &B[(size_t)(nBase + arow) * K + (k0 + acol)]);
            Bs[acol + 0][arow] = v.x;
            Bs[acol + 1][arow] = v.y;
            Bs[acol + 2][arow] = v.z;
            Bs[acol + 3][arow] = v.w;
        } else {
            float4 v = *reinterpret_cast<const float4*>(
                &B[(size_t)(k0 + bkr) * N + (nBase + bnc)]);
            *reinterpret_cast<float4*>(&Bs[bkr][bnc]) = v;
        }
        __syncthreads();

        #pragma unroll
        for (int kk = 0; kk < 8; kk++) {
            float ar[8], br[8];
            #pragma unroll
            for (int i = 0; i < 8; i++) ar[i] = As[kk][tr + i];
            #pragma unroll
            for (int j = 0; j < 8; j++) br[j] = Bs[kk][tc + j];
            #pragma unroll
            for (int i = 0; i < 8; i++)
                #pragma unroll
                for (int j = 0; j < 8; j++)
                    acc[i][j] = fmaf(ar[i], br[j], acc[i][j]);
        }
        __syncthreads();
    }

    // Epilogue: scale + optional bias, vectorized stores
    #pragma unroll
    for (int i = 0; i < 8; i++) {
        const size_t rowOff = (size_t)(mBase + tr + i) * N + nBase + tc;
        #pragma unroll
        for (int j = 0; j < 8; j += 4) {
            float4 v;
            v.x = acc[i][j + 0] * scale;
            v.y = acc[i][j + 1] * scale;
            v.z = acc[i][j + 2] * scale;
            v.w = acc[i][j + 3] * scale;
            if (bias) {
                v.x += bias[nBase + tc + j + 0];
                v.y += bias[nBase + tc + j + 1];
                v.z += bias[nBase + tc + j + 2];
                v.w += bias[nBase + tc + j + 3];
            }
            *reinterpret_cast<float4*>(&C[rowOff + j]) = v;
        }
    }
}

// ---------------------------------------------------------------------------
// Row softmax: one 256-thread block per row of length n
// ---------------------------------------------------------------------------
__global__ __launch_bounds__(256)
void softmax_rows(float* __restrict__ P, int n)
{
    const int tid = threadIdx.x;
    float* row = P + (size_t)blockIdx.x * n;

    __shared__ float red[8];
    __shared__ float bcast;

    // 1) row max
    float mx = -1e30f;
    for (int i = tid; i < n; i += 256) mx = fmaxf(mx, row[i]);
    #pragma unroll
    for (int o = 16; o; o >>= 1) mx = fmaxf(mx, __shfl_xor_sync(0xffffffffu, mx, o));
    if ((tid & 31) == 0) red[tid >> 5] = mx;
    __syncthreads();
    if (tid == 0) {
        float v = red[0];
        #pragma unroll
        for (int w = 1; w < 8; w++) v = fmaxf(v, red[w]);
        bcast = v;
    }
    __syncthreads();
    mx = bcast;
    __syncthreads();

    // 2) exp + sum
    float s = 0.0f;
    for (int i = tid; i < n; i += 256) {
        float e = __expf(row[i] - mx);
        row[i] = e;
        s += e;
    }
    #pragma unroll
    for (int o = 16; o; o >>= 1) s += __shfl_xor_sync(0xffffffffu, s, o);
    if ((tid & 31) == 0) red[tid >> 5] = s;
    __syncthreads();
    if (tid == 0) {
        float v = 0.0f;
        #pragma unroll
        for (int w = 0; w < 8; w++) v += red[w];
        bcast = 1.0f / v;
    }
    __syncthreads();
    const float inv = bcast;

    // 3) normalize
    for (int i = tid; i < n; i += 256) row[i] *= inv;
}

// ---------------------------------------------------------------------------
// Launch
// ---------------------------------------------------------------------------
extern "C" void kernel_launch(void* const* d_in, const int* in_sizes, int n_in,
                              void* d_out, int out_size)
{
    (void)in_sizes; (void)n_in; (void)out_size;

    const float* x   = (const float*)d_in[0];
    const float* w_q = (const float*)d_in[1];
    const float* b_q = (const float*)d_in[2];
    const float* w_k = (const float*)d_in[3];
    const float* b_k = (const float*)d_in[4];
    const float* w_v = (const float*)d_in[5];
    const float* b_v = (const float*)d_in[6];
    const float* w_o = (const float*)d_in[7];
    const float* b_o = (const float*)d_in[8];
    float* out = (float*)d_out;

    float *Qp, *Kp, *Vp, *Pp, *Op;
    cudaGetSymbolAddress((void**)&Qp, g_Q);
    cudaGetSymbolAddress((void**)&Kp, g_K);
    cudaGetSymbolAddress((void**)&Vp, g_V);
    cudaGetSymbolAddress((void**)&Pp, g_P);
    cudaGetSymbolAddress((void**)&Op, g_O);

    const dim3 blk(256);
    const float invSqrtD = 0.03125f; // 1/sqrt(1024)

    // Q/K/V projections: C[8192,1024] = x[8192,1024] @ W^T[1024,1024] + b
    {
        dim3 grid(DMODEL / 128, MTOT / 128, 1);
        gemm128<true><<<grid, blk>>>(x, w_q, Qp, b_q, MTOT, DMODEL, DMODEL, 1.0f, 0, 0, 0);
        gemm128<true><<<grid, blk>>>(x, w_k, Kp, b_k, MTOT, DMODEL, DMODEL, 1.0f, 0, 0, 0);
        gemm128<true><<<grid, blk>>>(x, w_v, Vp, b_v, MTOT, DMODEL, DMODEL, 1.0f, 0, 0, 0);
    }

    // Scores: per batch S[2048,2048] = Q @ K^T * (1/sqrt(d))
    {
        dim3 grid(SEQ / 128, SEQ / 128, BATCH);
        gemm128<true><<<grid, blk>>>(Qp, Kp, Pp, nullptr, SEQ, SEQ, DMODEL, invSqrtD,
                                     (size_t)SEQ * DMODEL, (size_t)SEQ * DMODEL,
                                     (size_t)SEQ * SEQ);
    }

    // Softmax over rows of P
    softmax_rows<<<BATCH * SEQ, blk>>>(Pp, SEQ);

    // O = P @ V : per batch [2048,1024] = [2048,2048] @ [2048,1024]  (NN)
    {
        dim3 grid(DMODEL / 128, SEQ / 128, BATCH);
        gemm128<false><<<grid, blk>>>(Pp, Vp, Op, nullptr, SEQ, DMODEL, SEQ, 1.0f,
                                      (size_t)SEQ * SEQ, (size_t)SEQ * DMODEL,
                                      (size_t)SEQ * DMODEL);
    }

    // Output projection: out[8192,1024] = O @ Wout^T + b_out
    {
        dim3 grid(DMODEL / 128, MTOT / 128, 1);
        gemm128<true><<<grid, blk>>>(Op, w_o, out, b_o, MTOT, DMODEL, DMODEL, 1.0f, 0, 0, 0);
    }
}

// round 3
// speedup vs baseline: 3.2811x; 3.2811x over previous
#include <cuda_runtime.h>
#include <cuda_bf16.h>
#include <cstdint>

#define BATCH 4
#define SEQ   2048
#define DM    1024
#define MTOT  (BATCH * SEQ)     // 8192

#define BM 128
#define BN 128
#define BK 64                    // bf16 per k-chunk (128 B rows)
#define NTHREADS 256
#define TILE_BYTES 16384         // 128 rows x 128 B
#define STAGE_BYTES (4 * TILE_BYTES)   // Ah Al Bh Bl
#define SMEM_SZ (2 * STAGE_BYTES)      // 131072

// ---------------- device scratch ----------------
#define NX ((size_t)MTOT * DM)
#define NW ((size_t)DM * DM)
#define NP ((size_t)BATCH * SEQ * SEQ)

__device__ float g_P[NP];
__device__ __nv_bfloat16 g_xh[NX],  g_xl[NX];
__device__ __nv_bfloat16 g_wqh[NW], g_wql[NW];
__device__ __nv_bfloat16 g_wkh[NW], g_wkl[NW];
__device__ __nv_bfloat16 g_wvh[NW], g_wvl[NW];
__device__ __nv_bfloat16 g_woh[NW], g_wol[NW];
__device__ __nv_bfloat16 g_qh[NX],  g_ql[NX];
__device__ __nv_bfloat16 g_kh[NX],  g_kl[NX];
__device__ __nv_bfloat16 g_vth[NX], g_vtl[NX];   // V^T per batch [DM][SEQ]
__device__ __nv_bfloat16 g_ph[NP],  g_pl[NP];
__device__ __nv_bfloat16 g_oh[NX],  g_ol[NX];

// ---------------- helpers ----------------
static __device__ __forceinline__ uint32_t smem_u32(const void* p) {
    uint32_t a;
    asm("{ .reg .u64 t; cvta.to.shared.u64 t, %1; cvt.u32.u64 %0, t; }" : "=r"(a) : "l"(p));
    return a;
}
static __device__ __forceinline__ uint32_t swz(uint32_t o) { return o ^ ((o >> 3) & 0x70); }

static __device__ __forceinline__ void cpa16(uint32_t s, const void* g) {
    asm volatile("cp.async.cg.shared.global [%0], [%1], 16;" :: "r"(s), "l"(g));
}
static __device__ __forceinline__ void cpa_commit() { asm volatile("cp.async.commit_group;"); }

static __device__ __forceinline__ void ldsm4(uint32_t (&r)[4], uint32_t addr) {
    asm volatile("ldmatrix.sync.aligned.m8n8.x4.shared.b16 {%0,%1,%2,%3}, [%4];"
                 : "=r"(r[0]), "=r"(r[1]), "=r"(r[2]), "=r"(r[3]) : "r"(addr));
}
static __device__ __forceinline__ void mma16816(float (&d)[4], const uint32_t (&a)[4],
                                                uint32_t b0, uint32_t b1) {
    asm volatile("mma.sync.aligned.m16n8k16.row.col.f32.bf16.bf16.f32 "
                 "{%0,%1,%2,%3}, {%4,%5,%6,%7}, {%8,%9}, {%0,%1,%2,%3};"
                 : "+f"(d[0]), "+f"(d[1]), "+f"(d[2]), "+f"(d[3])
                 : "r"(a[0]), "r"(a[1]), "r"(a[2]), "r"(a[3]), "r"(b0), "r"(b1));
}

// ---------------- split fp32 -> (hi, lo) bf16 ----------------
__global__ void split_kernel(const float* __restrict__ src, __nv_bfloat16* __restrict__ h,
                             __nv_bfloat16* __restrict__ l, size_t n) {
    size_t i = (size_t)blockIdx.x * blockDim.x + threadIdx.x;
    size_t stride = (size_t)gridDim.x * blockDim.x;
    for (; i < n; i += stride) {
        float v = src[i];
        __nv_bfloat16 hi = __float2bfloat16(v);
        h[i] = hi;
        l[i] = __float2bfloat16(v - __bfloat162float(hi));
    }
}

// ---------------- stage loader: 4 tiles x 16KB via cp.async ----------------
static __device__ __forceinline__ void load_stage(uint32_t sbase,
                                                  const __nv_bfloat16* const* base,
                                                  int K, int k0, int tid) {
    const int tr = tid >> 3;        // 0..31
    const int tc = tid & 7;         // 16B column
    #pragma unroll
    for (int s = 0; s < 4; s++) {
        const __nv_bfloat16* g = base[s] + (size_t)tr * K + k0 + tc * 8;
        uint32_t so = sbase + s * TILE_BYTES;
        #pragma unroll
        for (int r = 0; r < 4; r++) {
            uint32_t off = (uint32_t)(tr + r * 32) * 128 + tc * 16;
            cpa16(so + swz(off), g + (size_t)(r * 32) * K);
        }
    }
}

// ---------------- GEMM: C = scale*(Ah+Al)(Bh+Bl)^T + bias ----------------
// OUTMODE 0: fp32 C    1: split -> (Ch, Cl)    2: transposed split (V^T)
template <int OUTMODE>
__global__ __launch_bounds__(NTHREADS, 1)
void gemm_bf16x3(const __nv_bfloat16* __restrict__ Ah, const __nv_bfloat16* __restrict__ Al,
                 const __nv_bfloat16* __restrict__ Bh, const __nv_bfloat16* __restrict__ Bl,
                 float* __restrict__ Cf,
                 __nv_bfloat16* __restrict__ Ch, __nv_bfloat16* __restrict__ Cl,
                 const float* __restrict__ bias,
                 int M, int N, int K, float scale,
                 size_t sA, size_t sB, size_t sC, int ldT) {
    extern __shared__ __align__(1024) char smem[];
    const uint32_t sb = smem_u32(smem);
    const int tid = threadIdx.x;
    const int wid = tid >> 5, lane = tid & 31;

    Ah += (size_t)blockIdx.z * sA;  Al += (size_t)blockIdx.z * sA;
    Bh += (size_t)blockIdx.z * sB;  Bl += (size_t)blockIdx.z * sB;

    const int mBase = blockIdx.y * BM;
    const int nBase = blockIdx.x * BN;
    const int m0 = (wid & 3) * 32;      // warp M offset in tile
    const int n0 = (wid >> 2) * 64;     // warp N offset in tile

    const __nv_bfloat16* base[4] = {
        Ah + (size_t)mBase * K, Al + (size_t)mBase * K,
        Bh + (size_t)nBase * K, Bl + (size_t)nBase * K };

    float acc[16][4];
    #pragma unroll
    for (int i = 0; i < 16; i++)
        #pragma unroll
        for (int j = 0; j < 4; j++) acc[i][j] = 0.0f;

    // ldmatrix lane addressing (within tile)
    const uint32_t a_row  = lane & 15;
    const uint32_t a_half = (lane >> 4) * 16;
    const uint32_t b_row  = (lane & 7) + ((lane >> 4) & 1) * 8;
    const uint32_t b_half = ((lane >> 3) & 1) * 16;

    const int NC = K / BK;
    load_stage(sb, base, K, 0, tid);
    cpa_commit();

    for (int c = 0; c < NC; c++) {
        const uint32_t st = sb + (c & 1) * STAGE_BYTES;
        if (c + 1 < NC) {
            load_stage(sb + ((c + 1) & 1) * STAGE_BYTES, base, K, (c + 1) * BK, tid);
            cpa_commit();
            asm volatile("cp.async.wait_group 1;" ::: "memory");
        } else {
            asm volatile("cp.async.wait_group 0;" ::: "memory");
        }
        __syncthreads();

        const uint32_t tAh = st, tAl = st + TILE_BYTES;
        const uint32_t tBh = st + 2 * TILE_BYTES, tBl = st + 3 * TILE_BYTES;

        #pragma unroll
        for (int kk = 0; kk < 4; kk++) {
            const uint32_t kb = kk * 32;
            uint32_t ah[2][4], al[2][4], bh[4][4], bl[4][4];
            #pragma unroll
            for (int t = 0; t < 2; t++) {
                uint32_t off = swz((uint32_t)(m0 + t * 16 + a_row) * 128 + kb + a_half);
                ldsm4(ah[t], tAh + off);
                ldsm4(al[t], tAl + off);
            }
            #pragma unroll
            for (int u = 0; u < 4; u++) {
                uint32_t off = swz((uint32_t)(n0 + u * 16 + b_row) * 128 + kb + b_half);
                ldsm4(bh[u], tBh + off);
                ldsm4(bl[u], tBl + off);
            }
            #pragma unroll
            for (int t = 0; t < 2; t++)
                #pragma unroll
                for (int u = 0; u < 4; u++) {
                    #pragma unroll
                    for (int j = 0; j < 2; j++) {
                        float (&d)[4] = acc[t * 8 + u * 2 + j];
                        const uint32_t B0 = bh[u][j * 2], B1 = bh[u][j * 2 + 1];
                        mma16816(d, ah[t], B0, B1);
                        mma16816(d, ah[t], bl[u][j * 2], bl[u][j * 2 + 1]);
                        mma16816(d, al[t], B0, B1);
                    }
                }
        }
        __syncthreads();
    }

    // ---------------- epilogue (direct from registers) ----------------
    const int qrow = lane >> 2;
    const int qcol = (lane & 3) * 2;
    #pragma unroll
    for (int t = 0; t < 2; t++) {
        #pragma unroll
        for (int u = 0; u < 4; u++) {
            #pragma unroll
            for (int j = 0; j < 2; j++) {
                const float* d = acc[t * 8 + u * 2 + j];
                const int m = mBase + m0 + t * 16 + qrow;
                const int n = nBase + n0 + u * 16 + j * 8 + qcol;
                float b0 = 0.f, b1 = 0.f;
                if (bias) { b0 = bias[n]; b1 = bias[n + 1]; }
                float v0 = d[0] * scale + b0, v1 = d[1] * scale + b1;
                float v2 = d[2] * scale + b0, v3 = d[3] * scale + b1;
                if (OUTMODE == 0) {
                    const size_t o0 = (size_t)blockIdx.z * sC + (size_t)m * N + n;
                    const size_t o1 = o0 + (size_t)8 * N;
                    *reinterpret_cast<float2*>(&Cf[o0]) = make_float2(v0, v1);
                    *reinterpret_cast<float2*>(&Cf[o1]) = make_float2(v2, v3);
                } else if (OUTMODE == 1) {
                    const size_t o0 = (size_t)blockIdx.z * sC + (size_t)m * N + n;
                    const size_t o1 = o0 + (size_t)8 * N;
                    __nv_bfloat16 h0 = __float2bfloat16(v0), h1 = __float2bfloat16(v1);
                    __nv_bfloat16 h2 = __float2bfloat16(v2), h3 = __float2bfloat16(v3);
                    __nv_bfloat162 hp0(h0, h1), hp1(h2, h3);
                    __nv_bfloat162 lp0(__float2bfloat16(v0 - __bfloat162float(h0)),
                                       __float2bfloat16(v1 - __bfloat162float(h1)));
                    __nv_bfloat162 lp1(__float2bfloat16(v2 - __bfloat162float(h2)),
                                       __float2bfloat16(v3 - __bfloat162float(h3)));
                    *reinterpret_cast<__nv_bfloat162*>(&Ch[o0]) = hp0;
                    *reinterpret_cast<__nv_bfloat162*>(&Ch[o1]) = hp1;
                    *reinterpret_cast<__nv_bfloat162*>(&Cl[o0]) = lp0;
                    *reinterpret_cast<__nv_bfloat162*>(&Cl[o1]) = lp1;
                } else {
                    // transposed: C^T[n][m] within batch (batch = m / ldT)
                    const size_t boff = (size_t)(m / ldT) * sC;
                    const int mr = m % ldT;
                    __nv_bfloat16 h0 = __float2bfloat16(v0), h1 = __float2bfloat16(v1);
                    __nv_bfloat16 h2 = __float2bfloat16(v2), h3 = __float2bfloat16(v3);
                    Ch[boff + (size_t)n * ldT + mr]           = h0;
                    Ch[boff + (size_t)(n + 1) * ldT + mr]     = h1;
                    Ch[boff + (size_t)n * ldT + mr + 8]       = h2;
                    Ch[boff + (size_t)(n + 1) * ldT + mr + 8] = h3;
                    Cl[boff + (size_t)n * ldT + mr] =
                        __float2bfloat16(v0 - __bfloat162float(h0));
                    Cl[boff + (size_t)(n + 1) * ldT + mr] =
                        __float2bfloat16(v1 - __bfloat162float(h1));
                    Cl[boff + (size_t)n * ldT + mr + 8] =
                        __float2bfloat16(v2 - __bfloat162float(h2));
                    Cl[boff + (size_t)(n + 1) * ldT + mr + 8] =
                        __float2bfloat16(v3 - __bfloat162float(h3));
                }
            }
        }
    }
}

// ---------------- softmax rows + fused split ----------------
__global__ __launch_bounds__(256)
void softmax_split(float* __restrict__ P, __nv_bfloat16* __restrict__ Ph,
                   __nv_bfloat16* __restrict__ Pl, int n) {
    const int tid = threadIdx.x;
    const size_t roff = (size_t)blockIdx.x * n;
    float* row = P + roff;

    __shared__ float red[8];
    __shared__ float bcast;

    float mx = -1e30f;
    for (int i = tid; i < n; i += 256) mx = fmaxf(mx, row[i]);
    #pragma unroll
    for (int o = 16; o; o >>= 1) mx = fmaxf(mx, __shfl_xor_sync(0xffffffffu, mx, o));
    if ((tid & 31) == 0) red[tid >> 5] = mx;
    __syncthreads();
    if (tid == 0) {
        float v = red[0];
        #pragma unroll
        for (int w = 1; w < 8; w++) v = fmaxf(v, red[w]);
        bcast = v;
    }
    __syncthreads();
    mx = bcast;
    __syncthreads();

    float s = 0.0f;
    for (int i = tid; i < n; i += 256) {
        float e = __expf(row[i] - mx);
        row[i] = e;
        s += e;
    }
    #pragma unroll
    for (int o = 16; o; o >>= 1) s += __shfl_xor_sync(0xffffffffu, s, o);
    if ((tid & 31) == 0) red[tid >> 5] = s;
    __syncthreads();
    if (tid == 0) {
        float v = 0.0f;
        #pragma unroll
        for (int w = 0; w < 8; w++) v += red[w];
        bcast = 1.0f / v;
    }
    __syncthreads();
    const float inv = bcast;

    for (int i = tid; i < n; i += 256) {
        float p = row[i] * inv;
        __nv_bfloat16 h = __float2bfloat16(p);
        Ph[roff + i] = h;
        Pl[roff + i] = __float2bfloat16(p - __bfloat162float(h));
    }
}

// ---------------- launch ----------------
extern "C" void kernel_launch(void* const* d_in, const int* in_sizes, int n_in,
                              void* d_out, int out_size) {
    (void)in_sizes; (void)n_in; (void)out_size;

    const float* x   = (const float*)d_in[0];
    const float* w_q = (const float*)d_in[1];
    const float* b_q = (const float*)d_in[2];
    const float* w_k = (const float*)d_in[3];
    const float* b_k = (const float*)d_in[4];
    const float* w_v = (const float*)d_in[5];
    const float* b_v = (const float*)d_in[6];
    const float* w_o = (const float*)d_in[7];
    const float* b_o = (const float*)d_in[8];
    float* out = (float*)d_out;

    float* Pp;
    __nv_bfloat16 *xh, *xl, *wqh, *wql, *wkh, *wkl, *wvh, *wvl, *woh, *wol;
    __nv_bfloat16 *qh, *ql, *kh, *kl, *vth, *vtl, *ph, *pl, *oh, *ol;
    cudaGetSymbolAddress((void**)&Pp, g_P);
    cudaGetSymbolAddress((void**)&xh, g_xh);   cudaGetSymbolAddress((void**)&xl, g_xl);
    cudaGetSymbolAddress((void**)&wqh, g_wqh); cudaGetSymbolAddress((void**)&wql, g_wql);
    cudaGetSymbolAddress((void**)&wkh, g_wkh); cudaGetSymbolAddress((void**)&wkl, g_wkl);
    cudaGetSymbolAddress((void**)&wvh, g_wvh); cudaGetSymbolAddress((void**)&wvl, g_wvl);
    cudaGetSymbolAddress((void**)&woh, g_woh); cudaGetSymbolAddress((void**)&wol, g_wol);
    cudaGetSymbolAddress((void**)&qh, g_qh);   cudaGetSymbolAddress((void**)&ql, g_ql);
    cudaGetSymbolAddress((void**)&kh, g_kh);   cudaGetSymbolAddress((void**)&kl, g_kl);
    cudaGetSymbolAddress((void**)&vth, g_vth); cudaGetSymbolAddress((void**)&vtl, g_vtl);
    cudaGetSymbolAddress((void**)&ph, g_ph);   cudaGetSymbolAddress((void**)&pl, g_pl);
    cudaGetSymbolAddress((void**)&oh, g_oh);   cudaGetSymbolAddress((void**)&ol, g_ol);

    cudaFuncSetAttribute(gemm_bf16x3<0>, cudaFuncAttributeMaxDynamicSharedMemorySize, SMEM_SZ);
    cudaFuncSetAttribute(gemm_bf16x3<1>, cudaFuncAttributeMaxDynamicSharedMemorySize, SMEM_SZ);
    cudaFuncSetAttribute(gemm_bf16x3<2>, cudaFuncAttributeMaxDynamicSharedMemorySize, SMEM_SZ);

    // split inputs
    split_kernel<<<1024, 256>>>(x, xh, xl, NX);
    split_kernel<<<256, 256>>>(w_q, wqh, wql, NW);
    split_kernel<<<256, 256>>>(w_k, wkh, wkl, NW);
    split_kernel<<<256, 256>>>(w_v, wvh, wvl, NW);
    split_kernel<<<256, 256>>>(w_o, woh, wol, NW);

    const float invSqrtD = 0.03125f;

    // Q, K projections (split out), V projection (transposed split out)
    {
        dim3 grid(DM / BN, MTOT / BM, 1);
        gemm_bf16x3<1><<<grid, NTHREADS, SMEM_SZ>>>(xh, xl, wqh, wql, nullptr, qh, ql, b_q,
                                                    MTOT, DM, DM, 1.0f, 0, 0, 0, 0);
        gemm_bf16x3<1><<<grid, NTHREADS, SMEM_SZ>>>(xh, xl, wkh, wkl, nullptr, kh, kl, b_k,
                                                    MTOT, DM, DM, 1.0f, 0, 0, 0, 0);
        gemm_bf16x3<2><<<grid, NTHREADS, SMEM_SZ>>>(xh, xl, wvh, wvl, nullptr, vth, vtl, b_v,
                                                    MTOT, DM, DM, 1.0f, 0, 0,
                                                    (size_t)DM * SEQ, SEQ);
    }

    // scores P = Q K^T / sqrt(d)
    {
        dim3 grid(SEQ / BN, SEQ / BM, BATCH);
        gemm_bf16x3<0><<<grid, NTHREADS, SMEM_SZ>>>(qh, ql, kh, kl, Pp, nullptr, nullptr,
                                                    nullptr, SEQ, SEQ, DM, invSqrtD,
                                                    (size_t)SEQ * DM, (size_t)SEQ * DM,
                                                    (size_t)SEQ * SEQ, 0);
    }

    softmax_split<<<BATCH * SEQ, 256>>>(Pp, ph, pl, SEQ);

    // O = P V   (B = V^T, K-major)
    {
        dim3 grid(DM / BN, SEQ / BM, BATCH);
        gemm_bf16x3<1><<<grid, NTHREADS, SMEM_SZ>>>(ph, pl, vth, vtl, nullptr, oh, ol, nullptr,
                                                    SEQ, DM, SEQ, 1.0f,
                                                    (size_t)SEQ * SEQ, (size_t)DM * SEQ,
                                                    (size_t)SEQ * DM, 0);
    }

    // out = O W_out^T + b_out
    {
        dim3 grid(DM / BN, MTOT / BM, 1);
        gemm_bf16x3<0><<<grid, NTHREADS, SMEM_SZ>>>(oh, ol, woh, wol, out, nullptr, nullptr,
                                                    b_o, MTOT, DM, DM, 1.0f, 0, 0, 0, 0);
    }
}

// round 4
// speedup vs baseline: 3.3345x; 1.0163x over previous
#include <cuda_runtime.h>
#include <cuda_bf16.h>
#include <cstdint>

#define BATCH 4
#define SEQ   2048
#define DM    1024
#define MTOT  (BATCH * SEQ)     // 8192

#define BM 128
#define BN 128
#define BK 64                    // bf16 per k-chunk (128 B rows)
#define NTHREADS 256
#define TILE_BYTES 16384         // 128 rows x 128 B
#define STAGE_BYTES (4 * TILE_BYTES)   // Ah Al Bh Bl
#define NSTAGE 3
#define SMEM_SZ (NSTAGE * STAGE_BYTES) // 196608

// ---------------- device scratch ----------------
#define NX ((size_t)MTOT * DM)
#define NW ((size_t)DM * DM)
#define NP ((size_t)BATCH * SEQ * SEQ)

__device__ float g_P[NP];
__device__ __nv_bfloat16 g_xh[NX],  g_xl[NX];
__device__ __nv_bfloat16 g_wqh[NW], g_wql[NW];
__device__ __nv_bfloat16 g_wkh[NW], g_wkl[NW];
__device__ __nv_bfloat16 g_wvh[NW], g_wvl[NW];
__device__ __nv_bfloat16 g_woh[NW], g_wol[NW];
__device__ __nv_bfloat16 g_qh[NX],  g_ql[NX];
__device__ __nv_bfloat16 g_kh[NX],  g_kl[NX];
__device__ __nv_bfloat16 g_vth[NX], g_vtl[NX];   // V^T per batch [DM][SEQ]
__device__ __nv_bfloat16 g_ph[NP],  g_pl[NP];
__device__ __nv_bfloat16 g_oh[NX],  g_ol[NX];

// ---------------- helpers ----------------
static __device__ __forceinline__ uint32_t smem_u32(const void* p) {
    uint32_t a;
    asm("{ .reg .u64 t; cvta.to.shared.u64 t, %1; cvt.u32.u64 %0, t; }" : "=r"(a) : "l"(p));
    return a;
}
static __device__ __forceinline__ uint32_t swz(uint32_t o) { return o ^ ((o >> 3) & 0x70); }

static __device__ __forceinline__ void cpa16(uint32_t s, const void* g) {
    asm volatile("cp.async.cg.shared.global [%0], [%1], 16;" :: "r"(s), "l"(g));
}
static __device__ __forceinline__ void cpa_commit() { asm volatile("cp.async.commit_group;"); }

static __device__ __forceinline__ void ldsm4(uint32_t (&r)[4], uint32_t addr) {
    asm volatile("ldmatrix.sync.aligned.m8n8.x4.shared.b16 {%0,%1,%2,%3}, [%4];"
                 : "=r"(r[0]), "=r"(r[1]), "=r"(r[2]), "=r"(r[3]) : "r"(addr));
}
static __device__ __forceinline__ void mma16816(float (&d)[4], const uint32_t (&a)[4],
                                                uint32_t b0, uint32_t b1) {
    asm volatile("mma.sync.aligned.m16n8k16.row.col.f32.bf16.bf16.f32 "
                 "{%0,%1,%2,%3}, {%4,%5,%6,%7}, {%8,%9}, {%0,%1,%2,%3};"
                 : "+f"(d[0]), "+f"(d[1]), "+f"(d[2]), "+f"(d[3])
                 : "r"(a[0]), "r"(a[1]), "r"(a[2]), "r"(a[3]), "r"(b0), "r"(b1));
}

// ---------------- split fp32 -> (hi, lo) bf16 ----------------
__global__ void split_kernel(const float* __restrict__ src, __nv_bfloat16* __restrict__ h,
                             __nv_bfloat16* __restrict__ l, size_t n) {
    size_t i = (size_t)blockIdx.x * blockDim.x + threadIdx.x;
    size_t stride = (size_t)gridDim.x * blockDim.x;
    for (; i < n; i += stride) {
        float v = src[i];
        __nv_bfloat16 hi = __float2bfloat16(v);
        h[i] = hi;
        l[i] = __float2bfloat16(v - __bfloat162float(hi));
    }
}

// fused split for the 4 weight matrices (keeps launch count predictable for ncu)
__global__ void split4_kernel(const float* __restrict__ s0, const float* __restrict__ s1,
                              const float* __restrict__ s2, const float* __restrict__ s3,
                              __nv_bfloat16* __restrict__ h0, __nv_bfloat16* __restrict__ l0,
                              __nv_bfloat16* __restrict__ h1, __nv_bfloat16* __restrict__ l1,
                              __nv_bfloat16* __restrict__ h2, __nv_bfloat16* __restrict__ l2,
                              __nv_bfloat16* __restrict__ h3, __nv_bfloat16* __restrict__ l3,
                              size_t n) {
    const float* src = (blockIdx.y == 0) ? s0 : (blockIdx.y == 1) ? s1
                        : (blockIdx.y == 2) ? s2 : s3;
    __nv_bfloat16* h = (blockIdx.y == 0) ? h0 : (blockIdx.y == 1) ? h1
                        : (blockIdx.y == 2) ? h2 : h3;
    __nv_bfloat16* l = (blockIdx.y == 0) ? l0 : (blockIdx.y == 1) ? l1
                        : (blockIdx.y == 2) ? l2 : l3;
    size_t i = (size_t)blockIdx.x * blockDim.x + threadIdx.x;
    size_t stride = (size_t)gridDim.x * blockDim.x;
    for (; i < n; i += stride) {
        float v = src[i];
        __nv_bfloat16 hi = __float2bfloat16(v);
        h[i] = hi;
        l[i] = __float2bfloat16(v - __bfloat162float(hi));
    }
}

// ---------------- stage loader: 4 tiles x 16KB via cp.async ----------------
static __device__ __forceinline__ void load_stage(uint32_t sbase,
                                                  const __nv_bfloat16* const* base,
                                                  int K, int k0, int tid) {
    const int tr = tid >> 3;        // 0..31
    const int tc = tid & 7;         // 16B column
    #pragma unroll
    for (int s = 0; s < 4; s++) {
        const __nv_bfloat16* g = base[s] + (size_t)tr * K + k0 + tc * 8;
        uint32_t so = sbase + s * TILE_BYTES;
        #pragma unroll
        for (int r = 0; r < 4; r++) {
            uint32_t off = (uint32_t)(tr + r * 32) * 128 + tc * 16;
            cpa16(so + swz(off), g + (size_t)(r * 32) * K);
        }
    }
}

// ---------------- GEMM: C = scale*(Ah+Al)(Bh+Bl)^T + bias ----------------
// OUTMODE 0: fp32 C    1: split -> (Ch, Cl)    2: transposed split (V^T)
template <int OUTMODE>
__global__ __launch_bounds__(NTHREADS, 1)
void gemm_bf16x3(const __nv_bfloat16* __restrict__ Ah, const __nv_bfloat16* __restrict__ Al,
                 const __nv_bfloat16* __restrict__ Bh, const __nv_bfloat16* __restrict__ Bl,
                 float* __restrict__ Cf,
                 __nv_bfloat16* __restrict__ Ch, __nv_bfloat16* __restrict__ Cl,
                 const float* __restrict__ bias,
                 int M, int N, int K, float scale,
                 size_t sA, size_t sB, size_t sC, int ldT) {
    extern __shared__ __align__(1024) char smem[];
    const uint32_t sb = smem_u32(smem);
    const int tid = threadIdx.x;
    const int wid = tid >> 5, lane = tid & 31;

    Ah += (size_t)blockIdx.z * sA;  Al += (size_t)blockIdx.z * sA;
    Bh += (size_t)blockIdx.z * sB;  Bl += (size_t)blockIdx.z * sB;

    const int mBase = blockIdx.y * BM;
    const int nBase = blockIdx.x * BN;
    const int m0 = (wid & 3) * 32;      // warp M offset in tile
    const int n0 = (wid >> 2) * 64;     // warp N offset in tile

    const __nv_bfloat16* base[4] = {
        Ah + (size_t)mBase * K, Al + (size_t)mBase * K,
        Bh + (size_t)nBase * K, Bl + (size_t)nBase * K };

    float acc[16][4];
    #pragma unroll
    for (int i = 0; i < 16; i++)
        #pragma unroll
        for (int j = 0; j < 4; j++) acc[i][j] = 0.0f;

    const uint32_t a_row  = lane & 15;
    const uint32_t a_half = (lane >> 4) * 16;
    const uint32_t b_row  = (lane & 7) + ((lane >> 4) & 1) * 8;
    const uint32_t b_half = ((lane >> 3) & 1) * 16;

    const int NC = K / BK;

    // prologue: fill 2 of 3 stages
    load_stage(sb + 0 * STAGE_BYTES, base, K, 0, tid);
    cpa_commit();
    if (NC > 1) {
        load_stage(sb + 1 * STAGE_BYTES, base, K, BK, tid);
        cpa_commit();
    }

    int buf = 0, nbuf = 2 % NSTAGE;  // buffer of chunk c; buffer for chunk c+2
    for (int c = 0; c < NC; c++) {
        // wait for chunk c's loads
        const int ahead = NC - 1 - c;   // chunks issued beyond c (before this iter)
        if (ahead >= 2)      asm volatile("cp.async.wait_group 1;" ::: "memory");
        else if (ahead == 1) asm volatile("cp.async.wait_group 1;" ::: "memory");
        else                 asm volatile("cp.async.wait_group 0;" ::: "memory");
        __syncthreads();   // chunk c visible to all warps; all warps done with buf nbuf's old data

        if (c + 2 < NC) {
            load_stage(sb + nbuf * STAGE_BYTES, base, K, (c + 2) * BK, tid);
            cpa_commit();
        }

        const uint32_t st = sb + buf * STAGE_BYTES;
        const uint32_t tAh = st, tAl = st + TILE_BYTES;
        const uint32_t tBh = st + 2 * TILE_BYTES, tBl = st + 3 * TILE_BYTES;

        #pragma unroll
        for (int kk = 0; kk < 4; kk++) {
            const uint32_t kb = kk * 32;
            uint32_t ah[2][4], al[2][4], bh[4][4], bl[4][4];
            #pragma unroll
            for (int t = 0; t < 2; t++) {
                uint32_t off = swz((uint32_t)(m0 + t * 16 + a_row) * 128 + kb + a_half);
                ldsm4(ah[t], tAh + off);
                ldsm4(al[t], tAl + off);
            }
            #pragma unroll
            for (int u = 0; u < 4; u++) {
                uint32_t off = swz((uint32_t)(n0 + u * 16 + b_row) * 128 + kb + b_half);
                ldsm4(bh[u], tBh + off);
                ldsm4(bl[u], tBl + off);
            }
            #pragma unroll
            for (int t = 0; t < 2; t++)
                #pragma unroll
                for (int u = 0; u < 4; u++) {
                    #pragma unroll
                    for (int j = 0; j < 2; j++) {
                        float (&d)[4] = acc[t * 8 + u * 2 + j];
                        const uint32_t B0 = bh[u][j * 2], B1 = bh[u][j * 2 + 1];
                        mma16816(d, ah[t], B0, B1);
                        mma16816(d, ah[t], bl[u][j * 2], bl[u][j * 2 + 1]);
                        mma16816(d, al[t], B0, B1);
                    }
                }
        }
        buf = (buf + 1) % NSTAGE;
        nbuf = (nbuf + 1) % NSTAGE;
        __syncthreads();
    }

    // ---------------- epilogue ----------------
    const int qrow = lane >> 2;
    const int qcol = (lane & 3) * 2;
    #pragma unroll
    for (int t = 0; t < 2; t++) {
        #pragma unroll
        for (int u = 0; u < 4; u++) {
            #pragma unroll
            for (int j = 0; j < 2; j++) {
                const float* d = acc[t * 8 + u * 2 + j];
                const int m = mBase + m0 + t * 16 + qrow;
                const int n = nBase + n0 + u * 16 + j * 8 + qcol;
                float b0 = 0.f, b1 = 0.f;
                if (bias) { b0 = bias[n]; b1 = bias[n + 1]; }
                float v0 = d[0] * scale + b0, v1 = d[1] * scale + b1;
                float v2 = d[2] * scale + b0, v3 = d[3] * scale + b1;
                if (OUTMODE == 0) {
                    const size_t o0 = (size_t)blockIdx.z * sC + (size_t)m * N + n;
                    const size_t o1 = o0 + (size_t)8 * N;
                    *reinterpret_cast<float2*>(&Cf[o0]) = make_float2(v0, v1);
                    *reinterpret_cast<float2*>(&Cf[o1]) = make_float2(v2, v3);
                } else if (OUTMODE == 1) {
                    const size_t o0 = (size_t)blockIdx.z * sC + (size_t)m * N + n;
                    const size_t o1 = o0 + (size_t)8 * N;
                    __nv_bfloat16 h0 = __float2bfloat16(v0), h1 = __float2bfloat16(v1);
                    __nv_bfloat16 h2 = __float2bfloat16(v2), h3 = __float2bfloat16(v3);
                    __nv_bfloat162 hp0(h0, h1), hp1(h2, h3);
                    __nv_bfloat162 lp0(__float2bfloat16(v0 - __bfloat162float(h0)),
                                       __float2bfloat16(v1 - __bfloat162float(h1)));
                    __nv_bfloat162 lp1(__float2bfloat16(v2 - __bfloat162float(h2)),
                                       __float2bfloat16(v3 - __bfloat162float(h3)));
                    *reinterpret_cast<__nv_bfloat162*>(&Ch[o0]) = hp0;
                    *reinterpret_cast<__nv_bfloat162*>(&Ch[o1]) = hp1;
                    *reinterpret_cast<__nv_bfloat162*>(&Cl[o0]) = lp0;
                    *reinterpret_cast<__nv_bfloat162*>(&Cl[o1]) = lp1;
                } else {
                    const size_t boff = (size_t)(m / ldT) * sC;
                    const int mr = m % ldT;
                    __nv_bfloat16 h0 = __float2bfloat16(v0), h1 = __float2bfloat16(v1);
                    __nv_bfloat16 h2 = __float2bfloat16(v2), h3 = __float2bfloat16(v3);
                    Ch[boff + (size_t)n * ldT + mr]           = h0;
                    Ch[boff + (size_t)(n + 1) * ldT + mr]     = h1;
                    Ch[boff + (size_t)n * ldT + mr + 8]       = h2;
                    Ch[boff + (size_t)(n + 1) * ldT + mr + 8] = h3;
                    Cl[boff + (size_t)n * ldT + mr] =
                        __float2bfloat16(v0 - __bfloat162float(h0));
                    Cl[boff + (size_t)(n + 1) * ldT + mr] =
                        __float2bfloat16(v1 - __bfloat162float(h1));
                    Cl[boff + (size_t)n * ldT + mr + 8] =
                        __float2bfloat16(v2 - __bfloat162float(h2));
                    Cl[boff + (size_t)(n + 1) * ldT + mr + 8] =
                        __float2bfloat16(v3 - __bfloat162float(h3));
                }
            }
        }
    }
}

// ---------------- softmax rows + fused split, SMEM-resident ----------------
__global__ __launch_bounds__(256)
void softmax_split(const float* __restrict__ P, __nv_bfloat16* __restrict__ Ph,
                   __nv_bfloat16* __restrict__ Pl, int n) {
    const int tid = threadIdx.x;
    const size_t roff = (size_t)blockIdx.x * n;
    const float* row = P + roff;

    __shared__ float srow[SEQ];     // 8 KB
    __shared__ float red[8];
    __shared__ float bcast;

    float mx = -1e30f;
    for (int i = tid; i < n; i += 256) {
        float v = row[i];
        srow[i] = v;
        mx = fmaxf(mx, v);
    }
    #pragma unroll
    for (int o = 16; o; o >>= 1) mx = fmaxf(mx, __shfl_xor_sync(0xffffffffu, mx, o));
    if ((tid & 31) == 0) red[tid >> 5] = mx;
    __syncthreads();
    if (tid == 0) {
        float v = red[0];
        #pragma unroll
        for (int w = 1; w < 8; w++) v = fmaxf(v, red[w]);
        bcast = v;
    }
    __syncthreads();
    mx = bcast;
    __syncthreads();

    float s = 0.0f;
    for (int i = tid; i < n; i += 256) {
        float e = __expf(srow[i] - mx);
        srow[i] = e;
        s += e;
    }
    #pragma unroll
    for (int o = 16; o; o >>= 1) s += __shfl_xor_sync(0xffffffffu, s, o);
    if ((tid & 31) == 0) red[tid >> 5] = s;
    __syncthreads();
    if (tid == 0) {
        float v = 0.0f;
        #pragma unroll
        for (int w = 0; w < 8; w++) v += red[w];
        bcast = 1.0f / v;
    }
    __syncthreads();
    const float inv = bcast;

    for (int i = tid; i < n; i += 256) {
        float p = srow[i] * inv;
        __nv_bfloat16 h = __float2bfloat16(p);
        Ph[roff + i] = h;
        Pl[roff + i] = __float2bfloat16(p - __bfloat162float(h));
    }
}

// ---------------- launch ----------------
extern "C" void kernel_launch(void* const* d_in, const int* in_sizes, int n_in,
                              void* d_out, int out_size) {
    (void)in_sizes; (void)n_in; (void)out_size;

    const float* x   = (const float*)d_in[0];
    const float* w_q = (const float*)d_in[1];
    const float* b_q = (const float*)d_in[2];
    const float* w_k = (const float*)d_in[3];
    const float* b_k = (const float*)d_in[4];
    const float* w_v = (const float*)d_in[5];
    const float* b_v = (const float*)d_in[6];
    const float* w_o = (const float*)d_in[7];
    const float* b_o = (const float*)d_in[8];
    float* out = (float*)d_out;

    float* Pp;
    __nv_bfloat16 *xh, *xl, *wqh, *wql, *wkh, *wkl, *wvh, *wvl, *woh, *wol;
    __nv_bfloat16 *qh, *ql, *kh, *kl, *vth, *vtl, *ph, *pl, *oh, *ol;
    cudaGetSymbolAddress((void**)&Pp, g_P);
    cudaGetSymbolAddress((void**)&xh, g_xh);   cudaGetSymbolAddress((void**)&xl, g_xl);
    cudaGetSymbolAddress((void**)&wqh, g_wqh); cudaGetSymbolAddress((void**)&wql, g_wql);
    cudaGetSymbolAddress((void**)&wkh, g_wkh); cudaGetSymbolAddress((void**)&wkl, g_wkl);
    cudaGetSymbolAddress((void**)&wvh, g_wvh); cudaGetSymbolAddress((void**)&wvl, g_wvl);
    cudaGetSymbolAddress((void**)&woh, g_woh); cudaGetSymbolAddress((void**)&wol, g_wol);
    cudaGetSymbolAddress((void**)&qh, g_qh);   cudaGetSymbolAddress((void**)&ql, g_ql);
    cudaGetSymbolAddress((void**)&kh, g_kh);   cudaGetSymbolAddress((void**)&kl, g_kl);
    cudaGetSymbolAddress((void**)&vth, g_vth); cudaGetSymbolAddress((void**)&vtl, g_vtl);
    cudaGetSymbolAddress((void**)&ph, g_ph);   cudaGetSymbolAddress((void**)&pl, g_pl);
    cudaGetSymbolAddress((void**)&oh, g_oh);   cudaGetSymbolAddress((void**)&ol, g_ol);

    cudaFuncSetAttribute(gemm_bf16x3<0>, cudaFuncAttributeMaxDynamicSharedMemorySize, SMEM_SZ);
    cudaFuncSetAttribute(gemm_bf16x3<1>, cudaFuncAttributeMaxDynamicSharedMemorySize, SMEM_SZ);
    cudaFuncSetAttribute(gemm_bf16x3<2>, cudaFuncAttributeMaxDynamicSharedMemorySize, SMEM_SZ);

    // #1: split x   #2: split all weights
    split_kernel<<<1024, 256>>>(x, xh, xl, NX);
    {
        dim3 g(128, 4);
        split4_kernel<<<g, 256>>>(w_q, w_k, w_v, w_o,
                                  wqh, wql, wkh, wkl, wvh, wvl, woh, wol, NW);
    }

    const float invSqrtD = 0.03125f;

    // #3 Q, #4 K, #5 V(T)
    {
        dim3 grid(DM / BN, MTOT / BM, 1);
        gemm_bf16x3<1><<<grid, NTHREADS, SMEM_SZ>>>(xh, xl, wqh, wql, nullptr, qh, ql, b_q,
                                                    MTOT, DM, DM, 1.0f, 0, 0, 0, 0);
        gemm_bf16x3<1><<<grid, NTHREADS, SMEM_SZ>>>(xh, xl, wkh, wkl, nullptr, kh, kl, b_k,
                                                    MTOT, DM, DM, 1.0f, 0, 0, 0, 0);
        gemm_bf16x3<2><<<grid, NTHREADS, SMEM_SZ>>>(xh, xl, wvh, wvl, nullptr, vth, vtl, b_v,
                                                    MTOT, DM, DM, 1.0f, 0, 0,
                                                    (size_t)DM * SEQ, SEQ);
    }

    // #6: scores P = Q K^T / sqrt(d)   <-- ncu -s 5 -c 1 profiles this launch
    {
        dim3 grid(SEQ / BN, SEQ / BM, BATCH);
        gemm_bf16x3<0><<<grid, NTHREADS, SMEM_SZ>>>(qh, ql, kh, kl, Pp, nullptr, nullptr,
                                                    nullptr, SEQ, SEQ, DM, invSqrtD,
                                                    (size_t)SEQ * DM, (size_t)SEQ * DM,
                                                    (size_t)SEQ * SEQ, 0);
    }

    // #7 softmax
    softmax_split<<<BATCH * SEQ, 256>>>(Pp, ph, pl, SEQ);

    // #8: O = P V   (B = V^T, K-major)
    {
        dim3 grid(DM / BN, SEQ / BM, BATCH);
        gemm_bf16x3<1><<<grid, NTHREADS, SMEM_SZ>>>(ph, pl, vth, vtl, nullptr, oh, ol, nullptr,
                                                    SEQ, DM, SEQ, 1.0f,
                                                    (size_t)SEQ * SEQ, (size_t)DM * SEQ,
                                                    (size_t)SEQ * DM, 0);
    }

    // #9: out = O W_out^T + b_out
    {
        dim3 grid(DM / BN, MTOT / BM, 1);
        gemm_bf16x3<0><<<grid, NTHREADS, SMEM_SZ>>>(oh, ol, woh, wol, out, nullptr, nullptr,
                                                    b_o, MTOT, DM, DM, 1.0f, 0, 0, 0, 0);
    }
}

// round 5
// speedup vs baseline: 4.8491x; 1.4542x over previous
#include <cuda_runtime.h>
#include <cuda_fp16.h>
#include <cstdint>

#define BATCH 4
#define SEQ   2048
#define DM    1024
#define MTOT  (BATCH * SEQ)     // 8192

#define BM 128
#define BN 128
#define BK 64                    // fp16 per k-chunk (128 B rows)
#define NTHREADS 256
#define TILE_BYTES 16384         // 128 rows x 128 B
#define STAGE_BYTES (3 * TILE_BYTES)   // Ah Al Bh
#define NSTAGE 4
#define SMEM_SZ (NSTAGE * STAGE_BYTES) // 196608

// ---------------- device scratch ----------------
#define NX ((size_t)MTOT * DM)
#define NW ((size_t)DM * DM)
#define NP ((size_t)BATCH * SEQ * SEQ)

__device__ float g_P[NP];
__device__ __half g_xh[NX],  g_xl[NX];
__device__ __half g_wq[NW], g_wk[NW], g_wv[NW], g_wo[NW];   // hi only
__device__ __half g_qh[NX],  g_ql[NX];
__device__ __half g_kh[NX];                                  // hi only
__device__ __half g_vth[NX];                                 // V^T hi only, per batch [DM][SEQ]
__device__ __half g_ph[NP],  g_pl[NP];
__device__ __half g_oh[NX],  g_ol[NX];

// ---------------- helpers ----------------
static __device__ __forceinline__ uint32_t smem_u32(const void* p) {
    uint32_t a;
    asm("{ .reg .u64 t; cvta.to.shared.u64 t, %1; cvt.u32.u64 %0, t; }" : "=r"(a) : "l"(p));
    return a;
}
static __device__ __forceinline__ uint32_t swz(uint32_t o) { return o ^ ((o >> 3) & 0x70); }

static __device__ __forceinline__ void cpa16(uint32_t s, const void* g) {
    asm volatile("cp.async.cg.shared.global [%0], [%1], 16;" :: "r"(s), "l"(g));
}
static __device__ __forceinline__ void cpa_commit() { asm volatile("cp.async.commit_group;"); }

static __device__ __forceinline__ void ldsm4(uint32_t (&r)[4], uint32_t addr) {
    asm volatile("ldmatrix.sync.aligned.m8n8.x4.shared.b16 {%0,%1,%2,%3}, [%4];"
                 : "=r"(r[0]), "=r"(r[1]), "=r"(r[2]), "=r"(r[3]) : "r"(addr));
}
static __device__ __forceinline__ void mma16816(float (&d)[4], const uint32_t (&a)[4],
                                                uint32_t b0, uint32_t b1) {
    asm volatile("mma.sync.aligned.m16n8k16.row.col.f32.f16.f16.f32 "
                 "{%0,%1,%2,%3}, {%4,%5,%6,%7}, {%8,%9}, {%0,%1,%2,%3};"
                 : "+f"(d[0]), "+f"(d[1]), "+f"(d[2]), "+f"(d[3])
                 : "r"(a[0]), "r"(a[1]), "r"(a[2]), "r"(a[3]), "r"(b0), "r"(b1));
}
static __device__ __forceinline__ uint32_t packh(__half a, __half b) {
    __half2 p = __halves2half2(a, b);
    return *reinterpret_cast<uint32_t*>(&p);
}

// ---------------- split / convert kernels ----------------
__global__ void splitx_kernel(const float* __restrict__ src, __half* __restrict__ h,
                              __half* __restrict__ l, size_t n) {
    size_t i = (size_t)blockIdx.x * blockDim.x + threadIdx.x;
    size_t stride = (size_t)gridDim.x * blockDim.x;
    for (; i < n; i += stride) {
        float v = src[i];
        __half hi = __float2half_rn(v);
        h[i] = hi;
        l[i] = __float2half_rn(v - __half2float(hi));
    }
}

__global__ void conv4_kernel(const float* __restrict__ s0, const float* __restrict__ s1,
                             const float* __restrict__ s2, const float* __restrict__ s3,
                             __half* __restrict__ h0, __half* __restrict__ h1,
                             __half* __restrict__ h2, __half* __restrict__ h3, size_t n) {
    const float* src = (blockIdx.y == 0) ? s0 : (blockIdx.y == 1) ? s1
                        : (blockIdx.y == 2) ? s2 : s3;
    __half* h = (blockIdx.y == 0) ? h0 : (blockIdx.y == 1) ? h1
                 : (blockIdx.y == 2) ? h2 : h3;
    size_t i = (size_t)blockIdx.x * blockDim.x + threadIdx.x;
    size_t stride = (size_t)gridDim.x * blockDim.x;
    for (; i < n; i += stride) h[i] = __float2half_rn(src[i]);
}

// ---------------- stage loader: Ah, Al, Bh tiles ----------------
static __device__ __forceinline__ void load_stage(uint32_t sbase,
                                                  const __half* const* base,
                                                  int K, int k0, int tid) {
    const int tr = tid >> 3;        // 0..31
    const int tc = tid & 7;         // 16B column
    #pragma unroll
    for (int s = 0; s < 3; s++) {
        const __half* g = base[s] + (size_t)tr * K + k0 + tc * 8;
        uint32_t so = sbase + s * TILE_BYTES;
        #pragma unroll
        for (int r = 0; r < 4; r++) {
            uint32_t off = (uint32_t)(tr + r * 32) * 128 + tc * 16;
            cpa16(so + swz(off), g + (size_t)(r * 32) * K);
        }
    }
}

// ---------------- shared mainloop ----------------
// accumulates acc = (Ah+Al) * Bh^T over K
static __device__ __forceinline__ void mainloop(uint32_t sb, const __half* const* base,
                                                int K, int tid, int wid, int lane,
                                                float (*acc)[4]) {
    const int m0 = (wid & 3) * 32;
    const int n0 = (wid >> 2) * 64;
    const uint32_t a_row  = lane & 15;
    const uint32_t a_half = (lane >> 4) * 16;
    const uint32_t b_row  = (lane & 7) + ((lane >> 4) & 1) * 8;
    const uint32_t b_half = ((lane >> 3) & 1) * 16;

    const int NC = K / BK;
    #pragma unroll
    for (int s = 0; s < NSTAGE - 1; s++) {
        if (s < NC) load_stage(sb + s * STAGE_BYTES, base, K, s * BK, tid);
        cpa_commit();
    }

    for (int c = 0; c < NC; c++) {
        asm volatile("cp.async.wait_group 2;" ::: "memory");
        __syncthreads();

        // issue loads for chunk c+NSTAGE-1 (overwrites chunk c-1's buffer: safe post-barrier)
        if (c + NSTAGE - 1 < NC)
            load_stage(sb + ((c + NSTAGE - 1) % NSTAGE) * STAGE_BYTES, base, K,
                       (c + NSTAGE - 1) * BK, tid);
        cpa_commit();   // empty group in tail keeps wait_group accounting exact

        const uint32_t st = sb + (c % NSTAGE) * STAGE_BYTES;
        const uint32_t tAh = st, tAl = st + TILE_BYTES, tBh = st + 2 * TILE_BYTES;

        #pragma unroll
        for (int kk = 0; kk < 4; kk++) {
            const uint32_t kb = kk * 32;
            uint32_t ah[2][4], al[2][4], bh[4][4];
            #pragma unroll
            for (int t = 0; t < 2; t++) {
                uint32_t off = swz((uint32_t)(m0 + t * 16 + a_row) * 128 + kb + a_half);
                ldsm4(ah[t], tAh + off);
                ldsm4(al[t], tAl + off);
            }
            #pragma unroll
            for (int u = 0; u < 4; u++) {
                uint32_t off = swz((uint32_t)(n0 + u * 16 + b_row) * 128 + kb + b_half);
                ldsm4(bh[u], tBh + off);
            }
            #pragma unroll
            for (int t = 0; t < 2; t++)
                #pragma unroll
                for (int u = 0; u < 4; u++) {
                    #pragma unroll
                    for (int j = 0; j < 2; j++) {
                        float (&d)[4] = acc[t * 8 + u * 2 + j];
                        const uint32_t B0 = bh[u][j * 2], B1 = bh[u][j * 2 + 1];
                        mma16816(d, ah[t], B0, B1);
                        mma16816(d, al[t], B0, B1);
                    }
                }
        }
    }
}

// ---------------- generic GEMM: OUTMODE 0: fp32   1: split (Ch, Cl) ----------------
template <int OUTMODE>
__global__ __launch_bounds__(NTHREADS, 1)
void gemm_f16x2(const __half* __restrict__ Ah, const __half* __restrict__ Al,
                const __half* __restrict__ Bh,
                float* __restrict__ Cf, __half* __restrict__ Ch, __half* __restrict__ Cl,
                const float* __restrict__ bias,
                int M, int N, int K, float scale,
                size_t sA, size_t sB, size_t sC) {
    extern __shared__ __align__(1024) char smem[];
    const uint32_t sb = smem_u32(smem);
    const int tid = threadIdx.x, wid = tid >> 5, lane = tid & 31;

    Ah += (size_t)blockIdx.z * sA;  Al += (size_t)blockIdx.z * sA;
    Bh += (size_t)blockIdx.z * sB;

    const int mBase = blockIdx.y * BM;
    const int nBase = blockIdx.x * BN;
    const __half* base[3] = { Ah + (size_t)mBase * K, Al + (size_t)mBase * K,
                              Bh + (size_t)nBase * K };

    float acc[16][4];
    #pragma unroll
    for (int i = 0; i < 16; i++)
        #pragma unroll
        for (int j = 0; j < 4; j++) acc[i][j] = 0.0f;

    mainloop(sb, base, K, tid, wid, lane, acc);

    const int m0 = (wid & 3) * 32, n0 = (wid >> 2) * 64;
    const int qrow = lane >> 2, qcol = (lane & 3) * 2;
    #pragma unroll
    for (int t = 0; t < 2; t++)
        #pragma unroll
        for (int u = 0; u < 4; u++)
            #pragma unroll
            for (int j = 0; j < 2; j++) {
                const float* d = acc[t * 8 + u * 2 + j];
                const int m = mBase + m0 + t * 16 + qrow;
                const int n = nBase + n0 + u * 16 + j * 8 + qcol;
                float b0 = 0.f, b1 = 0.f;
                if (bias) { b0 = bias[n]; b1 = bias[n + 1]; }
                float v0 = d[0] * scale + b0, v1 = d[1] * scale + b1;
                float v2 = d[2] * scale + b0, v3 = d[3] * scale + b1;
                const size_t o0 = (size_t)blockIdx.z * sC + (size_t)m * N + n;
                const size_t o1 = o0 + (size_t)8 * N;
                if (OUTMODE == 0) {
                    *reinterpret_cast<float2*>(&Cf[o0]) = make_float2(v0, v1);
                    *reinterpret_cast<float2*>(&Cf[o1]) = make_float2(v2, v3);
                } else {
                    __half h0 = __float2half_rn(v0), h1 = __float2half_rn(v1);
                    __half h2 = __float2half_rn(v2), h3 = __float2half_rn(v3);
                    *reinterpret_cast<uint32_t*>(&Ch[o0]) = packh(h0, h1);
                    *reinterpret_cast<uint32_t*>(&Ch[o1]) = packh(h2, h3);
                    *reinterpret_cast<uint32_t*>(&Cl[o0]) =
                        packh(__float2half_rn(v0 - __half2float(h0)),
                              __float2half_rn(v1 - __half2float(h1)));
                    *reinterpret_cast<uint32_t*>(&Cl[o1]) =
                        packh(__float2half_rn(v2 - __half2float(h2)),
                              __float2half_rn(v3 - __half2float(h3)));
                }
            }
}

// ---------------- fused QKV projection: z=0 Q(split) z=1 K(hi) z=2 V^T(hi) ----------------
__global__ __launch_bounds__(NTHREADS, 1)
void gemm_qkv(const __half* __restrict__ xh, const __half* __restrict__ xl,
              const __half* __restrict__ wq, const __half* __restrict__ wk,
              const __half* __restrict__ wv,
              __half* __restrict__ qh, __half* __restrict__ ql,
              __half* __restrict__ kh, __half* __restrict__ vth,
              const float* __restrict__ bq, const float* __restrict__ bk,
              const float* __restrict__ bv) {
    extern __shared__ __align__(1024) char smem[];
    const uint32_t sb = smem_u32(smem);
    const int tid = threadIdx.x, wid = tid >> 5, lane = tid & 31;
    const int z = blockIdx.z;
    const int K = DM, N = DM;

    const __half* Bh = (z == 0) ? wq : (z == 1) ? wk : wv;
    const float* bias = (z == 0) ? bq : (z == 1) ? bk : bv;

    const int mBase = blockIdx.y * BM;
    const int nBase = blockIdx.x * BN;
    const __half* base[3] = { xh + (size_t)mBase * K, xl + (size_t)mBase * K,
                              Bh + (size_t)nBase * K };

    float acc[16][4];
    #pragma unroll
    for (int i = 0; i < 16; i++)
        #pragma unroll
        for (int j = 0; j < 4; j++) acc[i][j] = 0.0f;

    mainloop(sb, base, K, tid, wid, lane, acc);

    const int m0 = (wid & 3) * 32, n0 = (wid >> 2) * 64;
    const int qrow = lane >> 2, qcol = (lane & 3) * 2;
    #pragma unroll
    for (int t = 0; t < 2; t++)
        #pragma unroll
        for (int u = 0; u < 4; u++)
            #pragma unroll
            for (int j = 0; j < 2; j++) {
                const float* d = acc[t * 8 + u * 2 + j];
                const int m = mBase + m0 + t * 16 + qrow;
                const int n = nBase + n0 + u * 16 + j * 8 + qcol;
                const float b0 = bias[n], b1 = bias[n + 1];
                float v0 = d[0] + b0, v1 = d[1] + b1;
                float v2 = d[2] + b0, v3 = d[3] + b1;
                if (z == 0) {
                    const size_t o0 = (size_t)m * N + n;
                    const size_t o1 = o0 + (size_t)8 * N;
                    __half h0 = __float2half_rn(v0), h1 = __float2half_rn(v1);
                    __half h2 = __float2half_rn(v2), h3 = __float2half_rn(v3);
                    *reinterpret_cast<uint32_t*>(&qh[o0]) = packh(h0, h1);
                    *reinterpret_cast<uint32_t*>(&qh[o1]) = packh(h2, h3);
                    *reinterpret_cast<uint32_t*>(&ql[o0]) =
                        packh(__float2half_rn(v0 - __half2float(h0)),
                              __float2half_rn(v1 - __half2float(h1)));
                    *reinterpret_cast<uint32_t*>(&ql[o1]) =
                        packh(__float2half_rn(v2 - __half2float(h2)),
                              __float2half_rn(v3 - __half2float(h3)));
                } else if (z == 1) {
                    const size_t o0 = (size_t)m * N + n;
                    const size_t o1 = o0 + (size_t)8 * N;
                    *reinterpret_cast<uint32_t*>(&kh[o0]) =
                        packh(__float2half_rn(v0), __float2half_rn(v1));
                    *reinterpret_cast<uint32_t*>(&kh[o1]) =
                        packh(__float2half_rn(v2), __float2half_rn(v3));
                } else {
                    // V^T: per batch [DM][SEQ]; batch = m / SEQ
                    const size_t boff = (size_t)(m / SEQ) * ((size_t)DM * SEQ);
                    const int mr = m % SEQ;
                    vth[boff + (size_t)n * SEQ + mr]           = __float2half_rn(v0);
                    vth[boff + (size_t)(n + 1) * SEQ + mr]     = __float2half_rn(v1);
                    vth[boff + (size_t)n * SEQ + mr + 8]       = __float2half_rn(v2);
                    vth[boff + (size_t)(n + 1) * SEQ + mr + 8] = __float2half_rn(v3);
                }
            }
}

// ---------------- softmax rows + fused fp16 split, SMEM-resident ----------------
__global__ __launch_bounds__(256)
void softmax_split(const float* __restrict__ P, __half* __restrict__ Ph,
                   __half* __restrict__ Pl, int n) {
    const int tid = threadIdx.x;
    const size_t roff = (size_t)blockIdx.x * n;
    const float* row = P + roff;

    __shared__ float srow[SEQ];
    __shared__ float red[8];
    __shared__ float bcast;

    float mx = -1e30f;
    for (int i = tid; i < n; i += 256) {
        float v = row[i];
        srow[i] = v;
        mx = fmaxf(mx, v);
    }
    #pragma unroll
    for (int o = 16; o; o >>= 1) mx = fmaxf(mx, __shfl_xor_sync(0xffffffffu, mx, o));
    if ((tid & 31) == 0) red[tid >> 5] = mx;
    __syncthreads();
    if (tid == 0) {
        float v = red[0];
        #pragma unroll
        for (int w = 1; w < 8; w++) v = fmaxf(v, red[w]);
        bcast = v;
    }
    __syncthreads();
    mx = bcast;
    __syncthreads();

    float s = 0.0f;
    for (int i = tid; i < n; i += 256) {
        float e = __expf(srow[i] - mx);
        srow[i] = e;
        s += e;
    }
    #pragma unroll
    for (int o = 16; o; o >>= 1) s += __shfl_xor_sync(0xffffffffu, s, o);
    if ((tid & 31) == 0) red[tid >> 5] = s;
    __syncthreads();
    if (tid == 0) {
        float v = 0.0f;
        #pragma unroll
        for (int w = 0; w < 8; w++) v += red[w];
        bcast = 1.0f / v;
    }
    __syncthreads();
    const float inv = bcast;

    for (int i = tid; i < n; i += 256) {
        float p = srow[i] * inv;
        __half h = __float2half_rn(p);
        Ph[roff + i] = h;
        Pl[roff + i] = __float2half_rn(p - __half2float(h));
    }
}

// ---------------- launch ----------------
extern "C" void kernel_launch(void* const* d_in, const int* in_sizes, int n_in,
                              void* d_out, int out_size) {
    (void)in_sizes; (void)n_in; (void)out_size;

    const float* x   = (const float*)d_in[0];
    const float* w_q = (const float*)d_in[1];
    const float* b_q = (const float*)d_in[2];
    const float* w_k = (const float*)d_in[3];
    const float* b_k = (const float*)d_in[4];
    const float* w_v = (const float*)d_in[5];
    const float* b_v = (const float*)d_in[6];
    const float* w_o = (const float*)d_in[7];
    const float* b_o = (const float*)d_in[8];
    float* out = (float*)d_out;

    float* Pp;
    __half *xh, *xl, *wq, *wk, *wv, *wo, *qh, *ql, *kh, *vth, *ph, *pl, *oh, *ol;
    cudaGetSymbolAddress((void**)&Pp, g_P);
    cudaGetSymbolAddress((void**)&xh, g_xh);   cudaGetSymbolAddress((void**)&xl, g_xl);
    cudaGetSymbolAddress((void**)&wq, g_wq);   cudaGetSymbolAddress((void**)&wk, g_wk);
    cudaGetSymbolAddress((void**)&wv, g_wv);   cudaGetSymbolAddress((void**)&wo, g_wo);
    cudaGetSymbolAddress((void**)&qh, g_qh);   cudaGetSymbolAddress((void**)&ql, g_ql);
    cudaGetSymbolAddress((void**)&kh, g_kh);   cudaGetSymbolAddress((void**)&vth, g_vth);
    cudaGetSymbolAddress((void**)&ph, g_ph);   cudaGetSymbolAddress((void**)&pl, g_pl);
    cudaGetSymbolAddress((void**)&oh, g_oh);   cudaGetSymbolAddress((void**)&ol, g_ol);

    cudaFuncSetAttribute(gemm_f16x2<0>, cudaFuncAttributeMaxDynamicSharedMemorySize, SMEM_SZ);
    cudaFuncSetAttribute(gemm_f16x2<1>, cudaFuncAttributeMaxDynamicSharedMemorySize, SMEM_SZ);
    cudaFuncSetAttribute(gemm_qkv, cudaFuncAttributeMaxDynamicSharedMemorySize, SMEM_SZ);

    // #1 split x, #2 convert weights
    splitx_kernel<<<1024, 256>>>(x, xh, xl, NX);
    {
        dim3 g(128, 4);
        conv4_kernel<<<g, 256>>>(w_q, w_k, w_v, w_o, wq, wk, wv, wo, NW);
    }

    // #3 fused QKV projection
    {
        dim3 grid(DM / BN, MTOT / BM, 3);
        gemm_qkv<<<grid, NTHREADS, SMEM_SZ>>>(xh, xl, wq, wk, wv, qh, ql, kh, vth,
                                              b_q, b_k, b_v);
    }

    // #4 scores P = Q K^T / sqrt(d)
    {
        dim3 grid(SEQ / BN, SEQ / BM, BATCH);
        gemm_f16x2<0><<<grid, NTHREADS, SMEM_SZ>>>(qh, ql, kh, Pp, nullptr, nullptr, nullptr,
                                                   SEQ, SEQ, DM, 0.03125f,
                                                   (size_t)SEQ * DM, (size_t)SEQ * DM,
                                                   (size_t)SEQ * SEQ);
    }

    // #5 softmax + split
    softmax_split<<<BATCH * SEQ, 256>>>(Pp, ph, pl, SEQ);

    // #6 O = P V  (B = V^T hi, K-major)  <-- ncu profiles this launch
    {
        dim3 grid(DM / BN, SEQ / BM, BATCH);
        gemm_f16x2<1><<<grid, NTHREADS, SMEM_SZ>>>(ph, pl, vth, nullptr, oh, ol, nullptr,
                                                   SEQ, DM, SEQ, 1.0f,
                                                   (size_t)SEQ * SEQ, (size_t)DM * SEQ,
                                                   (size_t)SEQ * DM);
    }

    // #7 out = O W_out^T + b_out
    {
        dim3 grid(DM / BN, MTOT / BM, 1);
        gemm_f16x2<0><<<grid, NTHREADS, SMEM_SZ>>>(oh, ol, wo, out, nullptr, nullptr, b_o,
                                                   MTOT, DM, DM, 1.0f, 0, 0, 0);
    }
}

// round 6
// speedup vs baseline: 5.3369x; 1.1006x over previous
#include <cuda_runtime.h>
#include <cuda_fp16.h>
#include <cstdint>

#define BATCH 4
#define SEQ   2048
#define DM    1024
#define MTOT  (BATCH * SEQ)     // 8192

#define BM 128
#define BN 128
#define BK 64                    // fp16 per k-chunk (128 B rows)
#define NTHREADS 256
#define TILE_BYTES 16384         // 128 rows x 128 B
#define STAGE_BYTES (3 * TILE_BYTES)   // Ah Al Bh (Al slot unused when !SPLIT)
#define NSTAGE 4
#define SMEM_SZ (NSTAGE * STAGE_BYTES) // 196608

// ---------------- device scratch ----------------
#define NX ((size_t)MTOT * DM)
#define NW ((size_t)DM * DM)
#define NP ((size_t)BATCH * SEQ * SEQ)

__device__ float g_P[NP];
__device__ __half g_xh[NX],  g_xl[NX];
__device__ __half g_wq[NW], g_wk[NW], g_wv[NW], g_wo[NW];   // hi only
__device__ __half g_qh[NX],  g_ql[NX];
__device__ __half g_kh[NX];                                  // hi only
__device__ __half g_vth[NX];                                 // V^T hi only, per batch [DM][SEQ]
__device__ __half g_ph[NP],  g_pl[NP];
__device__ __half g_oh[NX],  g_ol[NX];

// ---------------- helpers ----------------
static __device__ __forceinline__ uint32_t smem_u32(const void* p) {
    uint32_t a;
    asm("{ .reg .u64 t; cvta.to.shared.u64 t, %1; cvt.u32.u64 %0, t; }" : "=r"(a) : "l"(p));
    return a;
}
static __device__ __forceinline__ uint32_t swz(uint32_t o) { return o ^ ((o >> 3) & 0x70); }

static __device__ __forceinline__ void cpa16(uint32_t s, const void* g) {
    asm volatile("cp.async.cg.shared.global [%0], [%1], 16;" :: "r"(s), "l"(g));
}
static __device__ __forceinline__ void cpa_commit() { asm volatile("cp.async.commit_group;"); }

static __device__ __forceinline__ void ldsm4(uint32_t (&r)[4], uint32_t addr) {
    asm volatile("ldmatrix.sync.aligned.m8n8.x4.shared.b16 {%0,%1,%2,%3}, [%4];"
                 : "=r"(r[0]), "=r"(r[1]), "=r"(r[2]), "=r"(r[3]) : "r"(addr));
}
static __device__ __forceinline__ void mma16816(float (&d)[4], const uint32_t (&a)[4],
                                                uint32_t b0, uint32_t b1) {
    asm volatile("mma.sync.aligned.m16n8k16.row.col.f32.f16.f16.f32 "
                 "{%0,%1,%2,%3}, {%4,%5,%6,%7}, {%8,%9}, {%0,%1,%2,%3};"
                 : "+f"(d[0]), "+f"(d[1]), "+f"(d[2]), "+f"(d[3])
                 : "r"(a[0]), "r"(a[1]), "r"(a[2]), "r"(a[3]), "r"(b0), "r"(b1));
}
static __device__ __forceinline__ uint32_t packh(__half a, __half b) {
    __half2 p = __halves2half2(a, b);
    return *reinterpret_cast<uint32_t*>(&p);
}

// ---------------- split / convert kernels ----------------
__global__ void splitx_kernel(const float* __restrict__ src, __half* __restrict__ h,
                              __half* __restrict__ l, size_t n) {
    size_t i = (size_t)blockIdx.x * blockDim.x + threadIdx.x;
    size_t stride = (size_t)gridDim.x * blockDim.x;
    for (; i < n; i += stride) {
        float v = src[i];
        __half hi = __float2half_rn(v);
        h[i] = hi;
        l[i] = __float2half_rn(v - __half2float(hi));
    }
}

__global__ void conv4_kernel(const float* __restrict__ s0, const float* __restrict__ s1,
                             const float* __restrict__ s2, const float* __restrict__ s3,
                             __half* __restrict__ h0, __half* __restrict__ h1,
                             __half* __restrict__ h2, __half* __restrict__ h3, size_t n) {
    const float* src = (blockIdx.y == 0) ? s0 : (blockIdx.y == 1) ? s1
                        : (blockIdx.y == 2) ? s2 : s3;
    __half* h = (blockIdx.y == 0) ? h0 : (blockIdx.y == 1) ? h1
                 : (blockIdx.y == 2) ? h2 : h3;
    size_t i = (size_t)blockIdx.x * blockDim.x + threadIdx.x;
    size_t stride = (size_t)gridDim.x * blockDim.x;
    for (; i < n; i += stride) h[i] = __float2half_rn(src[i]);
}

// ---------------- stage loader: Ah, (Al), Bh tiles ----------------
template <bool SPLIT>
static __device__ __forceinline__ void load_stage(uint32_t sbase,
                                                  const __half* const* base,
                                                  int K, int k0, int tid) {
    const int tr = tid >> 3;        // 0..31
    const int tc = tid & 7;         // 16B column
    #pragma unroll
    for (int s = 0; s < 3; s++) {
        if (!SPLIT && s == 1) continue;
        const __half* g = base[s] + (size_t)tr * K + k0 + tc * 8;
        uint32_t so = sbase + s * TILE_BYTES;
        #pragma unroll
        for (int r = 0; r < 4; r++) {
            uint32_t off = (uint32_t)(tr + r * 32) * 128 + tc * 16;
            cpa16(so + swz(off), g + (size_t)(r * 32) * K);
        }
    }
}

// ---------------- shared mainloop ----------------
// accumulates acc = (Ah [+ Al]) * Bh^T over K
template <bool SPLIT>
static __device__ __forceinline__ void mainloop(uint32_t sb, const __half* const* base,
                                                int K, int tid, int wid, int lane,
                                                float (*acc)[4]) {
    const int m0 = (wid & 3) * 32;
    const int n0 = (wid >> 2) * 64;
    const uint32_t a_row  = lane & 15;
    const uint32_t a_half = (lane >> 4) * 16;
    const uint32_t b_row  = (lane & 7) + ((lane >> 4) & 1) * 8;
    const uint32_t b_half = ((lane >> 3) & 1) * 16;

    const int NC = K / BK;
    #pragma unroll
    for (int s = 0; s < NSTAGE - 1; s++) {
        if (s < NC) load_stage<SPLIT>(sb + s * STAGE_BYTES, base, K, s * BK, tid);
        cpa_commit();
    }

    for (int c = 0; c < NC; c++) {
        asm volatile("cp.async.wait_group 2;" ::: "memory");
        __syncthreads();

        if (c + NSTAGE - 1 < NC)
            load_stage<SPLIT>(sb + ((c + NSTAGE - 1) % NSTAGE) * STAGE_BYTES, base, K,
                              (c + NSTAGE - 1) * BK, tid);
        cpa_commit();   // empty group in tail keeps wait_group accounting exact

        const uint32_t st = sb + (c % NSTAGE) * STAGE_BYTES;
        const uint32_t tAh = st, tAl = st + TILE_BYTES, tBh = st + 2 * TILE_BYTES;

        #pragma unroll
        for (int kk = 0; kk < 4; kk++) {
            const uint32_t kb = kk * 32;
            uint32_t ah[2][4], al[2][4], bh[4][4];
            #pragma unroll
            for (int t = 0; t < 2; t++) {
                uint32_t off = swz((uint32_t)(m0 + t * 16 + a_row) * 128 + kb + a_half);
                ldsm4(ah[t], tAh + off);
                if (SPLIT) ldsm4(al[t], tAl + off);
            }
            #pragma unroll
            for (int u = 0; u < 4; u++) {
                uint32_t off = swz((uint32_t)(n0 + u * 16 + b_row) * 128 + kb + b_half);
                ldsm4(bh[u], tBh + off);
            }
            #pragma unroll
            for (int t = 0; t < 2; t++)
                #pragma unroll
                for (int u = 0; u < 4; u++) {
                    #pragma unroll
                    for (int j = 0; j < 2; j++) {
                        float (&d)[4] = acc[t * 8 + u * 2 + j];
                        const uint32_t B0 = bh[u][j * 2], B1 = bh[u][j * 2 + 1];
                        mma16816(d, ah[t], B0, B1);
                        if (SPLIT) mma16816(d, al[t], B0, B1);
                    }
                }
        }
    }
}

// ---------------- generic GEMM: OUTMODE 0: fp32   1: split (Ch, Cl) ----------------
template <int OUTMODE>
__global__ __launch_bounds__(NTHREADS, 1)
void gemm_f16x2(const __half* __restrict__ Ah, const __half* __restrict__ Al,
                const __half* __restrict__ Bh,
                float* __restrict__ Cf, __half* __restrict__ Ch, __half* __restrict__ Cl,
                const float* __restrict__ bias,
                int M, int N, int K, float scale,
                size_t sA, size_t sB, size_t sC) {
    extern __shared__ __align__(1024) char smem[];
    const uint32_t sb = smem_u32(smem);
    const int tid = threadIdx.x, wid = tid >> 5, lane = tid & 31;

    Ah += (size_t)blockIdx.z * sA;  Al += (size_t)blockIdx.z * sA;
    Bh += (size_t)blockIdx.z * sB;

    const int mBase = blockIdx.y * BM;
    const int nBase = blockIdx.x * BN;
    const __half* base[3] = { Ah + (size_t)mBase * K, Al + (size_t)mBase * K,
                              Bh + (size_t)nBase * K };

    float acc[16][4];
    #pragma unroll
    for (int i = 0; i < 16; i++)
        #pragma unroll
        for (int j = 0; j < 4; j++) acc[i][j] = 0.0f;

    mainloop<true>(sb, base, K, tid, wid, lane, acc);

    const int m0 = (wid & 3) * 32, n0 = (wid >> 2) * 64;
    const int qrow = lane >> 2, qcol = (lane & 3) * 2;
    #pragma unroll
    for (int t = 0; t < 2; t++)
        #pragma unroll
        for (int u = 0; u < 4; u++)
            #pragma unroll
            for (int j = 0; j < 2; j++) {
                const float* d = acc[t * 8 + u * 2 + j];
                const int m = mBase + m0 + t * 16 + qrow;
                const int n = nBase + n0 + u * 16 + j * 8 + qcol;
                float b0 = 0.f, b1 = 0.f;
                if (bias) { b0 = bias[n]; b1 = bias[n + 1]; }
                float v0 = d[0] * scale + b0, v1 = d[1] * scale + b1;
                float v2 = d[2] * scale + b0, v3 = d[3] * scale + b1;
                const size_t o0 = (size_t)blockIdx.z * sC + (size_t)m * N + n;
                const size_t o1 = o0 + (size_t)8 * N;
                if (OUTMODE == 0) {
                    *reinterpret_cast<float2*>(&Cf[o0]) = make_float2(v0, v1);
                    *reinterpret_cast<float2*>(&Cf[o1]) = make_float2(v2, v3);
                } else {
                    __half h0 = __float2half_rn(v0), h1 = __float2half_rn(v1);
                    __half h2 = __float2half_rn(v2), h3 = __float2half_rn(v3);
                    *reinterpret_cast<uint32_t*>(&Ch[o0]) = packh(h0, h1);
                    *reinterpret_cast<uint32_t*>(&Ch[o1]) = packh(h2, h3);
                    *reinterpret_cast<uint32_t*>(&Cl[o0]) =
                        packh(__float2half_rn(v0 - __half2float(h0)),
                              __float2half_rn(v1 - __half2float(h1)));
                    *reinterpret_cast<uint32_t*>(&Cl[o1]) =
                        packh(__float2half_rn(v2 - __half2float(h2)),
                              __float2half_rn(v3 - __half2float(h3)));
                }
            }
}

// ---------------- fused QKV projection: z=0 Q(split, 2-MMA) z=1 K(hi, 1-MMA) z=2 V^T(hi, 1-MMA) ----------------
__global__ __launch_bounds__(NTHREADS, 1)
void gemm_qkv(const __half* __restrict__ xh, const __half* __restrict__ xl,
              const __half* __restrict__ wq, const __half* __restrict__ wk,
              const __half* __restrict__ wv,
              __half* __restrict__ qh, __half* __restrict__ ql,
              __half* __restrict__ kh, __half* __restrict__ vth,
              const float* __restrict__ bq, const float* __restrict__ bk,
              const float* __restrict__ bv) {
    extern __shared__ __align__(1024) char smem[];
    const uint32_t sb = smem_u32(smem);
    const int tid = threadIdx.x, wid = tid >> 5, lane = tid & 31;
    const int z = blockIdx.z;
    const int K = DM, N = DM;

    const __half* Bh = (z == 0) ? wq : (z == 1) ? wk : wv;
    const float* bias = (z == 0) ? bq : (z == 1) ? bk : bv;

    const int mBase = blockIdx.y * BM;
    const int nBase = blockIdx.x * BN;
    const __half* base[3] = { xh + (size_t)mBase * K, xl + (size_t)mBase * K,
                              Bh + (size_t)nBase * K };

    float acc[16][4];
    #pragma unroll
    for (int i = 0; i < 16; i++)
        #pragma unroll
        for (int j = 0; j < 4; j++) acc[i][j] = 0.0f;

    if (z == 0) mainloop<true>(sb, base, K, tid, wid, lane, acc);
    else        mainloop<false>(sb, base, K, tid, wid, lane, acc);

    const int m0 = (wid & 3) * 32, n0 = (wid >> 2) * 64;
    const int qrow = lane >> 2, qcol = (lane & 3) * 2;
    #pragma unroll
    for (int t = 0; t < 2; t++)
        #pragma unroll
        for (int u = 0; u < 4; u++)
            #pragma unroll
            for (int j = 0; j < 2; j++) {
                const float* d = acc[t * 8 + u * 2 + j];
                const int m = mBase + m0 + t * 16 + qrow;
                const int n = nBase + n0 + u * 16 + j * 8 + qcol;
                const float b0 = bias[n], b1 = bias[n + 1];
                float v0 = d[0] + b0, v1 = d[1] + b1;
                float v2 = d[2] + b0, v3 = d[3] + b1;
                if (z == 0) {
                    const size_t o0 = (size_t)m * N + n;
                    const size_t o1 = o0 + (size_t)8 * N;
                    __half h0 = __float2half_rn(v0), h1 = __float2half_rn(v1);
                    __half h2 = __float2half_rn(v2), h3 = __float2half_rn(v3);
                    *reinterpret_cast<uint32_t*>(&qh[o0]) = packh(h0, h1);
                    *reinterpret_cast<uint32_t*>(&qh[o1]) = packh(h2, h3);
                    *reinterpret_cast<uint32_t*>(&ql[o0]) =
                        packh(__float2half_rn(v0 - __half2float(h0)),
                              __float2half_rn(v1 - __half2float(h1)));
                    *reinterpret_cast<uint32_t*>(&ql[o1]) =
                        packh(__float2half_rn(v2 - __half2float(h2)),
                              __float2half_rn(v3 - __half2float(h3)));
                } else if (z == 1) {
                    const size_t o0 = (size_t)m * N + n;
                    const size_t o1 = o0 + (size_t)8 * N;
                    *reinterpret_cast<uint32_t*>(&kh[o0]) =
                        packh(__float2half_rn(v0), __float2half_rn(v1));
                    *reinterpret_cast<uint32_t*>(&kh[o1]) =
                        packh(__float2half_rn(v2), __float2half_rn(v3));
                } else {
                    // V^T: per batch [DM][SEQ]; batch = m / SEQ
                    const size_t boff = (size_t)(m / SEQ) * ((size_t)DM * SEQ);
                    const int mr = m % SEQ;
                    vth[boff + (size_t)n * SEQ + mr]           = __float2half_rn(v0);
                    vth[boff + (size_t)(n + 1) * SEQ + mr]     = __float2half_rn(v1);
                    vth[boff + (size_t)n * SEQ + mr + 8]       = __float2half_rn(v2);
                    vth[boff + (size_t)(n + 1) * SEQ + mr + 8] = __float2half_rn(v3);
                }
            }
}

// ---------------- softmax rows + fused fp16 split, SMEM-resident ----------------
__global__ __launch_bounds__(256)
void softmax_split(const float* __restrict__ P, __half* __restrict__ Ph,
                   __half* __restrict__ Pl, int n) {
    const int tid = threadIdx.x;
    const size_t roff = (size_t)blockIdx.x * n;
    const float* row = P + roff;

    __shared__ float srow[SEQ];
    __shared__ float red[8];
    __shared__ float bcast;

    float mx = -1e30f;
    for (int i = tid; i < n; i += 256) {
        float v = row[i];
        srow[i] = v;
        mx = fmaxf(mx, v);
    }
    #pragma unroll
    for (int o = 16; o; o >>= 1) mx = fmaxf(mx, __shfl_xor_sync(0xffffffffu, mx, o));
    if ((tid & 31) == 0) red[tid >> 5] = mx;
    __syncthreads();
    if (tid == 0) {
        float v = red[0];
        #pragma unroll
        for (int w = 1; w < 8; w++) v = fmaxf(v, red[w]);
        bcast = v;
    }
    __syncthreads();
    mx = bcast;
    __syncthreads();

    float s = 0.0f;
    for (int i = tid; i < n; i += 256) {
        float e = __expf(srow[i] - mx);
        srow[i] = e;
        s += e;
    }
    #pragma unroll
    for (int o = 16; o; o >>= 1) s += __shfl_xor_sync(0xffffffffu, s, o);
    if ((tid & 31) == 0) red[tid >> 5] = s;
    __syncthreads();
    if (tid == 0) {
        float v = 0.0f;
        #pragma unroll
        for (int w = 0; w < 8; w++) v += red[w];
        bcast = 1.0f / v;
    }
    __syncthreads();
    const float inv = bcast;

    for (int i = tid; i < n; i += 256) {
        float p = srow[i] * inv;
        __half h = __float2half_rn(p);
        Ph[roff + i] = h;
        Pl[roff + i] = __float2half_rn(p - __half2float(h));
    }
}

// ---------------- launch ----------------
extern "C" void kernel_launch(void* const* d_in, const int* in_sizes, int n_in,
                              void* d_out, int out_size) {
    (void)in_sizes; (void)n_in; (void)out_size;

    const float* x   = (const float*)d_in[0];
    const float* w_q = (const float*)d_in[1];
    const float* b_q = (const float*)d_in[2];
    const float* w_k = (const float*)d_in[3];
    const float* b_k = (const float*)d_in[4];
    const float* w_v = (const float*)d_in[5];
    const float* b_v = (const float*)d_in[6];
    const float* w_o = (const float*)d_in[7];
    const float* b_o = (const float*)d_in[8];
    float* out = (float*)d_out;

    float* Pp;
    __half *xh, *xl, *wq, *wk, *wv, *wo, *qh, *ql, *kh, *vth, *ph, *pl, *oh, *ol;
    cudaGetSymbolAddress((void**)&Pp, g_P);
    cudaGetSymbolAddress((void**)&xh, g_xh);   cudaGetSymbolAddress((void**)&xl, g_xl);
    cudaGetSymbolAddress((void**)&wq, g_wq);   cudaGetSymbolAddress((void**)&wk, g_wk);
    cudaGetSymbolAddress((void**)&wv, g_wv);   cudaGetSymbolAddress((void**)&wo, g_wo);
    cudaGetSymbolAddress((void**)&qh, g_qh);   cudaGetSymbolAddress((void**)&ql, g_ql);
    cudaGetSymbolAddress((void**)&kh, g_kh);   cudaGetSymbolAddress((void**)&vth, g_vth);
    cudaGetSymbolAddress((void**)&ph, g_ph);   cudaGetSymbolAddress((void**)&pl, g_pl);
    cudaGetSymbolAddress((void**)&oh, g_oh);   cudaGetSymbolAddress((void**)&ol, g_ol);

    cudaFuncSetAttribute(gemm_f16x2<0>, cudaFuncAttributeMaxDynamicSharedMemorySize, SMEM_SZ);
    cudaFuncSetAttribute(gemm_f16x2<1>, cudaFuncAttributeMaxDynamicSharedMemorySize, SMEM_SZ);
    cudaFuncSetAttribute(gemm_qkv, cudaFuncAttributeMaxDynamicSharedMemorySize, SMEM_SZ);

    // #1 split x, #2 convert weights
    splitx_kernel<<<1024, 256>>>(x, xh, xl, NX);
    {
        dim3 g(128, 4);
        conv4_kernel<<<g, 256>>>(w_q, w_k, w_v, w_o, wq, wk, wv, wo, NW);
    }

    // #3 fused QKV projection
    {
        dim3 grid(DM / BN, MTOT / BM, 3);
        gemm_qkv<<<grid, NTHREADS, SMEM_SZ>>>(xh, xl, wq, wk, wv, qh, ql, kh, vth,
                                              b_q, b_k, b_v);
    }

    // #4 scores P = Q K^T / sqrt(d)
    {
        dim3 grid(SEQ / BN, SEQ / BM, BATCH);
        gemm_f16x2<0><<<grid, NTHREADS, SMEM_SZ>>>(qh, ql, kh, Pp, nullptr, nullptr, nullptr,
                                                   SEQ, SEQ, DM, 0.03125f,
                                                   (size_t)SEQ * DM, (size_t)SEQ * DM,
                                                   (size_t)SEQ * SEQ);
    }

    // #5 softmax + split
    softmax_split<<<BATCH * SEQ, 256>>>(Pp, ph, pl, SEQ);

    // #6 O = P V  (B = V^T hi, K-major)
    {
        dim3 grid(DM / BN, SEQ / BM, BATCH);
        gemm_f16x2<1><<<grid, NTHREADS, SMEM_SZ>>>(ph, pl, vth, nullptr, oh, ol, nullptr,
                                                   SEQ, DM, SEQ, 1.0f,
                                                   (size_t)SEQ * SEQ, (size_t)DM * SEQ,
                                                   (size_t)SEQ * DM);
    }

    // #7 out = O W_out^T + b_out
    {
        dim3 grid(DM / BN, MTOT / BM, 1);
        gemm_f16x2<0><<<grid, NTHREADS, SMEM_SZ>>>(oh, ol, wo, out, nullptr, nullptr, b_o,
                                                   MTOT, DM, DM, 1.0f, 0, 0, 0);
    }
}

// round 7
// speedup vs baseline: 5.7643x; 1.0801x over previous
#include <cuda_runtime.h>
#include <cuda_fp16.h>
#include <cstdint>

#define BATCH 4
#define SEQ   2048
#define DM    1024
#define MTOT  (BATCH * SEQ)     // 8192

#define BM 128
#define BN 128
#define BK 64                    // fp16 per k-chunk (128 B rows)
#define NTHREADS 256
#define TILE_BYTES 16384         // 128 rows x 128 B
#define STAGE_BYTES (3 * TILE_BYTES)   // Ah Al Bh (Al slot unused when !SPLIT)
#define NSTAGE 2
#define SMEM_SZ (NSTAGE * STAGE_BYTES) // 98304 -> 2 CTAs/SM

// ---------------- device scratch ----------------
#define NX ((size_t)MTOT * DM)
#define NW ((size_t)DM * DM)
#define NP ((size_t)BATCH * SEQ * SEQ)

__device__ float g_P[NP];
__device__ __half g_xh[NX],  g_xl[NX];
__device__ __half g_wq[NW], g_wk[NW], g_wv[NW], g_wo[NW];   // hi only
__device__ __half g_qh[NX],  g_ql[NX];
__device__ __half g_kh[NX];                                  // hi only
__device__ __half g_vth[NX];                                 // V^T hi only, per batch [DM][SEQ]
__device__ __half g_ph[NP],  g_pl[NP];
__device__ __half g_oh[NX],  g_ol[NX];

// ---------------- helpers ----------------
static __device__ __forceinline__ uint32_t smem_u32(const void* p) {
    uint32_t a;
    asm("{ .reg .u64 t; cvta.to.shared.u64 t, %1; cvt.u32.u64 %0, t; }" : "=r"(a) : "l"(p));
    return a;
}
static __device__ __forceinline__ uint32_t swz(uint32_t o) { return o ^ ((o >> 3) & 0x70); }

static __device__ __forceinline__ void cpa16(uint32_t s, const void* g) {
    asm volatile("cp.async.cg.shared.global [%0], [%1], 16;" :: "r"(s), "l"(g));
}
static __device__ __forceinline__ void cpa_commit() { asm volatile("cp.async.commit_group;"); }

static __device__ __forceinline__ void ldsm4(uint32_t (&r)[4], uint32_t addr) {
    asm volatile("ldmatrix.sync.aligned.m8n8.x4.shared.b16 {%0,%1,%2,%3}, [%4];"
                 : "=r"(r[0]), "=r"(r[1]), "=r"(r[2]), "=r"(r[3]) : "r"(addr));
}
static __device__ __forceinline__ void mma16816(float (&d)[4], const uint32_t (&a)[4],
                                                uint32_t b0, uint32_t b1) {
    asm volatile("mma.sync.aligned.m16n8k16.row.col.f32.f16.f16.f32 "
                 "{%0,%1,%2,%3}, {%4,%5,%6,%7}, {%8,%9}, {%0,%1,%2,%3};"
                 : "+f"(d[0]), "+f"(d[1]), "+f"(d[2]), "+f"(d[3])
                 : "r"(a[0]), "r"(a[1]), "r"(a[2]), "r"(a[3]), "r"(b0), "r"(b1));
}
static __device__ __forceinline__ uint32_t packh(__half a, __half b) {
    __half2 p = __halves2half2(a, b);
    return *reinterpret_cast<uint32_t*>(&p);
}

// ---------------- split / convert kernels ----------------
__global__ void splitx_kernel(const float* __restrict__ src, __half* __restrict__ h,
                              __half* __restrict__ l, size_t n) {
    size_t i = (size_t)blockIdx.x * blockDim.x + threadIdx.x;
    size_t stride = (size_t)gridDim.x * blockDim.x;
    for (; i < n; i += stride) {
        float v = src[i];
        __half hi = __float2half_rn(v);
        h[i] = hi;
        l[i] = __float2half_rn(v - __half2float(hi));
    }
}

__global__ void conv4_kernel(const float* __restrict__ s0, const float* __restrict__ s1,
                             const float* __restrict__ s2, const float* __restrict__ s3,
                             __half* __restrict__ h0, __half* __restrict__ h1,
                             __half* __restrict__ h2, __half* __restrict__ h3, size_t n) {
    const float* src = (blockIdx.y == 0) ? s0 : (blockIdx.y == 1) ? s1
                        : (blockIdx.y == 2) ? s2 : s3;
    __half* h = (blockIdx.y == 0) ? h0 : (blockIdx.y == 1) ? h1
                 : (blockIdx.y == 2) ? h2 : h3;
    size_t i = (size_t)blockIdx.x * blockDim.x + threadIdx.x;
    size_t stride = (size_t)gridDim.x * blockDim.x;
    for (; i < n; i += stride) h[i] = __float2half_rn(src[i]);
}

// ---------------- stage loader: Ah, (Al), Bh tiles ----------------
template <bool SPLIT>
static __device__ __forceinline__ void load_stage(uint32_t sbase,
                                                  const __half* const* base,
                                                  int K, int k0, int tid) {
    const int tr = tid >> 3;        // 0..31
    const int tc = tid & 7;         // 16B column
    #pragma unroll
    for (int s = 0; s < 3; s++) {
        if (!SPLIT && s == 1) continue;
        const __half* g = base[s] + (size_t)tr * K + k0 + tc * 8;
        uint32_t so = sbase + s * TILE_BYTES;
        #pragma unroll
        for (int r = 0; r < 4; r++) {
            uint32_t off = (uint32_t)(tr + r * 32) * 128 + tc * 16;
            cpa16(so + swz(off), g + (size_t)(r * 32) * K);
        }
    }
}

// ---------------- shared mainloop ----------------
// accumulates acc = (Ah [+ Al]) * Bh^T over K
// double-buffer: wait(own) -> sync(publish + buffer-protect) -> issue c+1 -> compute c
template <bool SPLIT>
static __device__ __forceinline__ void mainloop(uint32_t sb, const __half* const* base,
                                                int K, int tid, int wid, int lane,
                                                float (*acc)[4]) {
    const int m0 = (wid & 3) * 32;
    const int n0 = (wid >> 2) * 64;
    const uint32_t a_row  = lane & 15;
    const uint32_t a_half = (lane >> 4) * 16;
    const uint32_t b_row  = (lane & 7) + ((lane >> 4) & 1) * 8;
    const uint32_t b_half = ((lane >> 3) & 1) * 16;

    const int NC = K / BK;
    load_stage<SPLIT>(sb, base, K, 0, tid);
    cpa_commit();

    for (int c = 0; c < NC; c++) {
        asm volatile("cp.async.wait_group 0;" ::: "memory");
        __syncthreads();

        if (c + 1 < NC) {
            load_stage<SPLIT>(sb + ((c + 1) & 1) * STAGE_BYTES, base, K, (c + 1) * BK, tid);
            cpa_commit();
        }

        const uint32_t st = sb + (c & 1) * STAGE_BYTES;
        const uint32_t tAh = st, tAl = st + TILE_BYTES, tBh = st + 2 * TILE_BYTES;

        #pragma unroll
        for (int kk = 0; kk < 4; kk++) {
            const uint32_t kb = kk * 32;
            uint32_t ah[2][4], al[2][4], bh[4][4];
            #pragma unroll
            for (int t = 0; t < 2; t++) {
                uint32_t off = swz((uint32_t)(m0 + t * 16 + a_row) * 128 + kb + a_half);
                ldsm4(ah[t], tAh + off);
                if (SPLIT) ldsm4(al[t], tAl + off);
            }
            #pragma unroll
            for (int u = 0; u < 4; u++) {
                uint32_t off = swz((uint32_t)(n0 + u * 16 + b_row) * 128 + kb + b_half);
                ldsm4(bh[u], tBh + off);
            }
            #pragma unroll
            for (int t = 0; t < 2; t++)
                #pragma unroll
                for (int u = 0; u < 4; u++) {
                    #pragma unroll
                    for (int j = 0; j < 2; j++) {
                        float (&d)[4] = acc[t * 8 + u * 2 + j];
                        const uint32_t B0 = bh[u][j * 2], B1 = bh[u][j * 2 + 1];
                        mma16816(d, ah[t], B0, B1);
                        if (SPLIT) mma16816(d, al[t], B0, B1);
                    }
                }
        }
    }
}

// ---------------- generic GEMM: OUTMODE 0: fp32   1: split (Ch, Cl) ----------------
template <int OUTMODE>
__global__ __launch_bounds__(NTHREADS, 2)
void gemm_f16x2(const __half* __restrict__ Ah, const __half* __restrict__ Al,
                const __half* __restrict__ Bh,
                float* __restrict__ Cf, __half* __restrict__ Ch, __half* __restrict__ Cl,
                const float* __restrict__ bias,
                int M, int N, int K, float scale,
                size_t sA, size_t sB, size_t sC) {
    extern __shared__ __align__(1024) char smem[];
    const uint32_t sb = smem_u32(smem);
    const int tid = threadIdx.x, wid = tid >> 5, lane = tid & 31;

    Ah += (size_t)blockIdx.z * sA;  Al += (size_t)blockIdx.z * sA;
    Bh += (size_t)blockIdx.z * sB;

    const int mBase = blockIdx.y * BM;
    const int nBase = blockIdx.x * BN;
    const __half* base[3] = { Ah + (size_t)mBase * K, Al + (size_t)mBase * K,
                              Bh + (size_t)nBase * K };

    float acc[16][4];
    #pragma unroll
    for (int i = 0; i < 16; i++)
        #pragma unroll
        for (int j = 0; j < 4; j++) acc[i][j] = 0.0f;

    mainloop<true>(sb, base, K, tid, wid, lane, acc);

    const int m0 = (wid & 3) * 32, n0 = (wid >> 2) * 64;
    const int qrow = lane >> 2, qcol = (lane & 3) * 2;
    #pragma unroll
    for (int t = 0; t < 2; t++)
        #pragma unroll
        for (int u = 0; u < 4; u++)
            #pragma unroll
            for (int j = 0; j < 2; j++) {
                const float* d = acc[t * 8 + u * 2 + j];
                const int m = mBase + m0 + t * 16 + qrow;
                const int n = nBase + n0 + u * 16 + j * 8 + qcol;
                float b0 = 0.f, b1 = 0.f;
                if (bias) { b0 = bias[n]; b1 = bias[n + 1]; }
                float v0 = d[0] * scale + b0, v1 = d[1] * scale + b1;
                float v2 = d[2] * scale + b0, v3 = d[3] * scale + b1;
                const size_t o0 = (size_t)blockIdx.z * sC + (size_t)m * N + n;
                const size_t o1 = o0 + (size_t)8 * N;
                if (OUTMODE == 0) {
                    *reinterpret_cast<float2*>(&Cf[o0]) = make_float2(v0, v1);
                    *reinterpret_cast<float2*>(&Cf[o1]) = make_float2(v2, v3);
                } else {
                    __half h0 = __float2half_rn(v0), h1 = __float2half_rn(v1);
                    __half h2 = __float2half_rn(v2), h3 = __float2half_rn(v3);
                    *reinterpret_cast<uint32_t*>(&Ch[o0]) = packh(h0, h1);
                    *reinterpret_cast<uint32_t*>(&Ch[o1]) = packh(h2, h3);
                    *reinterpret_cast<uint32_t*>(&Cl[o0]) =
                        packh(__float2half_rn(v0 - __half2float(h0)),
                              __float2half_rn(v1 - __half2float(h1)));
                    *reinterpret_cast<uint32_t*>(&Cl[o1]) =
                        packh(__float2half_rn(v2 - __half2float(h2)),
                              __float2half_rn(v3 - __half2float(h3)));
                }
            }
}

// ---------------- fused QKV projection: z=0 Q(split, 2-MMA) z=1 K(hi, 1-MMA) z=2 V^T(hi, 1-MMA) ----------------
__global__ __launch_bounds__(NTHREADS, 2)
void gemm_qkv(const __half* __restrict__ xh, const __half* __restrict__ xl,
              const __half* __restrict__ wq, const __half* __restrict__ wk,
              const __half* __restrict__ wv,
              __half* __restrict__ qh, __half* __restrict__ ql,
              __half* __restrict__ kh, __half* __restrict__ vth,
              const float* __restrict__ bq, const float* __restrict__ bk,
              const float* __restrict__ bv) {
    extern __shared__ __align__(1024) char smem[];
    const uint32_t sb = smem_u32(smem);
    const int tid = threadIdx.x, wid = tid >> 5, lane = tid & 31;
    const int z = blockIdx.z;
    const int K = DM, N = DM;

    const __half* Bh = (z == 0) ? wq : (z == 1) ? wk : wv;
    const float* bias = (z == 0) ? bq : (z == 1) ? bk : bv;

    const int mBase = blockIdx.y * BM;
    const int nBase = blockIdx.x * BN;
    const __half* base[3] = { xh + (size_t)mBase * K, xl + (size_t)mBase * K,
                              Bh + (size_t)nBase * K };

    float acc[16][4];
    #pragma unroll
    for (int i = 0; i < 16; i++)
        #pragma unroll
        for (int j = 0; j < 4; j++) acc[i][j] = 0.0f;

    if (z == 0) mainloop<true>(sb, base, K, tid, wid, lane, acc);
    else        mainloop<false>(sb, base, K, tid, wid, lane, acc);

    const int m0 = (wid & 3) * 32, n0 = (wid >> 2) * 64;
    const int qrow = lane >> 2, qcol = (lane & 3) * 2;
    #pragma unroll
    for (int t = 0; t < 2; t++)
        #pragma unroll
        for (int u = 0; u < 4; u++)
            #pragma unroll
            for (int j = 0; j < 2; j++) {
                const float* d = acc[t * 8 + u * 2 + j];
                const int m = mBase + m0 + t * 16 + qrow;
                const int n = nBase + n0 + u * 16 + j * 8 + qcol;
                const float b0 = bias[n], b1 = bias[n + 1];
                float v0 = d[0] + b0, v1 = d[1] + b1;
                float v2 = d[2] + b0, v3 = d[3] + b1;
                if (z == 0) {
                    const size_t o0 = (size_t)m * N + n;
                    const size_t o1 = o0 + (size_t)8 * N;
                    __half h0 = __float2half_rn(v0), h1 = __float2half_rn(v1);
                    __half h2 = __float2half_rn(v2), h3 = __float2half_rn(v3);
                    *reinterpret_cast<uint32_t*>(&qh[o0]) = packh(h0, h1);
                    *reinterpret_cast<uint32_t*>(&qh[o1]) = packh(h2, h3);
                    *reinterpret_cast<uint32_t*>(&ql[o0]) =
                        packh(__float2half_rn(v0 - __half2float(h0)),
                              __float2half_rn(v1 - __half2float(h1)));
                    *reinterpret_cast<uint32_t*>(&ql[o1]) =
                        packh(__float2half_rn(v2 - __half2float(h2)),
                              __float2half_rn(v3 - __half2float(h3)));
                } else if (z == 1) {
                    const size_t o0 = (size_t)m * N + n;
                    const size_t o1 = o0 + (size_t)8 * N;
                    *reinterpret_cast<uint32_t*>(&kh[o0]) =
                        packh(__float2half_rn(v0), __float2half_rn(v1));
                    *reinterpret_cast<uint32_t*>(&kh[o1]) =
                        packh(__float2half_rn(v2), __float2half_rn(v3));
                } else {
                    // V^T: per batch [DM][SEQ]; batch = m / SEQ
                    const size_t boff = (size_t)(m / SEQ) * ((size_t)DM * SEQ);
                    const int mr = m % SEQ;
                    vth[boff + (size_t)n * SEQ + mr]           = __float2half_rn(v0);
                    vth[boff + (size_t)(n + 1) * SEQ + mr]     = __float2half_rn(v1);
                    vth[boff + (size_t)n * SEQ + mr + 8]       = __float2half_rn(v2);
                    vth[boff + (size_t)(n + 1) * SEQ + mr + 8] = __float2half_rn(v3);
                }
            }
}

// ---------------- softmax rows + fused fp16 split, SMEM-resident ----------------
__global__ __launch_bounds__(256)
void softmax_split(const float* __restrict__ P, __half* __restrict__ Ph,
                   __half* __restrict__ Pl, int n) {
    const int tid = threadIdx.x;
    const size_t roff = (size_t)blockIdx.x * n;
    const float* row = P + roff;

    __shared__ float srow[SEQ];
    __shared__ float red[8];
    __shared__ float bcast;

    float mx = -1e30f;
    for (int i = tid; i < n; i += 256) {
        float v = row[i];
        srow[i] = v;
        mx = fmaxf(mx, v);
    }
    #pragma unroll
    for (int o = 16; o; o >>= 1) mx = fmaxf(mx, __shfl_xor_sync(0xffffffffu, mx, o));
    if ((tid & 31) == 0) red[tid >> 5] = mx;
    __syncthreads();
    if (tid == 0) {
        float v = red[0];
        #pragma unroll
        for (int w = 1; w < 8; w++) v = fmaxf(v, red[w]);
        bcast = v;
    }
    __syncthreads();
    mx = bcast;
    __syncthreads();

    float s = 0.0f;
    for (int i = tid; i < n; i += 256) {
        float e = __expf(srow[i] - mx);
        srow[i] = e;
        s += e;
    }
    #pragma unroll
    for (int o = 16; o; o >>= 1) s += __shfl_xor_sync(0xffffffffu, s, o);
    if ((tid & 31) == 0) red[tid >> 5] = s;
    __syncthreads();
    if (tid == 0) {
        float v = 0.0f;
        #pragma unroll
        for (int w = 0; w < 8; w++) v += red[w];
        bcast = 1.0f / v;
    }
    __syncthreads();
    const float inv = bcast;

    for (int i = tid; i < n; i += 256) {
        float p = srow[i] * inv;
        __half h = __float2half_rn(p);
        Ph[roff + i] = h;
        Pl[roff + i] = __float2half_rn(p - __half2float(h));
    }
}

// ---------------- launch ----------------
extern "C" void kernel_launch(void* const* d_in, const int* in_sizes, int n_in,
                              void* d_out, int out_size) {
    (void)in_sizes; (void)n_in; (void)out_size;

    const float* x   = (const float*)d_in[0];
    const float* w_q = (const float*)d_in[1];
    const float* b_q = (const float*)d_in[2];
    const float* w_k = (const float*)d_in[3];
    const float* b_k = (const float*)d_in[4];
    const float* w_v = (const float*)d_in[5];
    const float* b_v = (const float*)d_in[6];
    const float* w_o = (const float*)d_in[7];
    const float* b_o = (const float*)d_in[8];
    float* out = (float*)d_out;

    float* Pp;
    __half *xh, *xl, *wq, *wk, *wv, *wo, *qh, *ql, *kh, *vth, *ph, *pl, *oh, *ol;
    cudaGetSymbolAddress((void**)&Pp, g_P);
    cudaGetSymbolAddress((void**)&xh, g_xh);   cudaGetSymbolAddress((void**)&xl, g_xl);
    cudaGetSymbolAddress((void**)&wq, g_wq);   cudaGetSymbolAddress((void**)&wk, g_wk);
    cudaGetSymbolAddress((void**)&wv, g_wv);   cudaGetSymbolAddress((void**)&wo, g_wo);
    cudaGetSymbolAddress((void**)&qh, g_qh);   cudaGetSymbolAddress((void**)&ql, g_ql);
    cudaGetSymbolAddress((void**)&kh, g_kh);   cudaGetSymbolAddress((void**)&vth, g_vth);
    cudaGetSymbolAddress((void**)&ph, g_ph);   cudaGetSymbolAddress((void**)&pl, g_pl);
    cudaGetSymbolAddress((void**)&oh, g_oh);   cudaGetSymbolAddress((void**)&ol, g_ol);

    cudaFuncSetAttribute(gemm_f16x2<0>, cudaFuncAttributeMaxDynamicSharedMemorySize, SMEM_SZ);
    cudaFuncSetAttribute(gemm_f16x2<1>, cudaFuncAttributeMaxDynamicSharedMemorySize, SMEM_SZ);
    cudaFuncSetAttribute(gemm_qkv, cudaFuncAttributeMaxDynamicSharedMemorySize, SMEM_SZ);

    // #1 split x, #2 convert weights
    splitx_kernel<<<1024, 256>>>(x, xh, xl, NX);
    {
        dim3 g(128, 4);
        conv4_kernel<<<g, 256>>>(w_q, w_k, w_v, w_o, wq, wk, wv, wo, NW);
    }

    // #3 fused QKV projection
    {
        dim3 grid(DM / BN, MTOT / BM, 3);
        gemm_qkv<<<grid, NTHREADS, SMEM_SZ>>>(xh, xl, wq, wk, wv, qh, ql, kh, vth,
                                              b_q, b_k, b_v);
    }

    // #4 scores P = Q K^T / sqrt(d)
    {
        dim3 grid(SEQ / BN, SEQ / BM, BATCH);
        gemm_f16x2<0><<<grid, NTHREADS, SMEM_SZ>>>(qh, ql, kh, Pp, nullptr, nullptr, nullptr,
                                                   SEQ, SEQ, DM, 0.03125f,
                                                   (size_t)SEQ * DM, (size_t)SEQ * DM,
                                                   (size_t)SEQ * SEQ);
    }

    // #5 softmax + split
    softmax_split<<<BATCH * SEQ, 256>>>(Pp, ph, pl, SEQ);

    // #6 O = P V  (B = V^T hi, K-major)
    {
        dim3 grid(DM / BN, SEQ / BM, BATCH);
        gemm_f16x2<1><<<grid, NTHREADS, SMEM_SZ>>>(ph, pl, vth, nullptr, oh, ol, nullptr,
                                                   SEQ, DM, SEQ, 1.0f,
                                                   (size_t)SEQ * SEQ, (size_t)DM * SEQ,
                                                   (size_t)SEQ * DM);
    }

    // #7 out = O W_out^T + b_out
    {
        dim3 grid(DM / BN, MTOT / BM, 1);
        gemm_f16x2<0><<<grid, NTHREADS, SMEM_SZ>>>(oh, ol, wo, out, nullptr, nullptr, b_o,
                                                   MTOT, DM, DM, 1.0f, 0, 0, 0);
    }
}

// round 8
// speedup vs baseline: 8.6437x; 1.4995x over previous
#include <cuda_runtime.h>
#include <cuda_fp16.h>
#include <cstdint>

#define BATCH 4
#define SEQ   2048
#define DM    1024
#define MTOT  (BATCH * SEQ)     // 8192

#define BM 128
#define BN 128
#define BK 64                    // fp16 per k-chunk (128 B rows)
#define NTHREADS 256
#define TILE_BYTES 16384         // 128 rows x 128 B
#define STAGE_BYTES (2 * TILE_BYTES)   // A, B tiles
#define NSTAGE 3
#define SMEM_SZ (NSTAGE * STAGE_BYTES) // 98304 -> 2 CTAs/SM

// ---------------- device scratch ----------------
#define NX ((size_t)MTOT * DM)
#define NW ((size_t)DM * DM)
#define NP ((size_t)BATCH * SEQ * SEQ)

__device__ float g_P[NP];
__device__ __half g_x[NX];
__device__ __half g_wq[NW], g_wk[NW], g_wv[NW], g_wo[NW];
__device__ __half g_q[NX], g_k[NX];
__device__ __half g_vt[NX];                  // V^T per batch [DM][SEQ]
__device__ __half g_p[NP];
__device__ __half g_o[NX];

// ---------------- helpers ----------------
static __device__ __forceinline__ uint32_t smem_u32(const void* p) {
    uint32_t a;
    asm("{ .reg .u64 t; cvta.to.shared.u64 t, %1; cvt.u32.u64 %0, t; }" : "=r"(a) : "l"(p));
    return a;
}
static __device__ __forceinline__ uint32_t swz(uint32_t o) { return o ^ ((o >> 3) & 0x70); }

static __device__ __forceinline__ void cpa16(uint32_t s, const void* g) {
    asm volatile("cp.async.cg.shared.global [%0], [%1], 16;" :: "r"(s), "l"(g));
}
static __device__ __forceinline__ void cpa_commit() { asm volatile("cp.async.commit_group;"); }

static __device__ __forceinline__ void ldsm4(uint32_t (&r)[4], uint32_t addr) {
    asm volatile("ldmatrix.sync.aligned.m8n8.x4.shared.b16 {%0,%1,%2,%3}, [%4];"
                 : "=r"(r[0]), "=r"(r[1]), "=r"(r[2]), "=r"(r[3]) : "r"(addr));
}
static __device__ __forceinline__ void mma16816(float (&d)[4], const uint32_t (&a)[4],
                                                uint32_t b0, uint32_t b1) {
    asm volatile("mma.sync.aligned.m16n8k16.row.col.f32.f16.f16.f32 "
                 "{%0,%1,%2,%3}, {%4,%5,%6,%7}, {%8,%9}, {%0,%1,%2,%3};"
                 : "+f"(d[0]), "+f"(d[1]), "+f"(d[2]), "+f"(d[3])
                 : "r"(a[0]), "r"(a[1]), "r"(a[2]), "r"(a[3]), "r"(b0), "r"(b1));
}
static __device__ __forceinline__ uint32_t packh(__half a, __half b) {
    __half2 p = __halves2half2(a, b);
    return *reinterpret_cast<uint32_t*>(&p);
}

// ---------------- fp32 -> fp16 conversion ----------------
__global__ void conv_kernel(const float* __restrict__ src, __half* __restrict__ h, size_t n) {
    size_t i = (size_t)blockIdx.x * blockDim.x + threadIdx.x;
    size_t stride = (size_t)gridDim.x * blockDim.x;
    for (; i < n; i += stride) h[i] = __float2half_rn(src[i]);
}

__global__ void conv4_kernel(const float* __restrict__ s0, const float* __restrict__ s1,
                             const float* __restrict__ s2, const float* __restrict__ s3,
                             __half* __restrict__ h0, __half* __restrict__ h1,
                             __half* __restrict__ h2, __half* __restrict__ h3, size_t n) {
    const float* src = (blockIdx.y == 0) ? s0 : (blockIdx.y == 1) ? s1
                        : (blockIdx.y == 2) ? s2 : s3;
    __half* h = (blockIdx.y == 0) ? h0 : (blockIdx.y == 1) ? h1
                 : (blockIdx.y == 2) ? h2 : h3;
    size_t i = (size_t)blockIdx.x * blockDim.x + threadIdx.x;
    size_t stride = (size_t)gridDim.x * blockDim.x;
    for (; i < n; i += stride) h[i] = __float2half_rn(src[i]);
}

// ---------------- stage loader: A, B tiles ----------------
static __device__ __forceinline__ void load_stage(uint32_t sbase,
                                                  const __half* const* base,
                                                  int K, int k0, int tid) {
    const int tr = tid >> 3;        // 0..31
    const int tc = tid & 7;         // 16B column
    #pragma unroll
    for (int s = 0; s < 2; s++) {
        const __half* g = base[s] + (size_t)tr * K + k0 + tc * 8;
        uint32_t so = sbase + s * TILE_BYTES;
        #pragma unroll
        for (int r = 0; r < 4; r++) {
            uint32_t off = (uint32_t)(tr + r * 32) * 128 + tc * 16;
            cpa16(so + swz(off), g + (size_t)(r * 32) * K);
        }
    }
}

// ---------------- shared mainloop: acc = A * B^T over K ----------------
static __device__ __forceinline__ void mainloop(uint32_t sb, const __half* const* base,
                                                int K, int tid, int wid, int lane,
                                                float (*acc)[4]) {
    const int m0 = (wid & 3) * 32;
    const int n0 = (wid >> 2) * 64;
    const uint32_t a_row  = lane & 15;
    const uint32_t a_half = (lane >> 4) * 16;
    const uint32_t b_row  = (lane & 7) + ((lane >> 4) & 1) * 8;
    const uint32_t b_half = ((lane >> 3) & 1) * 16;

    const int NC = K / BK;
    #pragma unroll
    for (int s = 0; s < NSTAGE - 1; s++) {
        if (s < NC) load_stage(sb + s * STAGE_BYTES, base, K, s * BK, tid);
        cpa_commit();
    }

    for (int c = 0; c < NC; c++) {
        asm volatile("cp.async.wait_group 1;" ::: "memory");
        __syncthreads();

        if (c + NSTAGE - 1 < NC)
            load_stage(sb + ((c + NSTAGE - 1) % NSTAGE) * STAGE_BYTES, base, K,
                       (c + NSTAGE - 1) * BK, tid);
        cpa_commit();   // empty group in tail keeps wait_group accounting exact

        const uint32_t st = sb + (c % NSTAGE) * STAGE_BYTES;
        const uint32_t tA = st, tB = st + TILE_BYTES;

        #pragma unroll
        for (int kk = 0; kk < 4; kk++) {
            const uint32_t kb = kk * 32;
            uint32_t ah[2][4], bh[4][4];
            #pragma unroll
            for (int t = 0; t < 2; t++) {
                uint32_t off = swz((uint32_t)(m0 + t * 16 + a_row) * 128 + kb + a_half);
                ldsm4(ah[t], tA + off);
            }
            #pragma unroll
            for (int u = 0; u < 4; u++) {
                uint32_t off = swz((uint32_t)(n0 + u * 16 + b_row) * 128 + kb + b_half);
                ldsm4(bh[u], tB + off);
            }
            #pragma unroll
            for (int t = 0; t < 2; t++)
                #pragma unroll
                for (int u = 0; u < 4; u++) {
                    #pragma unroll
                    for (int j = 0; j < 2; j++) {
                        mma16816(acc[t * 8 + u * 2 + j], ah[t],
                                 bh[u][j * 2], bh[u][j * 2 + 1]);
                    }
                }
        }
    }
}

// ---------------- generic GEMM: C = scale*A*B^T + bias ----------------
// OUTMODE 0: fp32 C      1: fp16 C
template <int OUTMODE>
__global__ __launch_bounds__(NTHREADS, 2)
void gemm_f16(const __half* __restrict__ A, const __half* __restrict__ B,
              float* __restrict__ Cf, __half* __restrict__ Ch,
              const float* __restrict__ bias,
              int M, int N, int K, float scale,
              size_t sA, size_t sB, size_t sC) {
    extern __shared__ __align__(1024) char smem[];
    const uint32_t sb = smem_u32(smem);
    const int tid = threadIdx.x, wid = tid >> 5, lane = tid & 31;

    A += (size_t)blockIdx.z * sA;
    B += (size_t)blockIdx.z * sB;

    const int mBase = blockIdx.y * BM;
    const int nBase = blockIdx.x * BN;
    const __half* base[2] = { A + (size_t)mBase * K, B + (size_t)nBase * K };

    float acc[16][4];
    #pragma unroll
    for (int i = 0; i < 16; i++)
        #pragma unroll
        for (int j = 0; j < 4; j++) acc[i][j] = 0.0f;

    mainloop(sb, base, K, tid, wid, lane, acc);

    const int m0 = (wid & 3) * 32, n0 = (wid >> 2) * 64;
    const int qrow = lane >> 2, qcol = (lane & 3) * 2;
    #pragma unroll
    for (int t = 0; t < 2; t++)
        #pragma unroll
        for (int u = 0; u < 4; u++)
            #pragma unroll
            for (int j = 0; j < 2; j++) {
                const float* d = acc[t * 8 + u * 2 + j];
                const int m = mBase + m0 + t * 16 + qrow;
                const int n = nBase + n0 + u * 16 + j * 8 + qcol;
                float b0 = 0.f, b1 = 0.f;
                if (bias) { b0 = bias[n]; b1 = bias[n + 1]; }
                float v0 = d[0] * scale + b0, v1 = d[1] * scale + b1;
                float v2 = d[2] * scale + b0, v3 = d[3] * scale + b1;
                const size_t o0 = (size_t)blockIdx.z * sC + (size_t)m * N + n;
                const size_t o1 = o0 + (size_t)8 * N;
                if (OUTMODE == 0) {
                    *reinterpret_cast<float2*>(&Cf[o0]) = make_float2(v0, v1);
                    *reinterpret_cast<float2*>(&Cf[o1]) = make_float2(v2, v3);
                } else {
                    *reinterpret_cast<uint32_t*>(&Ch[o0]) =
                        packh(__float2half_rn(v0), __float2half_rn(v1));
                    *reinterpret_cast<uint32_t*>(&Ch[o1]) =
                        packh(__float2half_rn(v2), __float2half_rn(v3));
                }
            }
}

// ---------------- fused QKV projection: z=0 Q  z=1 K  z=2 V^T ----------------
__global__ __launch_bounds__(NTHREADS, 2)
void gemm_qkv(const __half* __restrict__ x,
              const __half* __restrict__ wq, const __half* __restrict__ wk,
              const __half* __restrict__ wv,
              __half* __restrict__ q, __half* __restrict__ k, __half* __restrict__ vt,
              const float* __restrict__ bq, const float* __restrict__ bk,
              const float* __restrict__ bv) {
    extern __shared__ __align__(1024) char smem[];
    const uint32_t sb = smem_u32(smem);
    const int tid = threadIdx.x, wid = tid >> 5, lane = tid & 31;
    const int z = blockIdx.z;
    const int K = DM, N = DM;

    const __half* B = (z == 0) ? wq : (z == 1) ? wk : wv;
    const float* bias = (z == 0) ? bq : (z == 1) ? bk : bv;

    const int mBase = blockIdx.y * BM;
    const int nBase = blockIdx.x * BN;
    const __half* base[2] = { x + (size_t)mBase * K, B + (size_t)nBase * K };

    float acc[16][4];
    #pragma unroll
    for (int i = 0; i < 16; i++)
        #pragma unroll
        for (int j = 0; j < 4; j++) acc[i][j] = 0.0f;

    mainloop(sb, base, K, tid, wid, lane, acc);

    const int m0 = (wid & 3) * 32, n0 = (wid >> 2) * 64;
    const int qrow = lane >> 2, qcol = (lane & 3) * 2;
    #pragma unroll
    for (int t = 0; t < 2; t++)
        #pragma unroll
        for (int u = 0; u < 4; u++)
            #pragma unroll
            for (int j = 0; j < 2; j++) {
                const float* d = acc[t * 8 + u * 2 + j];
                const int m = mBase + m0 + t * 16 + qrow;
                const int n = nBase + n0 + u * 16 + j * 8 + qcol;
                const float b0 = bias[n], b1 = bias[n + 1];
                float v0 = d[0] + b0, v1 = d[1] + b1;
                float v2 = d[2] + b0, v3 = d[3] + b1;
                if (z == 2) {
                    // V^T: per batch [DM][SEQ]; batch = m / SEQ
                    const size_t boff = (size_t)(m / SEQ) * ((size_t)DM * SEQ);
                    const int mr = m % SEQ;
                    vt[boff + (size_t)n * SEQ + mr]           = __float2half_rn(v0);
                    vt[boff + (size_t)(n + 1) * SEQ + mr]     = __float2half_rn(v1);
                    vt[boff + (size_t)n * SEQ + mr + 8]       = __float2half_rn(v2);
                    vt[boff + (size_t)(n + 1) * SEQ + mr + 8] = __float2half_rn(v3);
                } else {
                    __half* dst = (z == 0) ? q : k;
                    const size_t o0 = (size_t)m * N + n;
                    const size_t o1 = o0 + (size_t)8 * N;
                    *reinterpret_cast<uint32_t*>(&dst[o0]) =
                        packh(__float2half_rn(v0), __float2half_rn(v1));
                    *reinterpret_cast<uint32_t*>(&dst[o1]) =
                        packh(__float2half_rn(v2), __float2half_rn(v3));
                }
            }
}

// ---------------- softmax rows -> fp16 P, SMEM-resident ----------------
__global__ __launch_bounds__(256)
void softmax_f16(const float* __restrict__ P, __half* __restrict__ Ph, int n) {
    const int tid = threadIdx.x;
    const size_t roff = (size_t)blockIdx.x * n;
    const float* row = P + roff;

    __shared__ float srow[SEQ];
    __shared__ float red[8];
    __shared__ float bcast;

    float mx = -1e30f;
    for (int i = tid; i < n; i += 256) {
        float v = row[i];
        srow[i] = v;
        mx = fmaxf(mx, v);
    }
    #pragma unroll
    for (int o = 16; o; o >>= 1) mx = fmaxf(mx, __shfl_xor_sync(0xffffffffu, mx, o));
    if ((tid & 31) == 0) red[tid >> 5] = mx;
    __syncthreads();
    if (tid == 0) {
        float v = red[0];
        #pragma unroll
        for (int w = 1; w < 8; w++) v = fmaxf(v, red[w]);
        bcast = v;
    }
    __syncthreads();
    mx = bcast;
    __syncthreads();

    float s = 0.0f;
    for (int i = tid; i < n; i += 256) {
        float e = __expf(srow[i] - mx);
        srow[i] = e;
        s += e;
    }
    #pragma unroll
    for (int o = 16; o; o >>= 1) s += __shfl_xor_sync(0xffffffffu, s, o);
    if ((tid & 31) == 0) red[tid >> 5] = s;
    __syncthreads();
    if (tid == 0) {
        float v = 0.0f;
        #pragma unroll
        for (int w = 0; w < 8; w++) v += red[w];
        bcast = 1.0f / v;
    }
    __syncthreads();
    const float inv = bcast;

    for (int i = tid; i < n; i += 256)
        Ph[roff + i] = __float2half_rn(srow[i] * inv);
}

// ---------------- launch ----------------
extern "C" void kernel_launch(void* const* d_in, const int* in_sizes, int n_in,
                              void* d_out, int out_size) {
    (void)in_sizes; (void)n_in; (void)out_size;

    const float* x_f = (const float*)d_in[0];
    const float* w_q = (const float*)d_in[1];
    const float* b_q = (const float*)d_in[2];
    const float* w_k = (const float*)d_in[3];
    const float* b_k = (const float*)d_in[4];
    const float* w_v = (const float*)d_in[5];
    const float* b_v = (const float*)d_in[6];
    const float* w_o = (const float*)d_in[7];
    const float* b_o = (const float*)d_in[8];
    float* out = (float*)d_out;

    float* Pp;
    __half *x, *wq, *wk, *wv, *wo, *q, *k, *vt, *p, *o;
    cudaGetSymbolAddress((void**)&Pp, g_P);
    cudaGetSymbolAddress((void**)&x, g_x);
    cudaGetSymbolAddress((void**)&wq, g_wq);   cudaGetSymbolAddress((void**)&wk, g_wk);
    cudaGetSymbolAddress((void**)&wv, g_wv);   cudaGetSymbolAddress((void**)&wo, g_wo);
    cudaGetSymbolAddress((void**)&q, g_q);     cudaGetSymbolAddress((void**)&k, g_k);
    cudaGetSymbolAddress((void**)&vt, g_vt);
    cudaGetSymbolAddress((void**)&p, g_p);     cudaGetSymbolAddress((void**)&o, g_o);

    cudaFuncSetAttribute(gemm_f16<0>, cudaFuncAttributeMaxDynamicSharedMemorySize, SMEM_SZ);
    cudaFuncSetAttribute(gemm_f16<1>, cudaFuncAttributeMaxDynamicSharedMemorySize, SMEM_SZ);
    cudaFuncSetAttribute(gemm_qkv, cudaFuncAttributeMaxDynamicSharedMemorySize, SMEM_SZ);

    // #1 convert x, #2 convert weights
    conv_kernel<<<1024, 256>>>(x_f, x, NX);
    {
        dim3 g(128, 4);
        conv4_kernel<<<g, 256>>>(w_q, w_k, w_v, w_o, wq, wk, wv, wo, NW);
    }

    // #3 fused QKV projection
    {
        dim3 grid(DM / BN, MTOT / BM, 3);
        gemm_qkv<<<grid, NTHREADS, SMEM_SZ>>>(x, wq, wk, wv, q, k, vt, b_q, b_k, b_v);
    }

    // #4 scores P = Q K^T / sqrt(d)
    {
        dim3 grid(SEQ / BN, SEQ / BM, BATCH);
        gemm_f16<0><<<grid, NTHREADS, SMEM_SZ>>>(q, k, Pp, nullptr, nullptr,
                                                 SEQ, SEQ, DM, 0.03125f,
                                                 (size_t)SEQ * DM, (size_t)SEQ * DM,
                                                 (size_t)SEQ * SEQ);
    }

    // #5 softmax -> fp16 P
    softmax_f16<<<BATCH * SEQ, 256>>>(Pp, p, SEQ);

    // #6 O = P V  (B = V^T, K-major)
    {
        dim3 grid(DM / BN, SEQ / BM, BATCH);
        gemm_f16<1><<<grid, NTHREADS, SMEM_SZ>>>(p, vt, nullptr, o, nullptr,
                                                 SEQ, DM, SEQ, 1.0f,
                                                 (size_t)SEQ * SEQ, (size_t)DM * SEQ,
                                                 (size_t)SEQ * DM);
    }

    // #7 out = O W_out^T + b_out
    {
        dim3 grid(DM / BN, MTOT / BM, 1);
        gemm_f16<0><<<grid, NTHREADS, SMEM_SZ>>>(o, wo, out, nullptr, b_o,
                                                 MTOT, DM, DM, 1.0f, 0, 0, 0);
    }
}

// round 9
// speedup vs baseline: 8.9188x; 1.0318x over previous
#include <cuda_runtime.h>
#include <cuda_fp16.h>
#include <cstdint>

#define BATCH 4
#define SEQ   2048
#define DM    1024
#define MTOT  (BATCH * SEQ)     // 8192

#define BM 128
#define BN 128
#define BK 64                    // fp16 per k-chunk (128 B rows)
#define NTHREADS 128             // 4 warps, 2M x 2N, 64x64 warp tile
#define TILE_BYTES 16384         // 128 rows x 128 B
#define STAGE_BYTES (2 * TILE_BYTES)   // A, B tiles
#define NSTAGE 3
#define SMEM_SZ (NSTAGE * STAGE_BYTES) // 98304 -> 2 CTAs/SM

// ---------------- device scratch ----------------
#define NX ((size_t)MTOT * DM)
#define NW ((size_t)DM * DM)
#define NP ((size_t)BATCH * SEQ * SEQ)

__device__ float g_P[NP];
__device__ __half g_x[NX];
__device__ __half g_wq[NW], g_wk[NW], g_wv[NW], g_wo[NW];
__device__ __half g_q[NX], g_k[NX];
__device__ __half g_vt[NX];                  // V^T per batch [DM][SEQ]
__device__ __half g_p[NP];
__device__ __half g_o[NX];

// ---------------- helpers ----------------
static __device__ __forceinline__ uint32_t smem_u32(const void* p) {
    uint32_t a;
    asm("{ .reg .u64 t; cvta.to.shared.u64 t, %1; cvt.u32.u64 %0, t; }" : "=r"(a) : "l"(p));
    return a;
}
static __device__ __forceinline__ uint32_t swz(uint32_t o) { return o ^ ((o >> 3) & 0x70); }

static __device__ __forceinline__ void cpa16(uint32_t s, const void* g) {
    asm volatile("cp.async.cg.shared.global [%0], [%1], 16;" :: "r"(s), "l"(g));
}
static __device__ __forceinline__ void cpa_commit() { asm volatile("cp.async.commit_group;"); }

static __device__ __forceinline__ void ldsm4(uint32_t (&r)[4], uint32_t addr) {
    asm volatile("ldmatrix.sync.aligned.m8n8.x4.shared.b16 {%0,%1,%2,%3}, [%4];"
                 : "=r"(r[0]), "=r"(r[1]), "=r"(r[2]), "=r"(r[3]) : "r"(addr));
}
static __device__ __forceinline__ void mma16816(float (&d)[4], const uint32_t (&a)[4],
                                                uint32_t b0, uint32_t b1) {
    asm volatile("mma.sync.aligned.m16n8k16.row.col.f32.f16.f16.f32 "
                 "{%0,%1,%2,%3}, {%4,%5,%6,%7}, {%8,%9}, {%0,%1,%2,%3};"
                 : "+f"(d[0]), "+f"(d[1]), "+f"(d[2]), "+f"(d[3])
                 : "r"(a[0]), "r"(a[1]), "r"(a[2]), "r"(a[3]), "r"(b0), "r"(b1));
}
static __device__ __forceinline__ uint32_t packh(__half a, __half b) {
    __half2 p = __halves2half2(a, b);
    return *reinterpret_cast<uint32_t*>(&p);
}

// ---------------- fp32 -> fp16 conversion ----------------
__global__ void conv_kernel(const float* __restrict__ src, __half* __restrict__ h, size_t n) {
    size_t i = (size_t)blockIdx.x * blockDim.x + threadIdx.x;
    size_t stride = (size_t)gridDim.x * blockDim.x;
    for (; i < n; i += stride) h[i] = __float2half_rn(src[i]);
}

__global__ void conv4_kernel(const float* __restrict__ s0, const float* __restrict__ s1,
                             const float* __restrict__ s2, const float* __restrict__ s3,
                             __half* __restrict__ h0, __half* __restrict__ h1,
                             __half* __restrict__ h2, __half* __restrict__ h3, size_t n) {
    const float* src = (blockIdx.y == 0) ? s0 : (blockIdx.y == 1) ? s1
                        : (blockIdx.y == 2) ? s2 : s3;
    __half* h = (blockIdx.y == 0) ? h0 : (blockIdx.y == 1) ? h1
                 : (blockIdx.y == 2) ? h2 : h3;
    size_t i = (size_t)blockIdx.x * blockDim.x + threadIdx.x;
    size_t stride = (size_t)gridDim.x * blockDim.x;
    for (; i < n; i += stride) h[i] = __float2half_rn(src[i]);
}

// ---------------- stage loader: A, B tiles, 128 threads ----------------
static __device__ __forceinline__ void load_stage(uint32_t sbase,
                                                  const __half* const* base,
                                                  int K, int k0, int tid) {
    const int tr = tid >> 3;        // 0..15 starting row
    const int tc = tid & 7;         // 16B column
    #pragma unroll
    for (int s = 0; s < 2; s++) {
        const __half* g = base[s] + (size_t)tr * K + k0 + tc * 8;
        uint32_t so = sbase + s * TILE_BYTES;
        #pragma unroll
        for (int r = 0; r < 8; r++) {
            uint32_t off = (uint32_t)(tr + r * 16) * 128 + tc * 16;
            cpa16(so + swz(off), g + (size_t)(r * 16) * K);
        }
    }
}

// ---------------- shared mainloop: acc = A * B^T over K ----------------
// 4 warps, warp tile 64x64: acc[32][4] = acc[t*8 + u*2 + j]
static __device__ __forceinline__ void mainloop(uint32_t sb, const __half* const* base,
                                                int K, int tid, int wid, int lane,
                                                float (*acc)[4]) {
    const int m0 = (wid & 1) * 64;
    const int n0 = (wid >> 1) * 64;
    const uint32_t a_row  = lane & 15;
    const uint32_t a_half = (lane >> 4) * 16;
    const uint32_t b_row  = (lane & 7) + ((lane >> 4) & 1) * 8;
    const uint32_t b_half = ((lane >> 3) & 1) * 16;

    const int NC = K / BK;
    #pragma unroll
    for (int s = 0; s < NSTAGE - 1; s++) {
        if (s < NC) load_stage(sb + s * STAGE_BYTES, base, K, s * BK, tid);
        cpa_commit();
    }

    for (int c = 0; c < NC; c++) {
        asm volatile("cp.async.wait_group 1;" ::: "memory");
        __syncthreads();

        if (c + NSTAGE - 1 < NC)
            load_stage(sb + ((c + NSTAGE - 1) % NSTAGE) * STAGE_BYTES, base, K,
                       (c + NSTAGE - 1) * BK, tid);
        cpa_commit();   // empty group in tail keeps wait_group accounting exact

        const uint32_t st = sb + (c % NSTAGE) * STAGE_BYTES;
        const uint32_t tA = st, tB = st + TILE_BYTES;

        #pragma unroll
        for (int kk = 0; kk < 4; kk++) {
            const uint32_t kb = kk * 32;
            uint32_t ah[4][4], bh[4][4];
            #pragma unroll
            for (int t = 0; t < 4; t++) {
                uint32_t off = swz((uint32_t)(m0 + t * 16 + a_row) * 128 + kb + a_half);
                ldsm4(ah[t], tA + off);
            }
            #pragma unroll
            for (int u = 0; u < 4; u++) {
                uint32_t off = swz((uint32_t)(n0 + u * 16 + b_row) * 128 + kb + b_half);
                ldsm4(bh[u], tB + off);
            }
            #pragma unroll
            for (int t = 0; t < 4; t++)
                #pragma unroll
                for (int u = 0; u < 4; u++) {
                    #pragma unroll
                    for (int j = 0; j < 2; j++) {
                        mma16816(acc[t * 8 + u * 2 + j], ah[t],
                                 bh[u][j * 2], bh[u][j * 2 + 1]);
                    }
                }
        }
    }
}

// ---------------- generic GEMM: C = scale*A*B^T + bias ----------------
// OUTMODE 0: fp32 C      1: fp16 C
template <int OUTMODE>
__global__ __launch_bounds__(NTHREADS, 2)
void gemm_f16(const __half* __restrict__ A, const __half* __restrict__ B,
              float* __restrict__ Cf, __half* __restrict__ Ch,
              const float* __restrict__ bias,
              int M, int N, int K, float scale,
              size_t sA, size_t sB, size_t sC) {
    extern __shared__ __align__(1024) char smem[];
    const uint32_t sb = smem_u32(smem);
    const int tid = threadIdx.x, wid = tid >> 5, lane = tid & 31;

    A += (size_t)blockIdx.z * sA;
    B += (size_t)blockIdx.z * sB;

    const int mBase = blockIdx.y * BM;
    const int nBase = blockIdx.x * BN;
    const __half* base[2] = { A + (size_t)mBase * K, B + (size_t)nBase * K };

    float acc[32][4];
    #pragma unroll
    for (int i = 0; i < 32; i++)
        #pragma unroll
        for (int j = 0; j < 4; j++) acc[i][j] = 0.0f;

    mainloop(sb, base, K, tid, wid, lane, acc);

    const int m0 = (wid & 1) * 64, n0 = (wid >> 1) * 64;
    const int qrow = lane >> 2, qcol = (lane & 3) * 2;
    #pragma unroll
    for (int t = 0; t < 4; t++)
        #pragma unroll
        for (int u = 0; u < 4; u++)
            #pragma unroll
            for (int j = 0; j < 2; j++) {
                const float* d = acc[t * 8 + u * 2 + j];
                const int m = mBase + m0 + t * 16 + qrow;
                const int n = nBase + n0 + u * 16 + j * 8 + qcol;
                float b0 = 0.f, b1 = 0.f;
                if (bias) { b0 = bias[n]; b1 = bias[n + 1]; }
                float v0 = d[0] * scale + b0, v1 = d[1] * scale + b1;
                float v2 = d[2] * scale + b0, v3 = d[3] * scale + b1;
                const size_t o0 = (size_t)blockIdx.z * sC + (size_t)m * N + n;
                const size_t o1 = o0 + (size_t)8 * N;
                if (OUTMODE == 0) {
                    *reinterpret_cast<float2*>(&Cf[o0]) = make_float2(v0, v1);
                    *reinterpret_cast<float2*>(&Cf[o1]) = make_float2(v2, v3);
                } else {
                    *reinterpret_cast<uint32_t*>(&Ch[o0]) =
                        packh(__float2half_rn(v0), __float2half_rn(v1));
                    *reinterpret_cast<uint32_t*>(&Ch[o1]) =
                        packh(__float2half_rn(v2), __float2half_rn(v3));
                }
            }
}

// ---------------- fused QKV projection: z=0 Q  z=1 K  z=2 V^T ----------------
__global__ __launch_bounds__(NTHREADS, 2)
void gemm_qkv(const __half* __restrict__ x,
              const __half* __restrict__ wq, const __half* __restrict__ wk,
              const __half* __restrict__ wv,
              __half* __restrict__ q, __half* __restrict__ k, __half* __restrict__ vt,
              const float* __restrict__ bq, const float* __restrict__ bk,
              const float* __restrict__ bv) {
    extern __shared__ __align__(1024) char smem[];
    const uint32_t sb = smem_u32(smem);
    const int tid = threadIdx.x, wid = tid >> 5, lane = tid & 31;
    const int z = blockIdx.z;
    const int K = DM, N = DM;

    const __half* B = (z == 0) ? wq : (z == 1) ? wk : wv;
    const float* bias = (z == 0) ? bq : (z == 1) ? bk : bv;

    const int mBase = blockIdx.y * BM;
    const int nBase = blockIdx.x * BN;
    const __half* base[2] = { x + (size_t)mBase * K, B + (size_t)nBase * K };

    float acc[32][4];
    #pragma unroll
    for (int i = 0; i < 32; i++)
        #pragma unroll
        for (int j = 0; j < 4; j++) acc[i][j] = 0.0f;

    mainloop(sb, base, K, tid, wid, lane, acc);

    const int m0 = (wid & 1) * 64, n0 = (wid >> 1) * 64;
    const int qrow = lane >> 2, qcol = (lane & 3) * 2;
    #pragma unroll
    for (int t = 0; t < 4; t++)
        #pragma unroll
        for (int u = 0; u < 4; u++)
            #pragma unroll
            for (int j = 0; j < 2; j++) {
                const float* d = acc[t * 8 + u * 2 + j];
                const int m = mBase + m0 + t * 16 + qrow;
                const int n = nBase + n0 + u * 16 + j * 8 + qcol;
                const float b0 = bias[n], b1 = bias[n + 1];
                float v0 = d[0] + b0, v1 = d[1] + b1;
                float v2 = d[2] + b0, v3 = d[3] + b1;
                if (z == 2) {
                    // V^T: per batch [DM][SEQ]; batch = m / SEQ
                    const size_t boff = (size_t)(m / SEQ) * ((size_t)DM * SEQ);
                    const int mr = m % SEQ;
                    vt[boff + (size_t)n * SEQ + mr]           = __float2half_rn(v0);
                    vt[boff + (size_t)(n + 1) * SEQ + mr]     = __float2half_rn(v1);
                    vt[boff + (size_t)n * SEQ + mr + 8]       = __float2half_rn(v2);
                    vt[boff + (size_t)(n + 1) * SEQ + mr + 8] = __float2half_rn(v3);
                } else {
                    __half* dst = (z == 0) ? q : k;
                    const size_t o0 = (size_t)m * N + n;
                    const size_t o1 = o0 + (size_t)8 * N;
                    *reinterpret_cast<uint32_t*>(&dst[o0]) =
                        packh(__float2half_rn(v0), __float2half_rn(v1));
                    *reinterpret_cast<uint32_t*>(&dst[o1]) =
                        packh(__float2half_rn(v2), __float2half_rn(v3));
                }
            }
}

// ---------------- softmax rows -> fp16 P, SMEM-resident ----------------
__global__ __launch_bounds__(256)
void softmax_f16(const float* __restrict__ P, __half* __restrict__ Ph, int n) {
    const int tid = threadIdx.x;
    const size_t roff = (size_t)blockIdx.x * n;
    const float* row = P + roff;

    __shared__ float srow[SEQ];
    __shared__ float red[8];
    __shared__ float bcast;

    float mx = -1e30f;
    for (int i = tid; i < n; i += 256) {
        float v = row[i];
        srow[i] = v;
        mx = fmaxf(mx, v);
    }
    #pragma unroll
    for (int o = 16; o; o >>= 1) mx = fmaxf(mx, __shfl_xor_sync(0xffffffffu, mx, o));
    if ((tid & 31) == 0) red[tid >> 5] = mx;
    __syncthreads();
    if (tid == 0) {
        float v = red[0];
        #pragma unroll
        for (int w = 1; w < 8; w++) v = fmaxf(v, red[w]);
        bcast = v;
    }
    __syncthreads();
    mx = bcast;
    __syncthreads();

    float s = 0.0f;
    for (int i = tid; i < n; i += 256) {
        float e = __expf(srow[i] - mx);
        srow[i] = e;
        s += e;
    }
    #pragma unroll
    for (int o = 16; o; o >>= 1) s += __shfl_xor_sync(0xffffffffu, s, o);
    if ((tid & 31) == 0) red[tid >> 5] = s;
    __syncthreads();
    if (tid == 0) {
        float v = 0.0f;
        #pragma unroll
        for (int w = 0; w < 8; w++) v += red[w];
        bcast = 1.0f / v;
    }
    __syncthreads();
    const float inv = bcast;

    for (int i = tid; i < n; i += 256)
        Ph[roff + i] = __float2half_rn(srow[i] * inv);
}

// ---------------- launch ----------------
extern "C" void kernel_launch(void* const* d_in, const int* in_sizes, int n_in,
                              void* d_out, int out_size) {
    (void)in_sizes; (void)n_in; (void)out_size;

    const float* x_f = (const float*)d_in[0];
    const float* w_q = (const float*)d_in[1];
    const float* b_q = (const float*)d_in[2];
    const float* w_k = (const float*)d_in[3];
    const float* b_k = (const float*)d_in[4];
    const float* w_v = (const float*)d_in[5];
    const float* b_v = (const float*)d_in[6];
    const float* w_o = (const float*)d_in[7];
    const float* b_o = (const float*)d_in[8];
    float* out = (float*)d_out;

    float* Pp;
    __half *x, *wq, *wk, *wv, *wo, *q, *k, *vt, *p, *o;
    cudaGetSymbolAddress((void**)&Pp, g_P);
    cudaGetSymbolAddress((void**)&x, g_x);
    cudaGetSymbolAddress((void**)&wq, g_wq);   cudaGetSymbolAddress((void**)&wk, g_wk);
    cudaGetSymbolAddress((void**)&wv, g_wv);   cudaGetSymbolAddress((void**)&wo, g_wo);
    cudaGetSymbolAddress((void**)&q, g_q);     cudaGetSymbolAddress((void**)&k, g_k);
    cudaGetSymbolAddress((void**)&vt, g_vt);
    cudaGetSymbolAddress((void**)&p, g_p);     cudaGetSymbolAddress((void**)&o, g_o);

    cudaFuncSetAttribute(gemm_f16<0>, cudaFuncAttributeMaxDynamicSharedMemorySize, SMEM_SZ);
    cudaFuncSetAttribute(gemm_f16<1>, cudaFuncAttributeMaxDynamicSharedMemorySize, SMEM_SZ);
    cudaFuncSetAttribute(gemm_qkv, cudaFuncAttributeMaxDynamicSharedMemorySize, SMEM_SZ);

    // #1 convert x, #2 convert weights
    conv_kernel<<<1024, 256>>>(x_f, x, NX);
    {
        dim3 g(128, 4);
        conv4_kernel<<<g, 256>>>(w_q, w_k, w_v, w_o, wq, wk, wv, wo, NW);
    }

    // #3 fused QKV projection
    {
        dim3 grid(DM / BN, MTOT / BM, 3);
        gemm_qkv<<<grid, NTHREADS, SMEM_SZ>>>(x, wq, wk, wv, q, k, vt, b_q, b_k, b_v);
    }

    // #4 scores P = Q K^T / sqrt(d)
    {
        dim3 grid(SEQ / BN, SEQ / BM, BATCH);
        gemm_f16<0><<<grid, NTHREADS, SMEM_SZ>>>(q, k, Pp, nullptr, nullptr,
                                                 SEQ, SEQ, DM, 0.03125f,
                                                 (size_t)SEQ * DM, (size_t)SEQ * DM,
                                                 (size_t)SEQ * SEQ);
    }

    // #5 softmax -> fp16 P
    softmax_f16<<<BATCH * SEQ, 256>>>(Pp, p, SEQ);

    // #6 O = P V  (B = V^T, K-major)
    {
        dim3 grid(DM / BN, SEQ / BM, BATCH);
        gemm_f16<1><<<grid, NTHREADS, SMEM_SZ>>>(p, vt, nullptr, o, nullptr,
                                                 SEQ, DM, SEQ, 1.0f,
                                                 (size_t)SEQ * SEQ, (size_t)DM * SEQ,
                                                 (size_t)SEQ * DM);
    }

    // #7 out = O W_out^T + b_out
    {
        dim3 grid(DM / BN, MTOT / BM, 1);
        gemm_f16<0><<<grid, NTHREADS, SMEM_SZ>>>(o, wo, out, nullptr, b_o,
                                                 MTOT, DM, DM, 1.0f, 0, 0, 0);
    }
}

// round 10
// speedup vs baseline: 9.6049x; 1.0769x over previous
#include <cuda_runtime.h>
#include <cuda_fp16.h>
#include <cstdint>

#define BATCH 4
#define SEQ   2048
#define DM    1024
#define MTOT  (BATCH * SEQ)     // 8192

#define BM 128
#define BN 128
#define BK 64                    // fp16 per k-chunk (128 B rows)
#define NTHREADS 128             // 4 warps, 2M x 2N, 64x64 warp tile
#define TILE_BYTES 16384         // 128 rows x 128 B
#define STAGE_BYTES (2 * TILE_BYTES)   // A, B tiles
#define NSTAGE 3
#define SMEM_SZ (NSTAGE * STAGE_BYTES) // 98304 -> 2 CTAs/SM

// ---------------- device scratch ----------------
#define NX ((size_t)MTOT * DM)
#define NW ((size_t)DM * DM)
#define NP ((size_t)BATCH * SEQ * SEQ)

__device__ __half g_x[NX];
__device__ __half g_wq[NW], g_wk[NW], g_wv[NW], g_wo[NW];
__device__ __half g_q[NX], g_k[NX];
__device__ __half g_vt[NX];                  // V^T per batch [DM][SEQ]
__device__ __half g_p[NP];                   // scores -> (in-place softmax) -> probs
__device__ __half g_o[NX];

// ---------------- helpers ----------------
static __device__ __forceinline__ uint32_t smem_u32(const void* p) {
    uint32_t a;
    asm("{ .reg .u64 t; cvta.to.shared.u64 t, %1; cvt.u32.u64 %0, t; }" : "=r"(a) : "l"(p));
    return a;
}
static __device__ __forceinline__ uint32_t swz(uint32_t o) { return o ^ ((o >> 3) & 0x70); }

static __device__ __forceinline__ void cpa16(uint32_t s, const void* g) {
    asm volatile("cp.async.cg.shared.global [%0], [%1], 16;" :: "r"(s), "l"(g));
}
static __device__ __forceinline__ void cpa_commit() { asm volatile("cp.async.commit_group;"); }

static __device__ __forceinline__ void ldsm4(uint32_t (&r)[4], uint32_t addr) {
    asm volatile("ldmatrix.sync.aligned.m8n8.x4.shared.b16 {%0,%1,%2,%3}, [%4];"
                 : "=r"(r[0]), "=r"(r[1]), "=r"(r[2]), "=r"(r[3]) : "r"(addr));
}
static __device__ __forceinline__ void mma16816(float (&d)[4], const uint32_t (&a)[4],
                                                uint32_t b0, uint32_t b1) {
    asm volatile("mma.sync.aligned.m16n8k16.row.col.f32.f16.f16.f32 "
                 "{%0,%1,%2,%3}, {%4,%5,%6,%7}, {%8,%9}, {%0,%1,%2,%3};"
                 : "+f"(d[0]), "+f"(d[1]), "+f"(d[2]), "+f"(d[3])
                 : "r"(a[0]), "r"(a[1]), "r"(a[2]), "r"(a[3]), "r"(b0), "r"(b1));
}
static __device__ __forceinline__ uint32_t packh(__half a, __half b) {
    __half2 p = __halves2half2(a, b);
    return *reinterpret_cast<uint32_t*>(&p);
}

// ---------------- fp32 -> fp16 conversion ----------------
__global__ void conv_kernel(const float* __restrict__ src, __half* __restrict__ h, size_t n) {
    size_t i = (size_t)blockIdx.x * blockDim.x + threadIdx.x;
    size_t stride = (size_t)gridDim.x * blockDim.x;
    for (; i < n; i += stride) h[i] = __float2half_rn(src[i]);
}

__global__ void conv4_kernel(const float* __restrict__ s0, const float* __restrict__ s1,
                             const float* __restrict__ s2, const float* __restrict__ s3,
                             __half* __restrict__ h0, __half* __restrict__ h1,
                             __half* __restrict__ h2, __half* __restrict__ h3, size_t n) {
    const float* src = (blockIdx.y == 0) ? s0 : (blockIdx.y == 1) ? s1
                        : (blockIdx.y == 2) ? s2 : s3;
    __half* h = (blockIdx.y == 0) ? h0 : (blockIdx.y == 1) ? h1
                 : (blockIdx.y == 2) ? h2 : h3;
    size_t i = (size_t)blockIdx.x * blockDim.x + threadIdx.x;
    size_t stride = (size_t)gridDim.x * blockDim.x;
    for (; i < n; i += stride) h[i] = __float2half_rn(src[i]);
}

// ---------------- stage loader: A, B tiles, 128 threads, hoisted swizzle ----------------
// swz((tr + r*16)*128 + tc*16) = (tr + r*16)*128 + (tc*16 ^ ((tr&7)*16))  [16 | (r*16) => &7 unchanged]
static __device__ __forceinline__ void load_stage(uint32_t sbase,
                                                  const __half* const* base,
                                                  int K, int k0, int tid) {
    const int tr = tid >> 3;        // 0..15 starting row
    const int tc = tid & 7;         // 16B column
    const uint32_t start = (uint32_t)tr * 128 +
                           (((uint32_t)tc * 16) ^ (((uint32_t)tr & 7) * 16));
    #pragma unroll
    for (int s = 0; s < 2; s++) {
        const __half* g = base[s] + (size_t)tr * K + k0 + tc * 8;
        const uint32_t so = sbase + s * TILE_BYTES + start;
        #pragma unroll
        for (int r = 0; r < 8; r++) {
            cpa16(so + r * 2048, g + (size_t)(r * 16) * K);
        }
    }
}

// ---------------- shared mainloop: acc = A * B^T over K ----------------
// 4 warps, warp tile 64x64: acc[32][4] = acc[t*8 + u*2 + j]
// LDSM offsets hoisted: swz(base + kb + half) == swz(base + half) ^ kb  (kb in {0,32,64,96})
static __device__ __forceinline__ void mainloop(uint32_t sb, const __half* const* base,
                                                int K, int tid, int wid, int lane,
                                                float (*acc)[4]) {
    const int m0 = (wid & 1) * 64;
    const int n0 = (wid >> 1) * 64;
    const uint32_t a_row  = lane & 15;
    const uint32_t a_half = (lane >> 4) * 16;
    const uint32_t b_row  = (lane & 7) + ((lane >> 4) & 1) * 8;
    const uint32_t b_half = ((lane >> 3) & 1) * 16;

    uint32_t aoff[4], boff[4];
    #pragma unroll
    for (int t = 0; t < 4; t++)
        aoff[t] = swz((uint32_t)(m0 + t * 16 + a_row) * 128 + a_half);
    #pragma unroll
    for (int u = 0; u < 4; u++)
        boff[u] = swz((uint32_t)(n0 + u * 16 + b_row) * 128 + b_half) + TILE_BYTES;

    const int NC = K / BK;
    #pragma unroll
    for (int s = 0; s < NSTAGE - 1; s++) {
        if (s < NC) load_stage(sb + s * STAGE_BYTES, base, K, s * BK, tid);
        cpa_commit();
    }

    const uint32_t wrap = sb + NSTAGE * STAGE_BYTES;
    uint32_t st_c = sb;                                        // compute stage base
    uint32_t st_l = sb + (NSTAGE - 1) * STAGE_BYTES;           // load-target stage base

    for (int c = 0; c < NC; c++) {
        asm volatile("cp.async.wait_group 1;" ::: "memory");
        __syncthreads();

        if (c + NSTAGE - 1 < NC)
            load_stage(st_l, base, K, (c + NSTAGE - 1) * BK, tid);
        cpa_commit();   // empty group in tail keeps wait_group accounting exact

        #pragma unroll
        for (int kk = 0; kk < 4; kk++) {
            const uint32_t kb = kk * 32;
            uint32_t ah[4][4], bh[4][4];
            #pragma unroll
            for (int t = 0; t < 4; t++) ldsm4(ah[t], st_c + (aoff[t] ^ kb));
            #pragma unroll
            for (int u = 0; u < 4; u++) ldsm4(bh[u], st_c + (boff[u] ^ kb));
            #pragma unroll
            for (int t = 0; t < 4; t++)
                #pragma unroll
                for (int u = 0; u < 4; u++) {
                    #pragma unroll
                    for (int j = 0; j < 2; j++) {
                        mma16816(acc[t * 8 + u * 2 + j], ah[t],
                                 bh[u][j * 2], bh[u][j * 2 + 1]);
                    }
                }
        }
        st_c += STAGE_BYTES; if (st_c == wrap) st_c = sb;
        st_l += STAGE_BYTES; if (st_l == wrap) st_l = sb;
    }
}

// ---------------- generic GEMM: C = scale*A*B^T + bias ----------------
// OUTMODE 0: fp32 C      1: fp16 C
template <int OUTMODE>
__global__ __launch_bounds__(NTHREADS, 2)
void gemm_f16(const __half* __restrict__ A, const __half* __restrict__ B,
              float* __restrict__ Cf, __half* __restrict__ Ch,
              const float* __restrict__ bias,
              int M, int N, int K, float scale,
              size_t sA, size_t sB, size_t sC) {
    extern __shared__ __align__(1024) char smem[];
    const uint32_t sb = smem_u32(smem);
    const int tid = threadIdx.x, wid = tid >> 5, lane = tid & 31;

    A += (size_t)blockIdx.z * sA;
    B += (size_t)blockIdx.z * sB;

    const int mBase = blockIdx.y * BM;
    const int nBase = blockIdx.x * BN;
    const __half* base[2] = { A + (size_t)mBase * K, B + (size_t)nBase * K };

    float acc[32][4];
    #pragma unroll
    for (int i = 0; i < 32; i++)
        #pragma unroll
        for (int j = 0; j < 4; j++) acc[i][j] = 0.0f;

    mainloop(sb, base, K, tid, wid, lane, acc);

    const int m0 = (wid & 1) * 64, n0 = (wid >> 1) * 64;
    const int qrow = lane >> 2, qcol = (lane & 3) * 2;
    #pragma unroll
    for (int t = 0; t < 4; t++)
        #pragma unroll
        for (int u = 0; u < 4; u++)
            #pragma unroll
            for (int j = 0; j < 2; j++) {
                const float* d = acc[t * 8 + u * 2 + j];
                const int m = mBase + m0 + t * 16 + qrow;
                const int n = nBase + n0 + u * 16 + j * 8 + qcol;
                float b0 = 0.f, b1 = 0.f;
                if (bias) { b0 = bias[n]; b1 = bias[n + 1]; }
                float v0 = d[0] * scale + b0, v1 = d[1] * scale + b1;
                float v2 = d[2] * scale + b0, v3 = d[3] * scale + b1;
                const size_t o0 = (size_t)blockIdx.z * sC + (size_t)m * N + n;
                const size_t o1 = o0 + (size_t)8 * N;
                if (OUTMODE == 0) {
                    *reinterpret_cast<float2*>(&Cf[o0]) = make_float2(v0, v1);
                    *reinterpret_cast<float2*>(&Cf[o1]) = make_float2(v2, v3);
                } else {
                    *reinterpret_cast<uint32_t*>(&Ch[o0]) =
                        packh(__float2half_rn(v0), __float2half_rn(v1));
                    *reinterpret_cast<uint32_t*>(&Ch[o1]) =
                        packh(__float2half_rn(v2), __float2half_rn(v3));
                }
            }
}

// ---------------- fused QKV projection: z=0 Q  z=1 K  z=2 V^T ----------------
__global__ __launch_bounds__(NTHREADS, 2)
void gemm_qkv(const __half* __restrict__ x,
              const __half* __restrict__ wq, const __half* __restrict__ wk,
              const __half* __restrict__ wv,
              __half* __restrict__ q, __half* __restrict__ k, __half* __restrict__ vt,
              const float* __restrict__ bq, const float* __restrict__ bk,
              const float* __restrict__ bv) {
    extern __shared__ __align__(1024) char smem[];
    const uint32_t sb = smem_u32(smem);
    const int tid = threadIdx.x, wid = tid >> 5, lane = tid & 31;
    const int z = blockIdx.z;
    const int K = DM, N = DM;

    const __half* B = (z == 0) ? wq : (z == 1) ? wk : wv;
    const float* bias = (z == 0) ? bq : (z == 1) ? bk : bv;

    const int mBase = blockIdx.y * BM;
    const int nBase = blockIdx.x * BN;
    const __half* base[2] = { x + (size_t)mBase * K, B + (size_t)nBase * K };

    float acc[32][4];
    #pragma unroll
    for (int i = 0; i < 32; i++)
        #pragma unroll
        for (int j = 0; j < 4; j++) acc[i][j] = 0.0f;

    mainloop(sb, base, K, tid, wid, lane, acc);

    const int m0 = (wid & 1) * 64, n0 = (wid >> 1) * 64;
    const int qrow = lane >> 2, qcol = (lane & 3) * 2;
    #pragma unroll
    for (int t = 0; t < 4; t++)
        #pragma unroll
        for (int u = 0; u < 4; u++)
            #pragma unroll
            for (int j = 0; j < 2; j++) {
                const float* d = acc[t * 8 + u * 2 + j];
                const int m = mBase + m0 + t * 16 + qrow;
                const int n = nBase + n0 + u * 16 + j * 8 + qcol;
                const float b0 = bias[n], b1 = bias[n + 1];
                float v0 = d[0] + b0, v1 = d[1] + b1;
                float v2 = d[2] + b0, v3 = d[3] + b1;
                if (z == 2) {
                    // V^T: per batch [DM][SEQ]; batch = m / SEQ
                    const size_t boff = (size_t)(m / SEQ) * ((size_t)DM * SEQ);
                    const int mr = m % SEQ;
                    vt[boff + (size_t)n * SEQ + mr]           = __float2half_rn(v0);
                    vt[boff + (size_t)(n + 1) * SEQ + mr]     = __float2half_rn(v1);
                    vt[boff + (size_t)n * SEQ + mr + 8]       = __float2half_rn(v2);
                    vt[boff + (size_t)(n + 1) * SEQ + mr + 8] = __float2half_rn(v3);
                } else {
                    __half* dst = (z == 0) ? q : k;
                    const size_t o0 = (size_t)m * N + n;
                    const size_t o1 = o0 + (size_t)8 * N;
                    *reinterpret_cast<uint32_t*>(&dst[o0]) =
                        packh(__float2half_rn(v0), __float2half_rn(v1));
                    *reinterpret_cast<uint32_t*>(&dst[o1]) =
                        packh(__float2half_rn(v2), __float2half_rn(v3));
                }
            }
}

// ---------------- in-place fp16 softmax over rows, SMEM-resident ----------------
__global__ __launch_bounds__(256)
void softmax_f16(__half* __restrict__ P, int n) {
    const int tid = threadIdx.x;
    const size_t roff = (size_t)blockIdx.x * n;
    __half* row = P + roff;

    __shared__ float srow[SEQ];
    __shared__ float red[8];
    __shared__ float bcast;

    float mx = -1e30f;
    for (int i = tid; i < n; i += 256) {
        float v = __half2float(row[i]);
        srow[i] = v;
        mx = fmaxf(mx, v);
    }
    #pragma unroll
    for (int o = 16; o; o >>= 1) mx = fmaxf(mx, __shfl_xor_sync(0xffffffffu, mx, o));
    if ((tid & 31) == 0) red[tid >> 5] = mx;
    __syncthreads();
    if (tid == 0) {
        float v = red[0];
        #pragma unroll
        for (int w = 1; w < 8; w++) v = fmaxf(v, red[w]);
        bcast = v;
    }
    __syncthreads();
    mx = bcast;
    __syncthreads();

    float s = 0.0f;
    for (int i = tid; i < n; i += 256) {
        float e = __expf(srow[i] - mx);
        srow[i] = e;
        s += e;
    }
    #pragma unroll
    for (int o = 16; o; o >>= 1) s += __shfl_xor_sync(0xffffffffu, s, o);
    if ((tid & 31) == 0) red[tid >> 5] = s;
    __syncthreads();
    if (tid == 0) {
        float v = 0.0f;
        #pragma unroll
        for (int w = 0; w < 8; w++) v += red[w];
        bcast = 1.0f / v;
    }
    __syncthreads();
    const float inv = bcast;

    for (int i = tid; i < n; i += 256)
        row[i] = __float2half_rn(srow[i] * inv);
}

// ---------------- launch ----------------
extern "C" void kernel_launch(void* const* d_in, const int* in_sizes, int n_in,
                              void* d_out, int out_size) {
    (void)in_sizes; (void)n_in; (void)out_size;

    const float* x_f = (const float*)d_in[0];
    const float* w_q = (const float*)d_in[1];
    const float* b_q = (const float*)d_in[2];
    const float* w_k = (const float*)d_in[3];
    const float* b_k = (const float*)d_in[4];
    const float* w_v = (const float*)d_in[5];
    const float* b_v = (const float*)d_in[6];
    const float* w_o = (const float*)d_in[7];
    const float* b_o = (const float*)d_in[8];
    float* out = (float*)d_out;

    __half *x, *wq, *wk, *wv, *wo, *q, *k, *vt, *p, *o;
    cudaGetSymbolAddress((void**)&x, g_x);
    cudaGetSymbolAddress((void**)&wq, g_wq);   cudaGetSymbolAddress((void**)&wk, g_wk);
    cudaGetSymbolAddress((void**)&wv, g_wv);   cudaGetSymbolAddress((void**)&wo, g_wo);
    cudaGetSymbolAddress((void**)&q, g_q);     cudaGetSymbolAddress((void**)&k, g_k);
    cudaGetSymbolAddress((void**)&vt, g_vt);
    cudaGetSymbolAddress((void**)&p, g_p);     cudaGetSymbolAddress((void**)&o, g_o);

    cudaFuncSetAttribute(gemm_f16<0>, cudaFuncAttributeMaxDynamicSharedMemorySize, SMEM_SZ);
    cudaFuncSetAttribute(gemm_f16<1>, cudaFuncAttributeMaxDynamicSharedMemorySize, SMEM_SZ);
    cudaFuncSetAttribute(gemm_qkv, cudaFuncAttributeMaxDynamicSharedMemorySize, SMEM_SZ);

    // #1 convert x, #2 convert weights
    conv_kernel<<<1024, 256>>>(x_f, x, NX);
    {
        dim3 g(128, 4);
        conv4_kernel<<<g, 256>>>(w_q, w_k, w_v, w_o, wq, wk, wv, wo, NW);
    }

    // #3 fused QKV projection
    {
        dim3 grid(DM / BN, MTOT / BM, 3);
        gemm_qkv<<<grid, NTHREADS, SMEM_SZ>>>(x, wq, wk, wv, q, k, vt, b_q, b_k, b_v);
    }

    // #4 scores P = Q K^T / sqrt(d)  -> fp16 P directly
    {
        dim3 grid(SEQ / BN, SEQ / BM, BATCH);
        gemm_f16<1><<<grid, NTHREADS, SMEM_SZ>>>(q, k, nullptr, p, nullptr,
                                                 SEQ, SEQ, DM, 0.03125f,
                                                 (size_t)SEQ * DM, (size_t)SEQ * DM,
                                                 (size_t)SEQ * SEQ);
    }

    // #5 in-place fp16 softmax
    softmax_f16<<<BATCH * SEQ, 256>>>(p, SEQ);

    // #6 O = P V  (B = V^T, K-major)
    {
        dim3 grid(DM / BN, SEQ / BM, BATCH);
        gemm_f16<1><<<grid, NTHREADS, SMEM_SZ>>>(p, vt, nullptr, o, nullptr,
                                                 SEQ, DM, SEQ, 1.0f,
                                                 (size_t)SEQ * SEQ, (size_t)DM * SEQ,
                                                 (size_t)SEQ * DM);
    }

    // #7 out = O W_out^T + b_out
    {
        dim3 grid(DM / BN, MTOT / BM, 1);
        gemm_f16<0><<<grid, NTHREADS, SMEM_SZ>>>(o, wo, out, nullptr, b_o,
                                                 MTOT, DM, DM, 1.0f, 0, 0, 0);
    }
}

// round 11
// speedup vs baseline: 9.8170x; 1.0221x over previous
#include <cuda_runtime.h>
#include <cuda_fp16.h>
#include <cstdint>

#define BATCH 4
#define SEQ   2048
#define DM    1024
#define MTOT  (BATCH * SEQ)     // 8192

#define BM 128
#define BN 128
#define BK 64                    // fp16 per k-chunk (128 B rows)
#define NTHREADS 128             // 4 warps, 2M x 2N, 64x64 warp tile
#define TILE_BYTES 16384         // 128 rows x 128 B
#define STAGE_BYTES (2 * TILE_BYTES)   // A, B tiles
#define NSTAGE 3
#define SMEM_SZ (NSTAGE * STAGE_BYTES) // 98304 -> 2 CTAs/SM

// ---------------- device scratch ----------------
#define NX ((size_t)MTOT * DM)
#define NW ((size_t)DM * DM)
#define NP ((size_t)BATCH * SEQ * SEQ)

__device__ __half g_x[NX];
__device__ __half g_wq[NW], g_wk[NW], g_wv[NW], g_wo[NW];
__device__ __half g_q[NX], g_k[NX], g_v[NX];
__device__ __half g_w2[NX];                  // W2 = Wo * V^T, per batch [DM][SEQ]
__device__ __half g_p[NP];                   // scores -> (in-place softmax) -> probs

// ---------------- helpers ----------------
static __device__ __forceinline__ uint32_t smem_u32(const void* p) {
    uint32_t a;
    asm("{ .reg .u64 t; cvta.to.shared.u64 t, %1; cvt.u32.u64 %0, t; }" : "=r"(a) : "l"(p));
    return a;
}
static __device__ __forceinline__ uint32_t swz(uint32_t o) { return o ^ ((o >> 3) & 0x70); }

static __device__ __forceinline__ void cpa16(uint32_t s, const void* g) {
    asm volatile("cp.async.cg.shared.global [%0], [%1], 16;" :: "r"(s), "l"(g));
}
static __device__ __forceinline__ void cpa_commit() { asm volatile("cp.async.commit_group;"); }

static __device__ __forceinline__ void ldsm4(uint32_t (&r)[4], uint32_t addr) {
    asm volatile("ldmatrix.sync.aligned.m8n8.x4.shared.b16 {%0,%1,%2,%3}, [%4];"
                 : "=r"(r[0]), "=r"(r[1]), "=r"(r[2]), "=r"(r[3]) : "r"(addr));
}
static __device__ __forceinline__ void mma16816(float (&d)[4], const uint32_t (&a)[4],
                                                uint32_t b0, uint32_t b1) {
    asm volatile("mma.sync.aligned.m16n8k16.row.col.f32.f16.f16.f32 "
                 "{%0,%1,%2,%3}, {%4,%5,%6,%7}, {%8,%9}, {%0,%1,%2,%3};"
                 : "+f"(d[0]), "+f"(d[1]), "+f"(d[2]), "+f"(d[3])
                 : "r"(a[0]), "r"(a[1]), "r"(a[2]), "r"(a[3]), "r"(b0), "r"(b1));
}
static __device__ __forceinline__ uint32_t packh(__half a, __half b) {
    __half2 p = __halves2half2(a, b);
    return *reinterpret_cast<uint32_t*>(&p);
}

// ---------------- fp32 -> fp16 conversion ----------------
__global__ void conv_kernel(const float* __restrict__ src, __half* __restrict__ h, size_t n) {
    size_t i = (size_t)blockIdx.x * blockDim.x + threadIdx.x;
    size_t stride = (size_t)gridDim.x * blockDim.x;
    for (; i < n; i += stride) h[i] = __float2half_rn(src[i]);
}

__global__ void conv4_kernel(const float* __restrict__ s0, const float* __restrict__ s1,
                             const float* __restrict__ s2, const float* __restrict__ s3,
                             __half* __restrict__ h0, __half* __restrict__ h1,
                             __half* __restrict__ h2, __half* __restrict__ h3, size_t n) {
    const float* src = (blockIdx.y == 0) ? s0 : (blockIdx.y == 1) ? s1
                        : (blockIdx.y == 2) ? s2 : s3;
    __half* h = (blockIdx.y == 0) ? h0 : (blockIdx.y == 1) ? h1
                 : (blockIdx.y == 2) ? h2 : h3;
    size_t i = (size_t)blockIdx.x * blockDim.x + threadIdx.x;
    size_t stride = (size_t)gridDim.x * blockDim.x;
    for (; i < n; i += stride) h[i] = __float2half_rn(src[i]);
}

// ---------------- stage loader: A, B tiles, 128 threads, hoisted swizzle ----------------
static __device__ __forceinline__ void load_stage(uint32_t sbase,
                                                  const __half* const* base,
                                                  int K, int k0, int tid) {
    const int tr = tid >> 3;        // 0..15 starting row
    const int tc = tid & 7;         // 16B column
    const uint32_t start = (uint32_t)tr * 128 +
                           (((uint32_t)tc * 16) ^ (((uint32_t)tr & 7) * 16));
    #pragma unroll
    for (int s = 0; s < 2; s++) {
        const __half* g = base[s] + (size_t)tr * K + k0 + tc * 8;
        const uint32_t so = sbase + s * TILE_BYTES + start;
        #pragma unroll
        for (int r = 0; r < 8; r++) {
            cpa16(so + r * 2048, g + (size_t)(r * 16) * K);
        }
    }
}

// ---------------- shared mainloop: acc = A * B^T over K ----------------
static __device__ __forceinline__ void mainloop(uint32_t sb, const __half* const* base,
                                                int K, int tid, int wid, int lane,
                                                float (*acc)[4]) {
    const int m0 = (wid & 1) * 64;
    const int n0 = (wid >> 1) * 64;
    const uint32_t a_row  = lane & 15;
    const uint32_t a_half = (lane >> 4) * 16;
    const uint32_t b_row  = (lane & 7) + ((lane >> 4) & 1) * 8;
    const uint32_t b_half = ((lane >> 3) & 1) * 16;

    uint32_t aoff[4], boff[4];
    #pragma unroll
    for (int t = 0; t < 4; t++)
        aoff[t] = swz((uint32_t)(m0 + t * 16 + a_row) * 128 + a_half);
    #pragma unroll
    for (int u = 0; u < 4; u++)
        boff[u] = swz((uint32_t)(n0 + u * 16 + b_row) * 128 + b_half) + TILE_BYTES;

    const int NC = K / BK;
    #pragma unroll
    for (int s = 0; s < NSTAGE - 1; s++) {
        if (s < NC) load_stage(sb + s * STAGE_BYTES, base, K, s * BK, tid);
        cpa_commit();
    }

    const uint32_t wrap = sb + NSTAGE * STAGE_BYTES;
    uint32_t st_c = sb;                                        // compute stage base
    uint32_t st_l = sb + (NSTAGE - 1) * STAGE_BYTES;           // load-target stage base

    for (int c = 0; c < NC; c++) {
        asm volatile("cp.async.wait_group 1;" ::: "memory");
        __syncthreads();

        if (c + NSTAGE - 1 < NC)
            load_stage(st_l, base, K, (c + NSTAGE - 1) * BK, tid);
        cpa_commit();   // empty group in tail keeps wait_group accounting exact

        #pragma unroll
        for (int kk = 0; kk < 4; kk++) {
            const uint32_t kb = kk * 32;
            uint32_t ah[4][4], bh[4][4];
            #pragma unroll
            for (int t = 0; t < 4; t++) ldsm4(ah[t], st_c + (aoff[t] ^ kb));
            #pragma unroll
            for (int u = 0; u < 4; u++) ldsm4(bh[u], st_c + (boff[u] ^ kb));
            #pragma unroll
            for (int t = 0; t < 4; t++)
                #pragma unroll
                for (int u = 0; u < 4; u++) {
                    #pragma unroll
                    for (int j = 0; j < 2; j++) {
                        mma16816(acc[t * 8 + u * 2 + j], ah[t],
                                 bh[u][j * 2], bh[u][j * 2 + 1]);
                    }
                }
        }
        st_c += STAGE_BYTES; if (st_c == wrap) st_c = sb;
        st_l += STAGE_BYTES; if (st_l == wrap) st_l = sb;
    }
}

// ---------------- generic GEMM: C = scale*A*B^T + bias ----------------
// OUTMODE 0: fp32 C      1: fp16 C
template <int OUTMODE>
__global__ __launch_bounds__(NTHREADS, 2)
void gemm_f16(const __half* __restrict__ A, const __half* __restrict__ B,
              float* __restrict__ Cf, __half* __restrict__ Ch,
              const float* __restrict__ bias,
              int M, int N, int K, float scale,
              size_t sA, size_t sB, size_t sC) {
    extern __shared__ __align__(1024) char smem[];
    const uint32_t sb = smem_u32(smem);
    const int tid = threadIdx.x, wid = tid >> 5, lane = tid & 31;

    A += (size_t)blockIdx.z * sA;
    B += (size_t)blockIdx.z * sB;

    const int mBase = blockIdx.y * BM;
    const int nBase = blockIdx.x * BN;
    const __half* base[2] = { A + (size_t)mBase * K, B + (size_t)nBase * K };

    float acc[32][4];
    #pragma unroll
    for (int i = 0; i < 32; i++)
        #pragma unroll
        for (int j = 0; j < 4; j++) acc[i][j] = 0.0f;

    mainloop(sb, base, K, tid, wid, lane, acc);

    const int m0 = (wid & 1) * 64, n0 = (wid >> 1) * 64;
    const int qrow = lane >> 2, qcol = (lane & 3) * 2;
    #pragma unroll
    for (int t = 0; t < 4; t++)
        #pragma unroll
        for (int u = 0; u < 4; u++)
            #pragma unroll
            for (int j = 0; j < 2; j++) {
                const float* d = acc[t * 8 + u * 2 + j];
                const int m = mBase + m0 + t * 16 + qrow;
                const int n = nBase + n0 + u * 16 + j * 8 + qcol;
                float b0 = 0.f, b1 = 0.f;
                if (bias) { b0 = bias[n]; b1 = bias[n + 1]; }
                float v0 = d[0] * scale + b0, v1 = d[1] * scale + b1;
                float v2 = d[2] * scale + b0, v3 = d[3] * scale + b1;
                const size_t o0 = (size_t)blockIdx.z * sC + (size_t)m * N + n;
                const size_t o1 = o0 + (size_t)8 * N;
                if (OUTMODE == 0) {
                    *reinterpret_cast<float2*>(&Cf[o0]) = make_float2(v0, v1);
                    *reinterpret_cast<float2*>(&Cf[o1]) = make_float2(v2, v3);
                } else {
                    *reinterpret_cast<uint32_t*>(&Ch[o0]) =
                        packh(__float2half_rn(v0), __float2half_rn(v1));
                    *reinterpret_cast<uint32_t*>(&Ch[o1]) =
                        packh(__float2half_rn(v2), __float2half_rn(v3));
                }
            }
}

// ---------------- fused QKV projection: z selects weight/bias/output ----------------
__global__ __launch_bounds__(NTHREADS, 2)
void gemm_qkv(const __half* __restrict__ x,
              const __half* __restrict__ wq, const __half* __restrict__ wk,
              const __half* __restrict__ wv,
              __half* __restrict__ q, __half* __restrict__ k, __half* __restrict__ v,
              const float* __restrict__ bq, const float* __restrict__ bk,
              const float* __restrict__ bv) {
    extern __shared__ __align__(1024) char smem[];
    const uint32_t sb = smem_u32(smem);
    const int tid = threadIdx.x, wid = tid >> 5, lane = tid & 31;
    const int z = blockIdx.z;
    const int K = DM, N = DM;

    const __half* B = (z == 0) ? wq : (z == 1) ? wk : wv;
    const float* bias = (z == 0) ? bq : (z == 1) ? bk : bv;
    __half* dst = (z == 0) ? q : (z == 1) ? k : v;

    const int mBase = blockIdx.y * BM;
    const int nBase = blockIdx.x * BN;
    const __half* base[2] = { x + (size_t)mBase * K, B + (size_t)nBase * K };

    float acc[32][4];
    #pragma unroll
    for (int i = 0; i < 32; i++)
        #pragma unroll
        for (int j = 0; j < 4; j++) acc[i][j] = 0.0f;

    mainloop(sb, base, K, tid, wid, lane, acc);

    const int m0 = (wid & 1) * 64, n0 = (wid >> 1) * 64;
    const int qrow = lane >> 2, qcol = (lane & 3) * 2;
    #pragma unroll
    for (int t = 0; t < 4; t++)
        #pragma unroll
        for (int u = 0; u < 4; u++)
            #pragma unroll
            for (int j = 0; j < 2; j++) {
                const float* d = acc[t * 8 + u * 2 + j];
                const int m = mBase + m0 + t * 16 + qrow;
                const int n = nBase + n0 + u * 16 + j * 8 + qcol;
                const float b0 = bias[n], b1 = bias[n + 1];
                const size_t o0 = (size_t)m * N + n;
                const size_t o1 = o0 + (size_t)8 * N;
                *reinterpret_cast<uint32_t*>(&dst[o0]) =
                    packh(__float2half_rn(d[0] + b0), __float2half_rn(d[1] + b1));
                *reinterpret_cast<uint32_t*>(&dst[o1]) =
                    packh(__float2half_rn(d[2] + b0), __float2half_rn(d[3] + b1));
            }
}

// ---------------- in-place fp16 softmax over rows, SMEM-resident ----------------
__global__ __launch_bounds__(256)
void softmax_f16(__half* __restrict__ P, int n) {
    const int tid = threadIdx.x;
    const size_t roff = (size_t)blockIdx.x * n;
    __half* row = P + roff;

    __shared__ float srow[SEQ];
    __shared__ float red[8];
    __shared__ float bcast;

    float mx = -1e30f;
    for (int i = tid; i < n; i += 256) {
        float v = __half2float(row[i]);
        srow[i] = v;
        mx = fmaxf(mx, v);
    }
    #pragma unroll
    for (int o = 16; o; o >>= 1) mx = fmaxf(mx, __shfl_xor_sync(0xffffffffu, mx, o));
    if ((tid & 31) == 0) red[tid >> 5] = mx;
    __syncthreads();
    if (tid == 0) {
        float v = red[0];
        #pragma unroll
        for (int w = 1; w < 8; w++) v = fmaxf(v, red[w]);
        bcast = v;
    }
    __syncthreads();
    mx = bcast;
    __syncthreads();

    float s = 0.0f;
    for (int i = tid; i < n; i += 256) {
        float e = __expf(srow[i] - mx);
        srow[i] = e;
        s += e;
    }
    #pragma unroll
    for (int o = 16; o; o >>= 1) s += __shfl_xor_sync(0xffffffffu, s, o);
    if ((tid & 31) == 0) red[tid >> 5] = s;
    __syncthreads();
    if (tid == 0) {
        float v = 0.0f;
        #pragma unroll
        for (int w = 0; w < 8; w++) v += red[w];
        bcast = 1.0f / v;
    }
    __syncthreads();
    const float inv = bcast;

    for (int i = tid; i < n; i += 256)
        row[i] = __float2half_rn(srow[i] * inv);
}

// ---------------- launch ----------------
extern "C" void kernel_launch(void* const* d_in, const int* in_sizes, int n_in,
                              void* d_out, int out_size) {
    (void)in_sizes; (void)n_in; (void)out_size;

    const float* x_f = (const float*)d_in[0];
    const float* w_q = (const float*)d_in[1];
    const float* b_q = (const float*)d_in[2];
    const float* w_k = (const float*)d_in[3];
    const float* b_k = (const float*)d_in[4];
    const float* w_v = (const float*)d_in[5];
    const float* b_v = (const float*)d_in[6];
    const float* w_o = (const float*)d_in[7];
    const float* b_o = (const float*)d_in[8];
    float* out = (float*)d_out;

    __half *x, *wq, *wk, *wv, *wo, *q, *k, *v, *w2, *p;
    cudaGetSymbolAddress((void**)&x, g_x);
    cudaGetSymbolAddress((void**)&wq, g_wq);   cudaGetSymbolAddress((void**)&wk, g_wk);
    cudaGetSymbolAddress((void**)&wv, g_wv);   cudaGetSymbolAddress((void**)&wo, g_wo);
    cudaGetSymbolAddress((void**)&q, g_q);     cudaGetSymbolAddress((void**)&k, g_k);
    cudaGetSymbolAddress((void**)&v, g_v);     cudaGetSymbolAddress((void**)&w2, g_w2);
    cudaGetSymbolAddress((void**)&p, g_p);

    cudaFuncSetAttribute(gemm_f16<0>, cudaFuncAttributeMaxDynamicSharedMemorySize, SMEM_SZ);
    cudaFuncSetAttribute(gemm_f16<1>, cudaFuncAttributeMaxDynamicSharedMemorySize, SMEM_SZ);
    cudaFuncSetAttribute(gemm_qkv, cudaFuncAttributeMaxDynamicSharedMemorySize, SMEM_SZ);

    // side stream + events, created once on first (non-capture) call
    static cudaStream_t s2 = nullptr;
    static cudaEvent_t evV = nullptr, evW2 = nullptr;
    if (!s2) {
        cudaStreamCreate(&s2);
        cudaEventCreateWithFlags(&evV, cudaEventDisableTiming);
        cudaEventCreateWithFlags(&evW2, cudaEventDisableTiming);
    }

    // #1 convert x, #2 convert weights
    conv_kernel<<<1024, 256>>>(x_f, x, NX);
    {
        dim3 g(128, 4);
        conv4_kernel<<<g, 256>>>(w_q, w_k, w_v, w_o, wq, wk, wv, wo, NW);
    }

    // #3 fused QKV projection (plain outputs)
    {
        dim3 grid(DM / BN, MTOT / BM, 3);
        gemm_qkv<<<grid, NTHREADS, SMEM_SZ>>>(x, wq, wk, wv, q, k, v, b_q, b_k, b_v);
    }

    // fork: W2 = Wo * V^T per batch -> [DM, SEQ], concurrent with scores/softmax
    cudaEventRecord(evV, 0);
    cudaStreamWaitEvent(s2, evV, 0);
    {
        dim3 grid(SEQ / BN, DM / BM, BATCH);
        gemm_f16<1><<<grid, NTHREADS, SMEM_SZ, s2>>>(wo, v, nullptr, w2, nullptr,
                                                     DM, SEQ, DM, 1.0f,
                                                     0, (size_t)SEQ * DM, (size_t)DM * SEQ);
    }
    cudaEventRecord(evW2, s2);

    // #4 scores P = Q K^T / sqrt(d) -> fp16
    {
        dim3 grid(SEQ / BN, SEQ / BM, BATCH);
        gemm_f16<1><<<grid, NTHREADS, SMEM_SZ>>>(q, k, nullptr, p, nullptr,
                                                 SEQ, SEQ, DM, 0.03125f,
                                                 (size_t)SEQ * DM, (size_t)SEQ * DM,
                                                 (size_t)SEQ * SEQ);
    }

    // #5 in-place fp16 softmax
    softmax_f16<<<BATCH * SEQ, 256>>>(p, SEQ);

    // join, then #6 out = P * W2^T + b_out  (K = SEQ)
    cudaStreamWaitEvent(0, evW2, 0);
    {
        dim3 grid(DM / BN, SEQ / BM, BATCH);
        gemm_f16<0><<<grid, NTHREADS, SMEM_SZ>>>(p, w2, out, nullptr, b_o,
                                                 SEQ, DM, SEQ, 1.0f,
                                                 (size_t)SEQ * SEQ, (size_t)DM * SEQ,
                                                 (size_t)SEQ * DM);
    }
}

// round 12
// speedup vs baseline: 9.9499x; 1.0135x over previous
#include <cuda_runtime.h>
#include <cuda_fp16.h>
#include <cstdint>

#define BATCH 4
#define SEQ   2048
#define DM    1024
#define MTOT  (BATCH * SEQ)     // 8192
#define HALF_M 1024             // M rows per pipeline half (per batch)

#define BM 128
#define BN 128
#define BK 64                    // fp16 per k-chunk (128 B rows)
#define NTHREADS 128             // 4 warps, 2M x 2N, 64x64 warp tile
#define TILE_BYTES 16384         // 128 rows x 128 B
#define STAGE_BYTES (2 * TILE_BYTES)   // A, B tiles
#define NSTAGE 3
#define SMEM_SZ (NSTAGE * STAGE_BYTES) // 98304 -> 2 CTAs/SM

// ---------------- device scratch ----------------
#define NX ((size_t)MTOT * DM)
#define NW ((size_t)DM * DM)
#define NP ((size_t)BATCH * SEQ * SEQ)

__device__ __half g_x[NX];
__device__ __half g_wq[NW], g_wk[NW], g_wv[NW], g_wo[NW];
__device__ __half g_q[NX], g_k[NX], g_v[NX];
__device__ __half g_w2[NX];                  // W2 = Wo * V^T, per batch [DM][SEQ]
__device__ __half g_p[NP];                   // scores -> (in-place) unnormalized exp
__device__ float  g_inv[MTOT];               // per-row 1/sum

// ---------------- helpers ----------------
static __device__ __forceinline__ uint32_t smem_u32(const void* p) {
    uint32_t a;
    asm("{ .reg .u64 t; cvta.to.shared.u64 t, %1; cvt.u32.u64 %0, t; }" : "=r"(a) : "l"(p));
    return a;
}
static __device__ __forceinline__ uint32_t swz(uint32_t o) { return o ^ ((o >> 3) & 0x70); }

static __device__ __forceinline__ void cpa16(uint32_t s, const void* g) {
    asm volatile("cp.async.cg.shared.global [%0], [%1], 16;" :: "r"(s), "l"(g));
}
static __device__ __forceinline__ void cpa_commit() { asm volatile("cp.async.commit_group;"); }

static __device__ __forceinline__ void ldsm4(uint32_t (&r)[4], uint32_t addr) {
    asm volatile("ldmatrix.sync.aligned.m8n8.x4.shared.b16 {%0,%1,%2,%3}, [%4];"
                 : "=r"(r[0]), "=r"(r[1]), "=r"(r[2]), "=r"(r[3]) : "r"(addr));
}
static __device__ __forceinline__ void mma16816(float (&d)[4], const uint32_t (&a)[4],
                                                uint32_t b0, uint32_t b1) {
    asm volatile("mma.sync.aligned.m16n8k16.row.col.f32.f16.f16.f32 "
                 "{%0,%1,%2,%3}, {%4,%5,%6,%7}, {%8,%9}, {%0,%1,%2,%3};"
                 : "+f"(d[0]), "+f"(d[1]), "+f"(d[2]), "+f"(d[3])
                 : "r"(a[0]), "r"(a[1]), "r"(a[2]), "r"(a[3]), "r"(b0), "r"(b1));
}
static __device__ __forceinline__ uint32_t packh(__half a, __half b) {
    __half2 p = __halves2half2(a, b);
    return *reinterpret_cast<uint32_t*>(&p);
}

// ---------------- fp32 -> fp16 conversion ----------------
__global__ void conv_kernel(const float* __restrict__ src, __half* __restrict__ h, size_t n) {
    size_t i = (size_t)blockIdx.x * blockDim.x + threadIdx.x;
    size_t stride = (size_t)gridDim.x * blockDim.x;
    for (; i < n; i += stride) h[i] = __float2half_rn(src[i]);
}

__global__ void conv4_kernel(const float* __restrict__ s0, const float* __restrict__ s1,
                             const float* __restrict__ s2, const float* __restrict__ s3,
                             __half* __restrict__ h0, __half* __restrict__ h1,
                             __half* __restrict__ h2, __half* __restrict__ h3, size_t n) {
    const float* src = (blockIdx.y == 0) ? s0 : (blockIdx.y == 1) ? s1
                        : (blockIdx.y == 2) ? s2 : s3;
    __half* h = (blockIdx.y == 0) ? h0 : (blockIdx.y == 1) ? h1
                 : (blockIdx.y == 2) ? h2 : h3;
    size_t i = (size_t)blockIdx.x * blockDim.x + threadIdx.x;
    size_t stride = (size_t)gridDim.x * blockDim.x;
    for (; i < n; i += stride) h[i] = __float2half_rn(src[i]);
}

// ---------------- stage loader: A, B tiles, 128 threads, hoisted swizzle ----------------
static __device__ __forceinline__ void load_stage(uint32_t sbase,
                                                  const __half* const* base,
                                                  int K, int k0, int tid) {
    const int tr = tid >> 3;        // 0..15 starting row
    const int tc = tid & 7;         // 16B column
    const uint32_t start = (uint32_t)tr * 128 +
                           (((uint32_t)tc * 16) ^ (((uint32_t)tr & 7) * 16));
    #pragma unroll
    for (int s = 0; s < 2; s++) {
        const __half* g = base[s] + (size_t)tr * K + k0 + tc * 8;
        const uint32_t so = sbase + s * TILE_BYTES + start;
        #pragma unroll
        for (int r = 0; r < 8; r++) {
            cpa16(so + r * 2048, g + (size_t)(r * 16) * K);
        }
    }
}

// ---------------- shared mainloop: acc = A * B^T over K ----------------
static __device__ __forceinline__ void mainloop(uint32_t sb, const __half* const* base,
                                                int K, int tid, int wid, int lane,
                                                float (*acc)[4]) {
    const int m0 = (wid & 1) * 64;
    const int n0 = (wid >> 1) * 64;
    const uint32_t a_row  = lane & 15;
    const uint32_t a_half = (lane >> 4) * 16;
    const uint32_t b_row  = (lane & 7) + ((lane >> 4) & 1) * 8;
    const uint32_t b_half = ((lane >> 3) & 1) * 16;

    uint32_t aoff[4], boff[4];
    #pragma unroll
    for (int t = 0; t < 4; t++)
        aoff[t] = swz((uint32_t)(m0 + t * 16 + a_row) * 128 + a_half);
    #pragma unroll
    for (int u = 0; u < 4; u++)
        boff[u] = swz((uint32_t)(n0 + u * 16 + b_row) * 128 + b_half) + TILE_BYTES;

    const int NC = K / BK;
    #pragma unroll
    for (int s = 0; s < NSTAGE - 1; s++) {
        if (s < NC) load_stage(sb + s * STAGE_BYTES, base, K, s * BK, tid);
        cpa_commit();
    }

    const uint32_t wrap = sb + NSTAGE * STAGE_BYTES;
    uint32_t st_c = sb;
    uint32_t st_l = sb + (NSTAGE - 1) * STAGE_BYTES;

    for (int c = 0; c < NC; c++) {
        asm volatile("cp.async.wait_group 1;" ::: "memory");
        __syncthreads();

        if (c + NSTAGE - 1 < NC)
            load_stage(st_l, base, K, (c + NSTAGE - 1) * BK, tid);
        cpa_commit();

        #pragma unroll
        for (int kk = 0; kk < 4; kk++) {
            const uint32_t kb = kk * 32;
            uint32_t ah[4][4], bh[4][4];
            #pragma unroll
            for (int t = 0; t < 4; t++) ldsm4(ah[t], st_c + (aoff[t] ^ kb));
            #pragma unroll
            for (int u = 0; u < 4; u++) ldsm4(bh[u], st_c + (boff[u] ^ kb));
            #pragma unroll
            for (int t = 0; t < 4; t++)
                #pragma unroll
                for (int u = 0; u < 4; u++) {
                    #pragma unroll
                    for (int j = 0; j < 2; j++) {
                        mma16816(acc[t * 8 + u * 2 + j], ah[t],
                                 bh[u][j * 2], bh[u][j * 2 + 1]);
                    }
                }
        }
        st_c += STAGE_BYTES; if (st_c == wrap) st_c = sb;
        st_l += STAGE_BYTES; if (st_l == wrap) st_l = sb;
    }
}

// ---------------- generic GEMM: C = scale*rowinv[m]*A*B^T + bias ----------------
// OUTMODE 0: fp32 C      1: fp16 C
template <int OUTMODE>
__global__ __launch_bounds__(NTHREADS, 2)
void gemm_f16(const __half* __restrict__ A, const __half* __restrict__ B,
              float* __restrict__ Cf, __half* __restrict__ Ch,
              const float* __restrict__ bias,
              const float* __restrict__ rowinv, int invStride,
              int M, int N, int K, float scale,
              size_t sA, size_t sB, size_t sC) {
    extern __shared__ __align__(1024) char smem[];
    const uint32_t sb = smem_u32(smem);
    const int tid = threadIdx.x, wid = tid >> 5, lane = tid & 31;

    A += (size_t)blockIdx.z * sA;
    B += (size_t)blockIdx.z * sB;

    const int mBase = blockIdx.y * BM;
    const int nBase = blockIdx.x * BN;
    const __half* base[2] = { A + (size_t)mBase * K, B + (size_t)nBase * K };

    float acc[32][4];
    #pragma unroll
    for (int i = 0; i < 32; i++)
        #pragma unroll
        for (int j = 0; j < 4; j++) acc[i][j] = 0.0f;

    mainloop(sb, base, K, tid, wid, lane, acc);

    const int m0 = (wid & 1) * 64, n0 = (wid >> 1) * 64;
    const int qrow = lane >> 2, qcol = (lane & 3) * 2;
    #pragma unroll
    for (int t = 0; t < 4; t++)
        #pragma unroll
        for (int u = 0; u < 4; u++)
            #pragma unroll
            for (int j = 0; j < 2; j++) {
                const float* d = acc[t * 8 + u * 2 + j];
                const int m = mBase + m0 + t * 16 + qrow;
                const int n = nBase + n0 + u * 16 + j * 8 + qcol;
                float s0 = scale, s1 = scale;
                if (rowinv) {
                    s0 = scale * rowinv[blockIdx.z * invStride + m];
                    s1 = scale * rowinv[blockIdx.z * invStride + m + 8];
                }
                float b0 = 0.f, b1 = 0.f;
                if (bias) { b0 = bias[n]; b1 = bias[n + 1]; }
                float v0 = d[0] * s0 + b0, v1 = d[1] * s0 + b1;
                float v2 = d[2] * s1 + b0, v3 = d[3] * s1 + b1;
                const size_t o0 = (size_t)blockIdx.z * sC + (size_t)m * N + n;
                const size_t o1 = o0 + (size_t)8 * N;
                if (OUTMODE == 0) {
                    *reinterpret_cast<float2*>(&Cf[o0]) = make_float2(v0, v1);
                    *reinterpret_cast<float2*>(&Cf[o1]) = make_float2(v2, v3);
                } else {
                    *reinterpret_cast<uint32_t*>(&Ch[o0]) =
                        packh(__float2half_rn(v0), __float2half_rn(v1));
                    *reinterpret_cast<uint32_t*>(&Ch[o1]) =
                        packh(__float2half_rn(v2), __float2half_rn(v3));
                }
            }
}

// ---------------- fused QKV projection ----------------
__global__ __launch_bounds__(NTHREADS, 2)
void gemm_qkv(const __half* __restrict__ x,
              const __half* __restrict__ wq, const __half* __restrict__ wk,
              const __half* __restrict__ wv,
              __half* __restrict__ q, __half* __restrict__ k, __half* __restrict__ v,
              const float* __restrict__ bq, const float* __restrict__ bk,
              const float* __restrict__ bv) {
    extern __shared__ __align__(1024) char smem[];
    const uint32_t sb = smem_u32(smem);
    const int tid = threadIdx.x, wid = tid >> 5, lane = tid & 31;
    const int z = blockIdx.z;
    const int K = DM, N = DM;

    const __half* B = (z == 0) ? wq : (z == 1) ? wk : wv;
    const float* bias = (z == 0) ? bq : (z == 1) ? bk : bv;
    __half* dst = (z == 0) ? q : (z == 1) ? k : v;

    const int mBase = blockIdx.y * BM;
    const int nBase = blockIdx.x * BN;
    const __half* base[2] = { x + (size_t)mBase * K, B + (size_t)nBase * K };

    float acc[32][4];
    #pragma unroll
    for (int i = 0; i < 32; i++)
        #pragma unroll
        for (int j = 0; j < 4; j++) acc[i][j] = 0.0f;

    mainloop(sb, base, K, tid, wid, lane, acc);

    const int m0 = (wid & 1) * 64, n0 = (wid >> 1) * 64;
    const int qrow = lane >> 2, qcol = (lane & 3) * 2;
    #pragma unroll
    for (int t = 0; t < 4; t++)
        #pragma unroll
        for (int u = 0; u < 4; u++)
            #pragma unroll
            for (int j = 0; j < 2; j++) {
                const float* d = acc[t * 8 + u * 2 + j];
                const int m = mBase + m0 + t * 16 + qrow;
                const int n = nBase + n0 + u * 16 + j * 8 + qcol;
                const float b0 = bias[n], b1 = bias[n + 1];
                const size_t o0 = (size_t)m * N + n;
                const size_t o1 = o0 + (size_t)8 * N;
                *reinterpret_cast<uint32_t*>(&dst[o0]) =
                    packh(__float2half_rn(d[0] + b0), __float2half_rn(d[1] + b1));
                *reinterpret_cast<uint32_t*>(&dst[o1]) =
                    packh(__float2half_rn(d[2] + b0), __float2half_rn(d[3] + b1));
            }
}

// ---------------- softmax: in-place fp16 exp (unnormalized) + per-row inv sum ----------------
// P/inv_out already offset to the half; rpb = rows per batch half.
__global__ __launch_bounds__(256)
void softmax_exp(__half* __restrict__ P, float* __restrict__ inv_out, int n, int rpb) {
    const int tid = threadIdx.x;
    const int batch = blockIdx.x / rpb;
    const int r = blockIdx.x % rpb;
    const size_t roff = (size_t)batch * ((size_t)SEQ * SEQ) + (size_t)r * n;
    __half* row = P + roff;

    __shared__ float srow[SEQ];
    __shared__ float red[8];
    __shared__ float bcast;

    float mx = -1e30f;
    for (int i = tid; i < n; i += 256) {
        float v = __half2float(row[i]);
        srow[i] = v;
        mx = fmaxf(mx, v);
    }
    #pragma unroll
    for (int o = 16; o; o >>= 1) mx = fmaxf(mx, __shfl_xor_sync(0xffffffffu, mx, o));
    if ((tid & 31) == 0) red[tid >> 5] = mx;
    __syncthreads();
    if (tid == 0) {
        float v = red[0];
        #pragma unroll
        for (int w = 1; w < 8; w++) v = fmaxf(v, red[w]);
        bcast = v;
    }
    __syncthreads();
    mx = bcast;
    __syncthreads();

    float s = 0.0f;
    for (int i = tid; i < n; i += 256) {
        float e = __expf(srow[i] - mx);
        row[i] = __float2half_rn(e);
        s += e;
    }
    #pragma unroll
    for (int o = 16; o; o >>= 1) s += __shfl_xor_sync(0xffffffffu, s, o);
    if ((tid & 31) == 0) red[tid >> 5] = s;
    __syncthreads();
    if (tid == 0) {
        float v = 0.0f;
        #pragma unroll
        for (int w = 0; w < 8; w++) v += red[w];
        inv_out[batch * SEQ + r] = 1.0f / v;
    }
}

// ---------------- launch ----------------
extern "C" void kernel_launch(void* const* d_in, const int* in_sizes, int n_in,
                              void* d_out, int out_size) {
    (void)in_sizes; (void)n_in; (void)out_size;

    const float* x_f = (const float*)d_in[0];
    const float* w_q = (const float*)d_in[1];
    const float* b_q = (const float*)d_in[2];
    const float* w_k = (const float*)d_in[3];
    const float* b_k = (const float*)d_in[4];
    const float* w_v = (const float*)d_in[5];
    const float* b_v = (const float*)d_in[6];
    const float* w_o = (const float*)d_in[7];
    const float* b_o = (const float*)d_in[8];
    float* out = (float*)d_out;

    __half *x, *wq, *wk, *wv, *wo, *q, *k, *v, *w2, *p;
    float* inv;
    cudaGetSymbolAddress((void**)&x, g_x);
    cudaGetSymbolAddress((void**)&wq, g_wq);   cudaGetSymbolAddress((void**)&wk, g_wk);
    cudaGetSymbolAddress((void**)&wv, g_wv);   cudaGetSymbolAddress((void**)&wo, g_wo);
    cudaGetSymbolAddress((void**)&q, g_q);     cudaGetSymbolAddress((void**)&k, g_k);
    cudaGetSymbolAddress((void**)&v, g_v);     cudaGetSymbolAddress((void**)&w2, g_w2);
    cudaGetSymbolAddress((void**)&p, g_p);     cudaGetSymbolAddress((void**)&inv, g_inv);

    cudaFuncSetAttribute(gemm_f16<0>, cudaFuncAttributeMaxDynamicSharedMemorySize, SMEM_SZ);
    cudaFuncSetAttribute(gemm_f16<1>, cudaFuncAttributeMaxDynamicSharedMemorySize, SMEM_SZ);
    cudaFuncSetAttribute(gemm_qkv, cudaFuncAttributeMaxDynamicSharedMemorySize, SMEM_SZ);

    static cudaStream_t s2 = nullptr, s3 = nullptr;
    static cudaEvent_t evQKV = nullptr, evW2 = nullptr, evS[2] = {nullptr, nullptr},
                       evDone = nullptr;
    if (!s2) {
        cudaStreamCreate(&s2);
        cudaStreamCreate(&s3);
        cudaEventCreateWithFlags(&evQKV, cudaEventDisableTiming);
        cudaEventCreateWithFlags(&evW2, cudaEventDisableTiming);
        cudaEventCreateWithFlags(&evS[0], cudaEventDisableTiming);
        cudaEventCreateWithFlags(&evS[1], cudaEventDisableTiming);
        cudaEventCreateWithFlags(&evDone, cudaEventDisableTiming);
    }

    // main: conversions + QKV
    conv_kernel<<<1024, 256>>>(x_f, x, NX);
    {
        dim3 g(128, 4);
        conv4_kernel<<<g, 256>>>(w_q, w_k, w_v, w_o, wq, wk, wv, wo, NW);
    }
    {
        dim3 grid(DM / BN, MTOT / BM, 3);
        gemm_qkv<<<grid, NTHREADS, SMEM_SZ>>>(x, wq, wk, wv, q, k, v, b_q, b_k, b_v);
    }
    cudaEventRecord(evQKV, 0);

    // s2: W2 = Wo * V^T per batch -> [DM, SEQ]
    cudaStreamWaitEvent(s2, evQKV, 0);
    {
        dim3 grid(SEQ / BN, DM / BM, BATCH);
        gemm_f16<1><<<grid, NTHREADS, SMEM_SZ, s2>>>(wo, v, nullptr, w2, nullptr,
                                                     nullptr, 0,
                                                     DM, SEQ, DM, 1.0f,
                                                     0, (size_t)SEQ * DM, (size_t)DM * SEQ);
    }
    cudaEventRecord(evW2, s2);

    // main: scores halves (M split), record per-half events
    for (int h = 0; h < 2; h++) {
        dim3 grid(SEQ / BN, HALF_M / BM, BATCH);
        gemm_f16<1><<<grid, NTHREADS, SMEM_SZ>>>(
            q + (size_t)h * HALF_M * DM, k, nullptr,
            p + (size_t)h * HALF_M * SEQ, nullptr, nullptr, 0,
            HALF_M, SEQ, DM, 0.03125f,
            (size_t)SEQ * DM, (size_t)SEQ * DM, (size_t)SEQ * SEQ);
        cudaEventRecord(evS[h], 0);
    }

    // s3: per-half softmax + final GEMM (out = exp(P) * W2^T * inv + b_o)
    cudaStreamWaitEvent(s3, evW2, 0);
    for (int h = 0; h < 2; h++) {
        cudaStreamWaitEvent(s3, evS[h], 0);
        softmax_exp<<<BATCH * HALF_M, 256, 0, s3>>>(
            p + (size_t)h * HALF_M * SEQ, inv + h * HALF_M, SEQ, HALF_M);
        dim3 grid(DM / BN, HALF_M / BM, BATCH);
        gemm_f16<0><<<grid, NTHREADS, SMEM_SZ, s3>>>(
            p + (size_t)h * HALF_M * SEQ, w2,
            out + (size_t)h * HALF_M * DM, nullptr, b_o,
            inv + h * HALF_M, SEQ,
            HALF_M, DM, SEQ, 1.0f,
            (size_t)SEQ * SEQ, (size_t)DM * SEQ, (size_t)SEQ * DM);
    }
    cudaEventRecord(evDone, s3);
    cudaStreamWaitEvent(0, evDone, 0);
}